// round 1
// baseline (speedup 1.0000x reference)
#include <cuda_runtime.h>
#include <math.h>

#define NS   2048     // sequence length
#define NH   16       // heads
#define DH   64       // dim per head
#define DIMM 1024     // model dim
#define LDQ  6144     // qkv row stride (6 * 1024)

__device__ __constant__ float SCALE = 0.125f;  // 64^-0.5

// ---- scratch (device globals: allocation-free) ----
__device__ float g_qkv[(size_t)NS * LDQ];         // 50 MB  [n][6*H*D]
__device__ float g_t1 [(size_t)NH * NS * NS];     // 256 MB term1 (lower-tri)
__device__ float g_lk [(size_t)NH * NS * NS];     // 256 MB lookahead (strict upper)
__device__ float g_sc [(size_t)NH * NS * NS];     // 256 MB Sc -> scores -> attn
__device__ float g_ctx[(size_t)NS * DIMM];        // 8 MB   attention context

// ============================================================
// Generic NN SGEMM: C[MxN] = A[MxK] @ B[KxN]. 64x64 tiles, BK=16,
// 256 threads, 4x4 per thread. All dims multiples of tile sizes.
// ============================================================
__global__ void gemm_nn(const float* __restrict__ A, const float* __restrict__ B,
                        float* __restrict__ C, int K, int lda, int ldb, int ldc) {
    __shared__ float As[16][64];
    __shared__ float Bs[16][64];
    const int t  = threadIdx.x;
    const int tx = t & 15, ty = t >> 4;
    const int bi = blockIdx.y, bj = blockIdx.x;
    const int ar = t >> 2, ac = (t & 3) << 2;     // A tile load coords (64x16)
    const int br = t >> 4, bc = (t & 15) << 2;    // B tile load coords (16x64)

    const float* Ab = A + (size_t)(bi * 64 + ar) * lda + ac;
    const float* Bb = B + (size_t)br * ldb + bj * 64 + bc;

    float acc[4][4] = {};
    for (int k0 = 0; k0 < K; k0 += 16) {
        float4 a4 = *(const float4*)(Ab + k0);
        As[ac + 0][ar] = a4.x; As[ac + 1][ar] = a4.y;
        As[ac + 2][ar] = a4.z; As[ac + 3][ar] = a4.w;
        *(float4*)&Bs[br][bc] = *(const float4*)(Bb + (size_t)k0 * ldb);
        __syncthreads();
#pragma unroll
        for (int kk = 0; kk < 16; kk++) {
            float4 av = *(float4*)&As[kk][ty << 2];
            float4 bv = *(float4*)&Bs[kk][tx << 2];
            float a[4] = {av.x, av.y, av.z, av.w};
            float b[4] = {bv.x, bv.y, bv.z, bv.w};
#pragma unroll
            for (int m = 0; m < 4; m++)
#pragma unroll
                for (int n = 0; n < 4; n++)
                    acc[m][n] = fmaf(a[m], b[n], acc[m][n]);
        }
        __syncthreads();
    }
    float* Cb = C + (size_t)(bi * 64 + (ty << 2)) * ldc + bj * 64 + (tx << 2);
#pragma unroll
    for (int m = 0; m < 4; m++) {
        float4 v = make_float4(acc[m][0], acc[m][1], acc[m][2], acc[m][3]);
        *(float4*)(Cb + (size_t)m * ldc) = v;
    }
}

// ============================================================
// Per-head NT GEMM over K=64: C[i,j] = scale * dot(A[i,:], B[j,:])
// MODE 1: term1  (keep j<=i, else 0; skip blocks above diagonal)
// MODE 2: look   (sigmoid, keep j>i, else 0; skip blocks below diagonal)
// MODE 3: Sc     (plain; skip blocks above diagonal)
// A/B are head slices of g_qkv.
// ============================================================
template <int MODE>
__global__ void head_nt(const float* __restrict__ qkv, int aoff, int boff,
                        float* __restrict__ C) {
    const int h  = blockIdx.z;
    const int bi = blockIdx.y, bj = blockIdx.x;
    if (MODE != 2 && bj > bi) return;
    if (MODE == 2 && bj < bi) return;

    __shared__ float As[16][64];
    __shared__ float Bs[16][64];
    const int t  = threadIdx.x;
    const int tx = t & 15, ty = t >> 4;
    const int lr = t >> 2, lc = (t & 3) << 2;

    const float* Ab = qkv + (size_t)(bi * 64 + lr) * LDQ + aoff + h * DH + lc;
    const float* Bb = qkv + (size_t)(bj * 64 + lr) * LDQ + boff + h * DH + lc;

    float acc[4][4] = {};
#pragma unroll
    for (int k0 = 0; k0 < 64; k0 += 16) {
        float4 a4 = *(const float4*)(Ab + k0);
        float4 b4 = *(const float4*)(Bb + k0);
        As[lc + 0][lr] = a4.x; As[lc + 1][lr] = a4.y;
        As[lc + 2][lr] = a4.z; As[lc + 3][lr] = a4.w;
        Bs[lc + 0][lr] = b4.x; Bs[lc + 1][lr] = b4.y;
        Bs[lc + 2][lr] = b4.z; Bs[lc + 3][lr] = b4.w;
        __syncthreads();
#pragma unroll
        for (int kk = 0; kk < 16; kk++) {
            float4 av = *(float4*)&As[kk][ty << 2];
            float4 bv = *(float4*)&Bs[kk][tx << 2];
            float a[4] = {av.x, av.y, av.z, av.w};
            float b[4] = {bv.x, bv.y, bv.z, bv.w};
#pragma unroll
            for (int m = 0; m < 4; m++)
#pragma unroll
                for (int n = 0; n < 4; n++)
                    acc[m][n] = fmaf(a[m], b[n], acc[m][n]);
        }
        __syncthreads();
    }

    float* Cb = C + (size_t)h * NS * NS;
    const int gi = bi * 64 + (ty << 2);
    const int gj = bj * 64 + (tx << 2);
#pragma unroll
    for (int m = 0; m < 4; m++) {
#pragma unroll
        for (int n = 0; n < 4; n++) {
            const int i = gi + m, j = gj + n;
            float v = acc[m][n] * SCALE;
            if (MODE == 1) v = (j <= i) ? v : 0.0f;
            if (MODE == 2) v = (j >  i) ? (1.0f / (1.0f + expf(-v))) : 0.0f;
            Cb[(size_t)i * NS + j] = v;
        }
    }
}

// ============================================================
// Su = term1 @ look^T (strictly lower-tri result), fused epilogue:
//   g_sc[i,k] -= silu(Su[i,k])
// Block (bk, bi): only bi >= bk; j-range restricted to [bk*64, (bi+1)*64).
// ============================================================
__global__ void su_fuse(const float* __restrict__ T1, const float* __restrict__ LK,
                        float* __restrict__ SC) {
    const int h  = blockIdx.z;
    const int bi = blockIdx.y, bk = blockIdx.x;
    if (bk > bi) return;

    __shared__ float As[16][64];
    __shared__ float Bs[16][64];
    const int t  = threadIdx.x;
    const int tx = t & 15, ty = t >> 4;
    const int lr = t >> 2, lc = (t & 3) << 2;

    const size_t hoff = (size_t)h * NS * NS;
    const float* Ab = T1 + hoff + (size_t)(bi * 64 + lr) * NS + lc;
    const float* Bb = LK + hoff + (size_t)(bk * 64 + lr) * NS + lc;

    float acc[4][4] = {};
    const int kEnd = (bi + 1) * 64;
    for (int k0 = bk * 64; k0 < kEnd; k0 += 16) {
        float4 a4 = *(const float4*)(Ab + k0);
        float4 b4 = *(const float4*)(Bb + k0);
        As[lc + 0][lr] = a4.x; As[lc + 1][lr] = a4.y;
        As[lc + 2][lr] = a4.z; As[lc + 3][lr] = a4.w;
        Bs[lc + 0][lr] = b4.x; Bs[lc + 1][lr] = b4.y;
        Bs[lc + 2][lr] = b4.z; Bs[lc + 3][lr] = b4.w;
        __syncthreads();
#pragma unroll
        for (int kk = 0; kk < 16; kk++) {
            float4 av = *(float4*)&As[kk][ty << 2];
            float4 bv = *(float4*)&Bs[kk][tx << 2];
            float a[4] = {av.x, av.y, av.z, av.w};
            float b[4] = {bv.x, bv.y, bv.z, bv.w};
#pragma unroll
            for (int m = 0; m < 4; m++)
#pragma unroll
                for (int n = 0; n < 4; n++)
                    acc[m][n] = fmaf(a[m], b[n], acc[m][n]);
        }
        __syncthreads();
    }

    float* Cb = SC + hoff + (size_t)(bi * 64 + (ty << 2)) * NS + bk * 64 + (tx << 2);
#pragma unroll
    for (int m = 0; m < 4; m++) {
#pragma unroll
        for (int n = 0; n < 4; n++) {
            float su = acc[m][n];
            float s  = su / (1.0f + expf(-su));   // silu (silu(0)=0 keeps diag exact)
            Cb[(size_t)m * NS + n] -= s;
        }
    }
}

// ============================================================
// Row softmax over causal range j<=i, in place on g_sc.
// Zero-pads [i+1, blockRound(i+1)) so the AV GEMM can read whole 64-tiles.
// ============================================================
__global__ void row_softmax(float* __restrict__ SC) {
    const int h = blockIdx.y, i = blockIdx.x;
    float* row = SC + (size_t)h * NS * NS + (size_t)i * NS;
    const int t = threadIdx.x;
    const int len = i + 1;

    __shared__ float red[256];

    float lmax = -1e30f;
    for (int j = t; j < len; j += 256) lmax = fmaxf(lmax, row[j]);
    red[t] = lmax; __syncthreads();
    for (int s = 128; s > 0; s >>= 1) { if (t < s) red[t] = fmaxf(red[t], red[t + s]); __syncthreads(); }
    const float bmax = red[0];
    __syncthreads();

    float lsum = 0.0f;
    for (int j = t; j < len; j += 256) {
        float e = expf(row[j] - bmax);
        row[j] = e;
        lsum += e;
    }
    red[t] = lsum; __syncthreads();
    for (int s = 128; s > 0; s >>= 1) { if (t < s) red[t] += red[t + s]; __syncthreads(); }
    const float inv = 1.0f / red[0];
    __syncthreads();

    for (int j = t; j < len; j += 256) row[j] *= inv;

    const int padEnd = ((i >> 6) + 1) << 6;
    for (int j = len + t; j < padEnd; j += 256) row[j] = 0.0f;
}

// ============================================================
// AV GEMM: ctx[i, h*64+d] = sum_{j<= i-tile end} attn[h,i,j] * vc[h,j,d]
// NN GEMM, per (head, i-tile) block; K limited by causality to (bi+1)*64.
// ============================================================
__global__ void av_gemm(const float* __restrict__ ATT, const float* __restrict__ qkv,
                        float* __restrict__ ctx) {
    const int h = blockIdx.y, bi = blockIdx.x;
    __shared__ float As[16][64];
    __shared__ float Bs[16][64];
    const int t  = threadIdx.x;
    const int tx = t & 15, ty = t >> 4;
    const int ar = t >> 2, ac = (t & 3) << 2;
    const int br = t >> 4, bc = (t & 15) << 2;

    const float* Ab = ATT + (size_t)h * NS * NS + (size_t)(bi * 64 + ar) * NS + ac;
    const float* Bb = qkv + (size_t)br * LDQ + 5 * 1024 + h * DH + bc;  // vc slice

    float acc[4][4] = {};
    const int K = (bi + 1) * 64;
    for (int k0 = 0; k0 < K; k0 += 16) {
        float4 a4 = *(const float4*)(Ab + k0);
        As[ac + 0][ar] = a4.x; As[ac + 1][ar] = a4.y;
        As[ac + 2][ar] = a4.z; As[ac + 3][ar] = a4.w;
        *(float4*)&Bs[br][bc] = *(const float4*)(Bb + (size_t)k0 * LDQ);
        __syncthreads();
#pragma unroll
        for (int kk = 0; kk < 16; kk++) {
            float4 av = *(float4*)&As[kk][ty << 2];
            float4 bv = *(float4*)&Bs[kk][tx << 2];
            float a[4] = {av.x, av.y, av.z, av.w};
            float b[4] = {bv.x, bv.y, bv.z, bv.w};
#pragma unroll
            for (int m = 0; m < 4; m++)
#pragma unroll
                for (int n = 0; n < 4; n++)
                    acc[m][n] = fmaf(a[m], b[n], acc[m][n]);
        }
        __syncthreads();
    }
    float* Cb = ctx + (size_t)(bi * 64 + (ty << 2)) * DIMM + h * DH + (tx << 2);
#pragma unroll
    for (int m = 0; m < 4; m++) {
        float4 v = make_float4(acc[m][0], acc[m][1], acc[m][2], acc[m][3]);
        *(float4*)(Cb + (size_t)m * DIMM) = v;
    }
}

// ============================================================
extern "C" void kernel_launch(void* const* d_in, const int* in_sizes, int n_in,
                              void* d_out, int out_size) {
    const float* x    = (const float*)d_in[0];   // [1,2048,1024]
    const float* Wqkv = (const float*)d_in[1];   // [1024,6144]
    const float* Wout = (const float*)d_in[2];   // [1024,1024]
    float* out = (float*)d_out;                  // [1,2048,1024]

    float *qkv, *t1, *lk, *sc, *ctx;
    cudaGetSymbolAddress((void**)&qkv, g_qkv);
    cudaGetSymbolAddress((void**)&t1,  g_t1);
    cudaGetSymbolAddress((void**)&lk,  g_lk);
    cudaGetSymbolAddress((void**)&sc,  g_sc);
    cudaGetSymbolAddress((void**)&ctx, g_ctx);

    const dim3 thr(256);

    // 1) qkv = x @ W_qkv   [2048 x 6144]
    gemm_nn<<<dim3(LDQ / 64, NS / 64), thr>>>(x, Wqkv, qkv, DIMM, DIMM, LDQ, LDQ);

    // 2) per-head small GEMMs (K=64), triangle-skipped
    const dim3 gHead(NS / 64, NS / 64, NH);
    head_nt<1><<<gHead, thr>>>(qkv, 3 * 1024, 2 * 1024, t1);  // term1 = tril(qc_s @ vu^T)
    head_nt<2><<<gHead, thr>>>(qkv, 0 * 1024, 1 * 1024, lk);  // look  = triu1(sigmoid(qu_s @ ku^T))
    head_nt<3><<<gHead, thr>>>(qkv, 3 * 1024, 4 * 1024, sc);  // Sc    = qc_s @ kc^T (lower blocks)

    // 3) Su GEMM (triangle-restricted K range) fused with scores = Sc - silu(Su)
    su_fuse<<<gHead, thr>>>(t1, lk, sc);

    // 4) causal softmax in place
    row_softmax<<<dim3(NS, NH), thr>>>(sc);

    // 5) ctx = attn @ vc (causal K range)
    av_gemm<<<dim3(NS / 64, NH), thr>>>(sc, qkv, ctx);

    // 6) out = ctx @ W_out
    gemm_nn<<<dim3(DIMM / 64, NS / 64), thr>>>(ctx, Wout, out, DIMM, DIMM, DIMM, DIMM);
}

// round 2
// speedup vs baseline: 1.0772x; 1.0772x over previous
#include <cuda_runtime.h>
#include <math.h>

#define NS   2048     // sequence length
#define NH   16       // heads
#define DH   64       // dim per head
#define DIMM 1024     // model dim
#define LDQ  6144     // qkv row stride (6 * 1024)

__device__ __constant__ float SCALE = 0.125f;  // 64^-0.5

// ---- scratch (device globals: allocation-free) ----
__device__ float g_qkv[(size_t)NS * LDQ];         // 50 MB  [n][6*H*D]
__device__ float g_t1 [(size_t)NH * NS * NS];     // 256 MB term1 (lower-tri)
__device__ float g_lk [(size_t)NH * NS * NS];     // 256 MB lookahead (strict upper)
__device__ float g_sc [(size_t)NH * NS * NS];     // 256 MB Sc -> scores -> attn
__device__ float g_ctx[(size_t)NS * DIMM];        // 8 MB   attention context

// ============================================================
// Shared inner-product macro: 8x8 accum from As/Bs [8][128]
// ============================================================
#define MICRO_8x8(As, Bs)                                              \
    _Pragma("unroll")                                                  \
    for (int kk = 0; kk < 8; kk++) {                                   \
        float4 a0 = *(float4*)&As[kk][ty * 8];                         \
        float4 a1 = *(float4*)&As[kk][ty * 8 + 4];                     \
        float4 b0 = *(float4*)&Bs[kk][tx * 8];                         \
        float4 b1 = *(float4*)&Bs[kk][tx * 8 + 4];                     \
        float a[8] = {a0.x, a0.y, a0.z, a0.w, a1.x, a1.y, a1.z, a1.w}; \
        float b[8] = {b0.x, b0.y, b0.z, b0.w, b1.x, b1.y, b1.z, b1.w}; \
        _Pragma("unroll")                                              \
        for (int m = 0; m < 8; m++)                                    \
            _Pragma("unroll")                                          \
            for (int n = 0; n < 8; n++)                                \
                acc[m][n] = fmaf(a[m], b[n], acc[m][n]);               \
    }

// ============================================================
// Generic NN SGEMM: C[MxN] = A[MxK] @ B[KxN]. 128x128 tiles, BK=8,
// 256 threads, 8x8 per thread, register-prefetch pipeline.
// ============================================================
__global__ void gemm_nn(const float* __restrict__ A, const float* __restrict__ B,
                        float* __restrict__ C, int K, int lda, int ldb, int ldc) {
    __shared__ float As[8][128];
    __shared__ float Bs[8][128];
    const int t  = threadIdx.x;
    const int tx = t & 15, ty = t >> 4;
    const int bi = blockIdx.y, bj = blockIdx.x;
    const int ar = t >> 1, ac = (t & 1) << 2;     // A tile: 128 rows x 8 k
    const int br = t >> 5, bc = (t & 31) << 2;    // B tile: 8 k x 128 cols

    const float* Ap = A + (size_t)(bi * 128 + ar) * lda + ac;
    const float* Bp = B + (size_t)br * ldb + bj * 128 + bc;

    float acc[8][8] = {};
    float4 aR = *(const float4*)Ap;
    float4 bR = *(const float4*)Bp;

    for (int k0 = 0; k0 < K; k0 += 8) {
        As[ac + 0][ar] = aR.x; As[ac + 1][ar] = aR.y;
        As[ac + 2][ar] = aR.z; As[ac + 3][ar] = aR.w;
        *(float4*)&Bs[br][bc] = bR;
        __syncthreads();
        if (k0 + 8 < K) {
            aR = *(const float4*)(Ap + k0 + 8);
            bR = *(const float4*)(Bp + (size_t)(k0 + 8) * ldb);
        }
        MICRO_8x8(As, Bs)
        __syncthreads();
    }

    float* Cp = C + (size_t)(bi * 128 + ty * 8) * ldc + bj * 128 + tx * 8;
#pragma unroll
    for (int m = 0; m < 8; m++) {
        *(float4*)(Cp + (size_t)m * ldc)     = make_float4(acc[m][0], acc[m][1], acc[m][2], acc[m][3]);
        *(float4*)(Cp + (size_t)m * ldc + 4) = make_float4(acc[m][4], acc[m][5], acc[m][6], acc[m][7]);
    }
}

// ============================================================
// Per-head NT GEMM over K=64 (both operands row-major, K in cols).
// MODE 1: term1 (keep j<=i else 0), MODE 2: lookahead (sigmoid, keep j>i),
// MODE 3: Sc (plain). Triangle block skipping.
// ============================================================
template <int MODE>
__global__ void head_nt(const float* __restrict__ qkv, int aoff, int boff,
                        float* __restrict__ C) {
    const int h  = blockIdx.z;
    const int bi = blockIdx.y, bj = blockIdx.x;
    if (MODE != 2 && bj > bi) return;
    if (MODE == 2 && bj < bi) return;

    __shared__ float As[8][128];
    __shared__ float Bs[8][128];
    const int t  = threadIdx.x;
    const int tx = t & 15, ty = t >> 4;
    const int lr = t >> 1, lc = (t & 1) << 2;

    const float* Ap = qkv + (size_t)(bi * 128 + lr) * LDQ + aoff + h * DH + lc;
    const float* Bp = qkv + (size_t)(bj * 128 + lr) * LDQ + boff + h * DH + lc;

    float acc[8][8] = {};
    float4 aR = *(const float4*)Ap;
    float4 bR = *(const float4*)Bp;

#pragma unroll
    for (int k0 = 0; k0 < 64; k0 += 8) {
        As[lc + 0][lr] = aR.x; As[lc + 1][lr] = aR.y;
        As[lc + 2][lr] = aR.z; As[lc + 3][lr] = aR.w;
        Bs[lc + 0][lr] = bR.x; Bs[lc + 1][lr] = bR.y;
        Bs[lc + 2][lr] = bR.z; Bs[lc + 3][lr] = bR.w;
        __syncthreads();
        if (k0 + 8 < 64) {
            aR = *(const float4*)(Ap + k0 + 8);
            bR = *(const float4*)(Bp + k0 + 8);
        }
        MICRO_8x8(As, Bs)
        __syncthreads();
    }

    float* Cb = C + (size_t)h * NS * NS;
    const int gi = bi * 128 + ty * 8;
    const int gj = bj * 128 + tx * 8;
#pragma unroll
    for (int m = 0; m < 8; m++) {
        const int i = gi + m;
        float o[8];
#pragma unroll
        for (int n = 0; n < 8; n++) {
            const int j = gj + n;
            float v = acc[m][n] * SCALE;
            if (MODE == 1) v = (j <= i) ? v : 0.0f;
            if (MODE == 2) v = (j >  i) ? (1.0f / (1.0f + expf(-v))) : 0.0f;
            o[n] = v;
        }
        float* row = Cb + (size_t)i * NS + gj;
        *(float4*)(row)     = make_float4(o[0], o[1], o[2], o[3]);
        *(float4*)(row + 4) = make_float4(o[4], o[5], o[6], o[7]);
    }
}

// ============================================================
// Su = term1 @ look^T (strictly lower-tri), fused: SC[i,k] -= silu(Su[i,k]).
// Block (bk, bi), bi >= bk; j-range restricted to [bk*128, (bi+1)*128).
// ============================================================
__global__ void su_fuse(const float* __restrict__ T1, const float* __restrict__ LK,
                        float* __restrict__ SC) {
    const int h  = blockIdx.z;
    const int bi = blockIdx.y, bk = blockIdx.x;
    if (bk > bi) return;

    __shared__ float As[8][128];
    __shared__ float Bs[8][128];
    const int t  = threadIdx.x;
    const int tx = t & 15, ty = t >> 4;
    const int lr = t >> 1, lc = (t & 1) << 2;

    const size_t hoff = (size_t)h * NS * NS;
    const float* Ap = T1 + hoff + (size_t)(bi * 128 + lr) * NS + lc;
    const float* Bp = LK + hoff + (size_t)(bk * 128 + lr) * NS + lc;

    float acc[8][8] = {};
    const int kStart = bk * 128;
    const int kEnd   = (bi + 1) * 128;
    float4 aR = *(const float4*)(Ap + kStart);
    float4 bR = *(const float4*)(Bp + kStart);

    for (int k0 = kStart; k0 < kEnd; k0 += 8) {
        As[lc + 0][lr] = aR.x; As[lc + 1][lr] = aR.y;
        As[lc + 2][lr] = aR.z; As[lc + 3][lr] = aR.w;
        Bs[lc + 0][lr] = bR.x; Bs[lc + 1][lr] = bR.y;
        Bs[lc + 2][lr] = bR.z; Bs[lc + 3][lr] = bR.w;
        __syncthreads();
        if (k0 + 8 < kEnd) {
            aR = *(const float4*)(Ap + k0 + 8);
            bR = *(const float4*)(Bp + k0 + 8);
        }
        MICRO_8x8(As, Bs)
        __syncthreads();
    }

    float* Cp = SC + hoff + (size_t)(bi * 128 + ty * 8) * NS + bk * 128 + tx * 8;
#pragma unroll
    for (int m = 0; m < 8; m++) {
        float4 c0 = *(float4*)(Cp + (size_t)m * NS);
        float4 c1 = *(float4*)(Cp + (size_t)m * NS + 4);
        float s[8];
#pragma unroll
        for (int n = 0; n < 8; n++) {
            float su = acc[m][n];
            s[n] = su / (1.0f + expf(-su));   // silu(0)=0 keeps untouched region exact
        }
        c0.x -= s[0]; c0.y -= s[1]; c0.z -= s[2]; c0.w -= s[3];
        c1.x -= s[4]; c1.y -= s[5]; c1.z -= s[6]; c1.w -= s[7];
        *(float4*)(Cp + (size_t)m * NS)     = c0;
        *(float4*)(Cp + (size_t)m * NS + 4) = c1;
    }
}

// ============================================================
// Row softmax over causal range j<=i, in place; zero-pads up to the next
// 128 boundary so the AV GEMM reads whole 128-wide K tiles.
// ============================================================
__global__ void row_softmax(float* __restrict__ SC) {
    const int h = blockIdx.y, i = blockIdx.x;
    float* row = SC + (size_t)h * NS * NS + (size_t)i * NS;
    const int t = threadIdx.x;
    const int len = i + 1;

    __shared__ float red[256];

    float lmax = -1e30f;
    for (int j = t; j < len; j += 256) lmax = fmaxf(lmax, row[j]);
    red[t] = lmax; __syncthreads();
    for (int s = 128; s > 0; s >>= 1) { if (t < s) red[t] = fmaxf(red[t], red[t + s]); __syncthreads(); }
    const float bmax = red[0];
    __syncthreads();

    float lsum = 0.0f;
    for (int j = t; j < len; j += 256) {
        float e = expf(row[j] - bmax);
        row[j] = e;
        lsum += e;
    }
    red[t] = lsum; __syncthreads();
    for (int s = 128; s > 0; s >>= 1) { if (t < s) red[t] += red[t + s]; __syncthreads(); }
    const float inv = 1.0f / red[0];
    __syncthreads();

    for (int j = t; j < len; j += 256) row[j] *= inv;

    const int padEnd = ((i >> 7) + 1) << 7;
    for (int j = len + t; j < padEnd; j += 256) row[j] = 0.0f;
}

// ============================================================
// AV GEMM: ctx[i, h*64+d] = sum_j attn[h,i,j] * vc[h,j,d]
// Tile: M=128, N=64(=DH), BK=8. 256 threads, 8x4 per thread.
// Causal K range: (bi+1)*128.
// ============================================================
__global__ void av_gemm(const float* __restrict__ ATT, const float* __restrict__ qkv,
                        float* __restrict__ ctx) {
    const int h = blockIdx.y, bi = blockIdx.x;
    __shared__ float As[8][128];
    __shared__ float Bs[8][64];
    const int t  = threadIdx.x;
    const int tx = t & 15, ty = t >> 4;
    const int ar = t >> 1, ac = (t & 1) << 2;     // attn tile 128 x 8
    const int br = t >> 5, bc = (t & 31) << 1;    // v tile 8 x 64 (float2)

    const size_t hoff = (size_t)h * NS * NS;
    const float* Ap = ATT + hoff + (size_t)(bi * 128 + ar) * NS + ac;
    const float* Bp = qkv + (size_t)br * LDQ + 5 * 1024 + h * DH + bc;

    float acc[8][4] = {};
    const int K = (bi + 1) * 128;
    float4 aR = *(const float4*)Ap;
    float2 bR = *(const float2*)Bp;

    for (int k0 = 0; k0 < K; k0 += 8) {
        As[ac + 0][ar] = aR.x; As[ac + 1][ar] = aR.y;
        As[ac + 2][ar] = aR.z; As[ac + 3][ar] = aR.w;
        *(float2*)&Bs[br][bc] = bR;
        __syncthreads();
        if (k0 + 8 < K) {
            aR = *(const float4*)(Ap + k0 + 8);
            bR = *(const float2*)(Bp + (size_t)(k0 + 8) * LDQ);
        }
#pragma unroll
        for (int kk = 0; kk < 8; kk++) {
            float4 a0 = *(float4*)&As[kk][ty * 8];
            float4 a1 = *(float4*)&As[kk][ty * 8 + 4];
            float4 bv = *(float4*)&Bs[kk][tx * 4];
            float a[8] = {a0.x, a0.y, a0.z, a0.w, a1.x, a1.y, a1.z, a1.w};
            float b[4] = {bv.x, bv.y, bv.z, bv.w};
#pragma unroll
            for (int m = 0; m < 8; m++)
#pragma unroll
                for (int n = 0; n < 4; n++)
                    acc[m][n] = fmaf(a[m], b[n], acc[m][n]);
        }
        __syncthreads();
    }

    float* Cp = ctx + (size_t)(bi * 128 + ty * 8) * DIMM + h * DH + tx * 4;
#pragma unroll
    for (int m = 0; m < 8; m++)
        *(float4*)(Cp + (size_t)m * DIMM) = make_float4(acc[m][0], acc[m][1], acc[m][2], acc[m][3]);
}

// ============================================================
extern "C" void kernel_launch(void* const* d_in, const int* in_sizes, int n_in,
                              void* d_out, int out_size) {
    const float* x    = (const float*)d_in[0];   // [1,2048,1024]
    const float* Wqkv = (const float*)d_in[1];   // [1024,6144]
    const float* Wout = (const float*)d_in[2];   // [1024,1024]
    float* out = (float*)d_out;                  // [1,2048,1024]

    float *qkv, *t1, *lk, *sc, *ctx;
    cudaGetSymbolAddress((void**)&qkv, g_qkv);
    cudaGetSymbolAddress((void**)&t1,  g_t1);
    cudaGetSymbolAddress((void**)&lk,  g_lk);
    cudaGetSymbolAddress((void**)&sc,  g_sc);
    cudaGetSymbolAddress((void**)&ctx, g_ctx);

    const dim3 thr(256);

    // 1) qkv = x @ W_qkv   [2048 x 6144]
    gemm_nn<<<dim3(LDQ / 128, NS / 128), thr>>>(x, Wqkv, qkv, DIMM, DIMM, LDQ, LDQ);

    // 2) per-head small GEMMs (K=64), triangle-skipped
    const dim3 gHead(NS / 128, NS / 128, NH);
    head_nt<1><<<gHead, thr>>>(qkv, 3 * 1024, 2 * 1024, t1);  // term1 = tril(qc_s @ vu^T)
    head_nt<2><<<gHead, thr>>>(qkv, 0 * 1024, 1 * 1024, lk);  // look  = triu1(sigmoid(qu_s @ ku^T))
    head_nt<3><<<gHead, thr>>>(qkv, 3 * 1024, 4 * 1024, sc);  // Sc    = qc_s @ kc^T (lower blocks)

    // 3) Su GEMM (triangle-restricted K range) fused with scores = Sc - silu(Su)
    su_fuse<<<gHead, thr>>>(t1, lk, sc);

    // 4) causal softmax in place (pads to 128-block boundary)
    row_softmax<<<dim3(NS, NH), thr>>>(sc);

    // 5) ctx = attn @ vc (causal K range)
    av_gemm<<<dim3(NS / 128, NH), thr>>>(sc, qkv, ctx);

    // 6) out = ctx @ W_out
    gemm_nn<<<dim3(DIMM / 128, NS / 128), thr>>>(ctx, Wout, out, DIMM, DIMM, DIMM, DIMM);
}

// round 4
// speedup vs baseline: 1.2276x; 1.1396x over previous
#include <cuda_runtime.h>
#include <cuda_bf16.h>
#include <math.h>
#include <stdint.h>

#define NS   2048     // sequence length
#define NH   16       // heads
#define DH   64       // dim per head
#define DIMM 1024     // model dim
#define LDQ  6144     // qkv row stride (6 * 1024)

__device__ __constant__ float SCALE = 0.125f;  // 64^-0.5

// ---- scratch (device globals: allocation-free) ----
__device__ float g_qkv[(size_t)NS * LDQ];                 // 50 MB
__device__ __nv_bfloat16 g_t1h[(size_t)NH * NS * NS];     // 128 MB term1 hi
__device__ __nv_bfloat16 g_t1l[(size_t)NH * NS * NS];     // 128 MB term1 lo
__device__ __nv_bfloat16 g_lkh[(size_t)NH * NS * NS];     // 128 MB lookahead hi
__device__ __nv_bfloat16 g_lkl[(size_t)NH * NS * NS];     // 128 MB lookahead lo
__device__ float g_sc [(size_t)NH * NS * NS];             // 256 MB Sc -> scores -> attn
__device__ float g_ctx[(size_t)NS * DIMM];                // 8 MB

// ============================================================
// helpers
// ============================================================
__device__ __forceinline__ uint32_t smem_u32(const void* p) {
    uint32_t a;
    asm("{ .reg .u64 t; cvta.to.shared.u64 t, %1; cvt.u32.u64 %0, t; }" : "=r"(a) : "l"(p));
    return a;
}

#define CPASYNC16(s, g) \
    asm volatile("cp.async.cg.shared.global [%0], [%1], 16;" :: "r"(s), "l"(g) : "memory")
#define CP_COMMIT() asm volatile("cp.async.commit_group;" ::: "memory")
#define CP_WAIT0()  asm volatile("cp.async.wait_group 0;" ::: "memory")
#define CP_WAIT1()  asm volatile("cp.async.wait_group 1;" ::: "memory")

#define LDMX4(r, addr) \
    asm volatile("ldmatrix.sync.aligned.m8n8.x4.shared.b16 {%0,%1,%2,%3}, [%4];" \
        : "=r"((r)[0]), "=r"((r)[1]), "=r"((r)[2]), "=r"((r)[3]) : "r"(addr))

#define MMA16816(d, a, b0, b1) \
    asm volatile("mma.sync.aligned.m16n8k16.row.col.f32.bf16.bf16.f32 " \
        "{%0,%1,%2,%3}, {%4,%5,%6,%7}, {%8,%9}, {%0,%1,%2,%3};" \
        : "+f"((d)[0]), "+f"((d)[1]), "+f"((d)[2]), "+f"((d)[3]) \
        : "r"((a)[0]), "r"((a)[1]), "r"((a)[2]), "r"((a)[3]), "r"(b0), "r"(b1))

// ============================================================
// Shared inner-product macro: 8x8 accum from As/Bs [8][128]
// ============================================================
#define MICRO_8x8(As, Bs)                                              \
    _Pragma("unroll")                                                  \
    for (int kk = 0; kk < 8; kk++) {                                   \
        float4 a0 = *(float4*)&As[kk][ty * 8];                         \
        float4 a1 = *(float4*)&As[kk][ty * 8 + 4];                     \
        float4 b0 = *(float4*)&Bs[kk][tx * 8];                         \
        float4 b1 = *(float4*)&Bs[kk][tx * 8 + 4];                     \
        float a[8] = {a0.x, a0.y, a0.z, a0.w, a1.x, a1.y, a1.z, a1.w}; \
        float b[8] = {b0.x, b0.y, b0.z, b0.w, b1.x, b1.y, b1.z, b1.w}; \
        _Pragma("unroll")                                              \
        for (int m = 0; m < 8; m++)                                    \
            _Pragma("unroll")                                          \
            for (int n = 0; n < 8; n++)                                \
                acc[m][n] = fmaf(a[m], b[n], acc[m][n]);               \
    }

// ============================================================
// Generic NN SGEMM: 128x128 tiles, BK=8, 256 threads, 8x8/thread.
// ============================================================
__global__ void gemm_nn(const float* __restrict__ A, const float* __restrict__ B,
                        float* __restrict__ C, int K, int lda, int ldb, int ldc) {
    __shared__ float As[8][128];
    __shared__ float Bs[8][128];
    const int t  = threadIdx.x;
    const int tx = t & 15, ty = t >> 4;
    const int bi = blockIdx.y, bj = blockIdx.x;
    const int ar = t >> 1, ac = (t & 1) << 2;
    const int br = t >> 5, bc = (t & 31) << 2;

    const float* Ap = A + (size_t)(bi * 128 + ar) * lda + ac;
    const float* Bp = B + (size_t)br * ldb + bj * 128 + bc;

    float acc[8][8] = {};
    float4 aR = *(const float4*)Ap;
    float4 bR = *(const float4*)Bp;

    for (int k0 = 0; k0 < K; k0 += 8) {
        As[ac + 0][ar] = aR.x; As[ac + 1][ar] = aR.y;
        As[ac + 2][ar] = aR.z; As[ac + 3][ar] = aR.w;
        *(float4*)&Bs[br][bc] = bR;
        __syncthreads();
        if (k0 + 8 < K) {
            aR = *(const float4*)(Ap + k0 + 8);
            bR = *(const float4*)(Bp + (size_t)(k0 + 8) * ldb);
        }
        MICRO_8x8(As, Bs)
        __syncthreads();
    }

    float* Cp = C + (size_t)(bi * 128 + ty * 8) * ldc + bj * 128 + tx * 8;
#pragma unroll
    for (int m = 0; m < 8; m++) {
        *(float4*)(Cp + (size_t)m * ldc)     = make_float4(acc[m][0], acc[m][1], acc[m][2], acc[m][3]);
        *(float4*)(Cp + (size_t)m * ldc + 4) = make_float4(acc[m][4], acc[m][5], acc[m][6], acc[m][7]);
    }
}

// ============================================================
// Per-head NT GEMM K=64, masked, bf16 hi/lo split output.
// MODE 1: term1 (keep j<=i else 0). MODE 2: lookahead (sigmoid, keep j>i).
// ============================================================
template <int MODE>
__global__ void head_nt_b(const float* __restrict__ qkv, int aoff, int boff,
                          __nv_bfloat16* __restrict__ CH, __nv_bfloat16* __restrict__ CL) {
    const int h  = blockIdx.z;
    const int bi = blockIdx.y, bj = blockIdx.x;
    if (MODE == 1 && bj > bi) return;
    if (MODE == 2 && bj < bi) return;

    __shared__ float As[8][128];
    __shared__ float Bs[8][128];
    const int t  = threadIdx.x;
    const int tx = t & 15, ty = t >> 4;
    const int lr = t >> 1, lc = (t & 1) << 2;

    const float* Ap = qkv + (size_t)(bi * 128 + lr) * LDQ + aoff + h * DH + lc;
    const float* Bp = qkv + (size_t)(bj * 128 + lr) * LDQ + boff + h * DH + lc;

    float acc[8][8] = {};
    float4 aR = *(const float4*)Ap;
    float4 bR = *(const float4*)Bp;

#pragma unroll
    for (int k0 = 0; k0 < 64; k0 += 8) {
        As[lc + 0][lr] = aR.x; As[lc + 1][lr] = aR.y;
        As[lc + 2][lr] = aR.z; As[lc + 3][lr] = aR.w;
        Bs[lc + 0][lr] = bR.x; Bs[lc + 1][lr] = bR.y;
        Bs[lc + 2][lr] = bR.z; Bs[lc + 3][lr] = bR.w;
        __syncthreads();
        if (k0 + 8 < 64) {
            aR = *(const float4*)(Ap + k0 + 8);
            bR = *(const float4*)(Bp + k0 + 8);
        }
        MICRO_8x8(As, Bs)
        __syncthreads();
    }

    const size_t hb = (size_t)h * NS * NS;
    const int gi = bi * 128 + ty * 8;
    const int gj = bj * 128 + tx * 8;
#pragma unroll
    for (int m = 0; m < 8; m++) {
        const int i = gi + m;
        __nv_bfloat16 oh[8], ol[8];
#pragma unroll
        for (int n = 0; n < 8; n++) {
            const int j = gj + n;
            float v = acc[m][n] * SCALE;
            if (MODE == 1) v = (j <= i) ? v : 0.0f;
            if (MODE == 2) v = (j >  i) ? (1.0f / (1.0f + expf(-v))) : 0.0f;
            __nv_bfloat16 hv = __float2bfloat16_rn(v);
            oh[n] = hv;
            ol[n] = __float2bfloat16_rn(v - __bfloat162float(hv));
        }
        __nv_bfloat16* rh = CH + hb + (size_t)i * NS + gj;
        __nv_bfloat16* rl = CL + hb + (size_t)i * NS + gj;
        *(uint4*)rh = *(uint4*)oh;
        *(uint4*)rl = *(uint4*)ol;
    }
}

// ============================================================
// Per-head NT GEMM K=64 for Sc (fp32 out, lower blocks only).
// ============================================================
__global__ void head_nt_sc(const float* __restrict__ qkv, int aoff, int boff,
                           float* __restrict__ C) {
    const int h  = blockIdx.z;
    const int bi = blockIdx.y, bj = blockIdx.x;
    if (bj > bi) return;

    __shared__ float As[8][128];
    __shared__ float Bs[8][128];
    const int t  = threadIdx.x;
    const int tx = t & 15, ty = t >> 4;
    const int lr = t >> 1, lc = (t & 1) << 2;

    const float* Ap = qkv + (size_t)(bi * 128 + lr) * LDQ + aoff + h * DH + lc;
    const float* Bp = qkv + (size_t)(bj * 128 + lr) * LDQ + boff + h * DH + lc;

    float acc[8][8] = {};
    float4 aR = *(const float4*)Ap;
    float4 bR = *(const float4*)Bp;

#pragma unroll
    for (int k0 = 0; k0 < 64; k0 += 8) {
        As[lc + 0][lr] = aR.x; As[lc + 1][lr] = aR.y;
        As[lc + 2][lr] = aR.z; As[lc + 3][lr] = aR.w;
        Bs[lc + 0][lr] = bR.x; Bs[lc + 1][lr] = bR.y;
        Bs[lc + 2][lr] = bR.z; Bs[lc + 3][lr] = bR.w;
        __syncthreads();
        if (k0 + 8 < 64) {
            aR = *(const float4*)(Ap + k0 + 8);
            bR = *(const float4*)(Bp + k0 + 8);
        }
        MICRO_8x8(As, Bs)
        __syncthreads();
    }

    float* Cb = C + (size_t)h * NS * NS;
    const int gi = bi * 128 + ty * 8;
    const int gj = bj * 128 + tx * 8;
#pragma unroll
    for (int m = 0; m < 8; m++) {
        float* row = Cb + (size_t)(gi + m) * NS + gj;
        *(float4*)(row)     = make_float4(acc[m][0] * SCALE, acc[m][1] * SCALE, acc[m][2] * SCALE, acc[m][3] * SCALE);
        *(float4*)(row + 4) = make_float4(acc[m][4] * SCALE, acc[m][5] * SCALE, acc[m][6] * SCALE, acc[m][7] * SCALE);
    }
}

// ============================================================
// Su via warp-level bf16 mma.sync (split hi/lo, 3 products):
//   Su = term1 @ look^T over K range [bk*128, (bi+1)*128)
//   fused epilogue: SC[i,k] -= silu(Su[i,k])
// CTA: 256 thr (8 warps), output 128x128; warp tile 64x32.
// cp.async double-buffered 64-wide K chunks; ldmatrix operand loads.
// ============================================================
#define SU_PADB   144                       // bytes per smem row (64 bf16 + 8 pad)
#define SU_TILEB  (128 * SU_PADB)           // 18432 B per operand tile
#define SU_BUFB   (4 * SU_TILEB)            // Ah, Al, Bh, Bl
#define SU_SMEM   (2 * SU_BUFB)             // double buffer: 147456 B

__global__ void __launch_bounds__(256) su_fuse_mma(
    const __nv_bfloat16* __restrict__ T1H, const __nv_bfloat16* __restrict__ T1L,
    const __nv_bfloat16* __restrict__ LKH, const __nv_bfloat16* __restrict__ LKL,
    float* __restrict__ SC)
{
    const int h = blockIdx.z, bi = blockIdx.y, bk = blockIdx.x;
    if (bk > bi) return;

    extern __shared__ char sm[];
    const uint32_t smb = smem_u32(sm);
    const int t = threadIdx.x;
    const int wid = t >> 5, lane = t & 31;
    const int m0 = (wid & 1) * 64;          // warp m origin in tile
    const int n0 = (wid >> 1) * 32;         // warp n origin in tile

    const size_t hb = (size_t)h * NS * NS;
    const __nv_bfloat16* srcs[4] = {
        T1H + hb + (size_t)(bi * 128) * NS,
        T1L + hb + (size_t)(bi * 128) * NS,
        LKH + hb + (size_t)(bk * 128) * NS,
        LKL + hb + (size_t)(bk * 128) * NS
    };

    // cp.async mapping: 4 groups of 64 threads, one operand tile per group.
    const int grp  = t >> 6;
    const int gg   = t & 63;
    const int col  = gg & 7;                // 16B column (8 bf16)
    const int row0 = gg >> 3;               // base row 0..7, step 8
    const __nv_bfloat16* gsrc = srcs[grp] + (size_t)row0 * NS + col * 8;
    const uint32_t sdst = smb + grp * SU_TILEB + row0 * SU_PADB + col * 16;

    const int nCh = 2 * (bi - bk + 1);

#define SU_ISSUE(c)                                                        \
    do {                                                                   \
        const __nv_bfloat16* gp = gsrc + (size_t)bk * 128 + (size_t)(c) * 64; \
        const uint32_t sb = sdst + ((c) & 1) * SU_BUFB;                    \
        _Pragma("unroll")                                                  \
        for (int kq = 0; kq < 16; kq++)                                    \
            CPASYNC16(sb + kq * 8 * SU_PADB, gp + (size_t)(kq * 8) * NS);  \
        CP_COMMIT();                                                       \
    } while (0)

    SU_ISSUE(0);

    float acc[4][4][4] = {};                 // [tm][tn][reg]

    const int lrow = lane & 15;
    const uint32_t lkoff = (uint32_t)((lane >> 4) * 16);

    for (int c = 0; c < nCh; c++) {
        if (c + 1 < nCh) { SU_ISSUE(c + 1); CP_WAIT1(); }
        else             { CP_WAIT0(); }
        __syncthreads();

        const uint32_t base = smb + (c & 1) * SU_BUFB;
        const uint32_t aH = base;
        const uint32_t aL = base + SU_TILEB;
        const uint32_t bH = base + 2 * SU_TILEB;
        const uint32_t bL = base + 3 * SU_TILEB;

#pragma unroll
        for (int kk = 0; kk < 4; kk++) {
            const uint32_t ko = kk * 32 + lkoff;
            uint32_t ah[4][4], al[4][4];
            const uint32_t aoff = (uint32_t)((m0 + lrow) * SU_PADB) + ko;
#pragma unroll
            for (int tm = 0; tm < 4; tm++) {
                LDMX4(ah[tm], aH + aoff + tm * 16 * SU_PADB);
                LDMX4(al[tm], aL + aoff + tm * 16 * SU_PADB);
            }
            uint32_t bh[2][4], bl[2][4];
            const uint32_t boff = (uint32_t)((n0 + lrow) * SU_PADB) + ko;
#pragma unroll
            for (int tp = 0; tp < 2; tp++) {
                LDMX4(bh[tp], bH + boff + tp * 16 * SU_PADB);
                LDMX4(bl[tp], bL + boff + tp * 16 * SU_PADB);
            }
#pragma unroll
            for (int tm = 0; tm < 4; tm++) {
#pragma unroll
                for (int tn = 0; tn < 4; tn++) {
                    const int tp = tn >> 1, sel = tn & 1;
                    MMA16816(acc[tm][tn], ah[tm], bh[tp][sel], bh[tp][sel + 2]);
                    MMA16816(acc[tm][tn], ah[tm], bl[tp][sel], bl[tp][sel + 2]);
                    MMA16816(acc[tm][tn], al[tm], bh[tp][sel], bh[tp][sel + 2]);
                }
            }
        }
        __syncthreads();
    }

    // epilogue: SC -= silu(Su), straight from fragments (float2 RMW)
    const int g  = lane >> 2;
    const int tg = lane & 3;
#pragma unroll
    for (int tm = 0; tm < 4; tm++) {
#pragma unroll
        for (int tn = 0; tn < 4; tn++) {
            const int i0 = bi * 128 + m0 + tm * 16 + g;
            const int j0 = bk * 128 + n0 + tn * 8 + tg * 2;
            float* p0 = SC + hb + (size_t)i0 * NS + j0;
            float* p1 = p0 + (size_t)8 * NS;
            float2 c0 = *(float2*)p0;
            float2 c1 = *(float2*)p1;
            float s0 = acc[tm][tn][0], s1 = acc[tm][tn][1];
            float s2 = acc[tm][tn][2], s3 = acc[tm][tn][3];
            c0.x -= s0 / (1.0f + expf(-s0));
            c0.y -= s1 / (1.0f + expf(-s1));
            c1.x -= s2 / (1.0f + expf(-s2));
            c1.y -= s3 / (1.0f + expf(-s3));
            *(float2*)p0 = c0;
            *(float2*)p1 = c1;
        }
    }
}

// ============================================================
// Row softmax (causal), zero-pads row to next 128 boundary.
// ============================================================
__global__ void row_softmax(float* __restrict__ SC) {
    const int h = blockIdx.y, i = blockIdx.x;
    float* row = SC + (size_t)h * NS * NS + (size_t)i * NS;
    const int t = threadIdx.x;
    const int len = i + 1;

    __shared__ float red[256];

    float lmax = -1e30f;
    for (int j = t; j < len; j += 256) lmax = fmaxf(lmax, row[j]);
    red[t] = lmax; __syncthreads();
    for (int s = 128; s > 0; s >>= 1) { if (t < s) red[t] = fmaxf(red[t], red[t + s]); __syncthreads(); }
    const float bmax = red[0];
    __syncthreads();

    float lsum = 0.0f;
    for (int j = t; j < len; j += 256) {
        float e = expf(row[j] - bmax);
        row[j] = e;
        lsum += e;
    }
    red[t] = lsum; __syncthreads();
    for (int s = 128; s > 0; s >>= 1) { if (t < s) red[t] += red[t + s]; __syncthreads(); }
    const float inv = 1.0f / red[0];
    __syncthreads();

    for (int j = t; j < len; j += 256) row[j] *= inv;

    const int padEnd = ((i >> 7) + 1) << 7;
    for (int j = len + t; j < padEnd; j += 256) row[j] = 0.0f;
}

// ============================================================
// AV GEMM: ctx = attn @ vc (causal K range). M=128, N=64, BK=8.
// ============================================================
__global__ void av_gemm(const float* __restrict__ ATT, const float* __restrict__ qkv,
                        float* __restrict__ ctx) {
    const int h = blockIdx.y, bi = blockIdx.x;
    __shared__ float As[8][128];
    __shared__ float Bs[8][64];
    const int t  = threadIdx.x;
    const int tx = t & 15, ty = t >> 4;
    const int ar = t >> 1, ac = (t & 1) << 2;
    const int br = t >> 5, bc = (t & 31) << 1;

    const size_t hoff = (size_t)h * NS * NS;
    const float* Ap = ATT + hoff + (size_t)(bi * 128 + ar) * NS + ac;
    const float* Bp = qkv + (size_t)br * LDQ + 5 * 1024 + h * DH + bc;

    float acc[8][4] = {};
    const int K = (bi + 1) * 128;
    float4 aR = *(const float4*)Ap;
    float2 bR = *(const float2*)Bp;

    for (int k0 = 0; k0 < K; k0 += 8) {
        As[ac + 0][ar] = aR.x; As[ac + 1][ar] = aR.y;
        As[ac + 2][ar] = aR.z; As[ac + 3][ar] = aR.w;
        *(float2*)&Bs[br][bc] = bR;
        __syncthreads();
        if (k0 + 8 < K) {
            aR = *(const float4*)(Ap + k0 + 8);
            bR = *(const float2*)(Bp + (size_t)(k0 + 8) * LDQ);
        }
#pragma unroll
        for (int kk = 0; kk < 8; kk++) {
            float4 a0 = *(float4*)&As[kk][ty * 8];
            float4 a1 = *(float4*)&As[kk][ty * 8 + 4];
            float4 bv = *(float4*)&Bs[kk][tx * 4];
            float a[8] = {a0.x, a0.y, a0.z, a0.w, a1.x, a1.y, a1.z, a1.w};
            float b[4] = {bv.x, bv.y, bv.z, bv.w};
#pragma unroll
            for (int m = 0; m < 8; m++)
#pragma unroll
                for (int n = 0; n < 4; n++)
                    acc[m][n] = fmaf(a[m], b[n], acc[m][n]);
        }
        __syncthreads();
    }

    float* Cp = ctx + (size_t)(bi * 128 + ty * 8) * DIMM + h * DH + tx * 4;
#pragma unroll
    for (int m = 0; m < 8; m++)
        *(float4*)(Cp + (size_t)m * DIMM) = make_float4(acc[m][0], acc[m][1], acc[m][2], acc[m][3]);
}

// ============================================================
extern "C" void kernel_launch(void* const* d_in, const int* in_sizes, int n_in,
                              void* d_out, int out_size) {
    const float* x    = (const float*)d_in[0];
    const float* Wqkv = (const float*)d_in[1];
    const float* Wout = (const float*)d_in[2];
    float* out = (float*)d_out;

    float *qkv, *sc, *ctx;
    __nv_bfloat16 *t1h, *t1l, *lkh, *lkl;
    cudaGetSymbolAddress((void**)&qkv, g_qkv);
    cudaGetSymbolAddress((void**)&t1h, g_t1h);
    cudaGetSymbolAddress((void**)&t1l, g_t1l);
    cudaGetSymbolAddress((void**)&lkh, g_lkh);
    cudaGetSymbolAddress((void**)&lkl, g_lkl);
    cudaGetSymbolAddress((void**)&sc,  g_sc);
    cudaGetSymbolAddress((void**)&ctx, g_ctx);

    cudaFuncSetAttribute(su_fuse_mma, cudaFuncAttributeMaxDynamicSharedMemorySize, SU_SMEM);

    const dim3 thr(256);

    // 1) qkv = x @ W_qkv
    gemm_nn<<<dim3(LDQ / 128, NS / 128), thr>>>(x, Wqkv, qkv, DIMM, DIMM, LDQ, LDQ);

    // 2) per-head K=64 GEMMs, triangle-skipped
    const dim3 gHead(NS / 128, NS / 128, NH);
    head_nt_b<1><<<gHead, thr>>>(qkv, 3 * 1024, 2 * 1024, t1h, t1l);  // term1 (bf16 hi/lo)
    head_nt_b<2><<<gHead, thr>>>(qkv, 0 * 1024, 1 * 1024, lkh, lkl);  // lookahead (bf16 hi/lo)
    head_nt_sc  <<<gHead, thr>>>(qkv, 3 * 1024, 4 * 1024, sc);        // Sc (fp32)

    // 3) Su via bf16-split mma.sync, fused scores = Sc - silu(Su)
    su_fuse_mma<<<gHead, thr, SU_SMEM>>>(t1h, t1l, lkh, lkl, sc);

    // 4) causal softmax in place
    row_softmax<<<dim3(NS, NH), thr>>>(sc);

    // 5) ctx = attn @ vc
    av_gemm<<<dim3(NS / 128, NH), thr>>>(sc, qkv, ctx);

    // 6) out = ctx @ W_out
    gemm_nn<<<dim3(DIMM / 128, NS / 128), thr>>>(ctx, Wout, out, DIMM, DIMM, DIMM, DIMM);
}

// round 5
// speedup vs baseline: 1.5350x; 1.2504x over previous
#include <cuda_runtime.h>
#include <cuda_bf16.h>
#include <math.h>
#include <stdint.h>

#define NS   2048
#define NH   16
#define DH   64
#define DIMM 1024
#define LDQ  6144

__device__ __constant__ float SCALE = 0.125f;

// ---- scratch ----
__device__ float g_qkv[(size_t)NS * LDQ];                 // fp32 qkv (for av_gemm vc)
__device__ __nv_bfloat16 g_qh [(size_t)NS * LDQ];         // qkv hi
__device__ __nv_bfloat16 g_ql [(size_t)NS * LDQ];         // qkv lo
__device__ __nv_bfloat16 g_xh [(size_t)NS * DIMM];
__device__ __nv_bfloat16 g_xl [(size_t)NS * DIMM];
__device__ __nv_bfloat16 g_wqh[(size_t)LDQ * DIMM];       // W_qkv^T hi [6144 x 1024]
__device__ __nv_bfloat16 g_wql[(size_t)LDQ * DIMM];
__device__ __nv_bfloat16 g_t1h[(size_t)NH * NS * NS];
__device__ __nv_bfloat16 g_t1l[(size_t)NH * NS * NS];
__device__ __nv_bfloat16 g_lkh[(size_t)NH * NS * NS];
__device__ __nv_bfloat16 g_lkl[(size_t)NH * NS * NS];
__device__ float g_sc [(size_t)NH * NS * NS];
__device__ float g_ctx[(size_t)NS * DIMM];

// ============================================================
// helpers
// ============================================================
__device__ __forceinline__ uint32_t smem_u32(const void* p) {
    uint32_t a;
    asm("{ .reg .u64 t; cvta.to.shared.u64 t, %1; cvt.u32.u64 %0, t; }" : "=r"(a) : "l"(p));
    return a;
}

#define CPASYNC16(s, g) \
    asm volatile("cp.async.cg.shared.global [%0], [%1], 16;" :: "r"(s), "l"(g) : "memory")
#define CP_COMMIT() asm volatile("cp.async.commit_group;" ::: "memory")
#define CP_WAIT0()  asm volatile("cp.async.wait_group 0;" ::: "memory")
#define CP_WAIT1()  asm volatile("cp.async.wait_group 1;" ::: "memory")

#define LDMX4(r, addr) \
    asm volatile("ldmatrix.sync.aligned.m8n8.x4.shared.b16 {%0,%1,%2,%3}, [%4];" \
        : "=r"((r)[0]), "=r"((r)[1]), "=r"((r)[2]), "=r"((r)[3]) : "r"(addr))

#define MMA16816(d, a, b0, b1) \
    asm volatile("mma.sync.aligned.m16n8k16.row.col.f32.bf16.bf16.f32 " \
        "{%0,%1,%2,%3}, {%4,%5,%6,%7}, {%8,%9}, {%0,%1,%2,%3};" \
        : "+f"((d)[0]), "+f"((d)[1]), "+f"((d)[2]), "+f"((d)[3]) \
        : "r"((a)[0]), "r"((a)[1]), "r"((a)[2]), "r"((a)[3]), "r"(b0), "r"(b1))

__device__ __forceinline__ uint32_t pack_bf2(float a, float b) {
    __nv_bfloat162 t = __floats2bfloat162_rn(a, b);
    return *(uint32_t*)&t;
}
__device__ __forceinline__ void split1(float v, __nv_bfloat16& h, float& r) {
    h = __float2bfloat16_rn(v);
    r = v - __bfloat162float(h);
}

#define PADB   144
#define TILEB  (128 * PADB)
#define BUFB   (4 * TILEB)
#define DBUF_SMEM (2 * BUFB)    // 147456
#define SBUF_SMEM BUFB          // 73728

// ============================================================
// conversion kernels
// ============================================================
__global__ void conv_split(const float* __restrict__ src,
                           __nv_bfloat16* __restrict__ hi, __nv_bfloat16* __restrict__ lo,
                           int n) {
    int i = blockIdx.x * 256 + threadIdx.x;
    if (i >= n) return;
    float v = src[i];
    __nv_bfloat16 h; float r;
    split1(v, h, r);
    hi[i] = h;
    lo[i] = __float2bfloat16_rn(r);
}

// dst[C x R] = src[R x C]^T, split bf16
__global__ void conv_split_T(const float* __restrict__ src,
                             __nv_bfloat16* __restrict__ hi, __nv_bfloat16* __restrict__ lo,
                             int R, int C) {
    __shared__ float tile[32][33];
    const int bx = blockIdx.x * 32, by = blockIdx.y * 32;
    const int tx = threadIdx.x, ty = threadIdx.y;
#pragma unroll
    for (int i = 0; i < 32; i += 8)
        tile[ty + i][tx] = src[(size_t)(by + ty + i) * C + bx + tx];
    __syncthreads();
#pragma unroll
    for (int i = 0; i < 32; i += 8) {
        float v = tile[tx][ty + i];
        __nv_bfloat16 h; float r;
        split1(v, h, r);
        size_t o = (size_t)(bx + ty + i) * R + by + tx;
        hi[o] = h;
        lo[o] = __float2bfloat16_rn(r);
    }
}

// ============================================================
// qkv = x @ Wqkv via split-bf16 mma (NT: B = Wqkv^T, k-contig)
// Tile 128x128, K=1024 in 16 chunks of 64, double-buffered.
// Epilogue writes fp32 qkv + split bf16 qkv.
// ============================================================
__global__ void __launch_bounds__(256) qkv_mma(
    const __nv_bfloat16* __restrict__ XH, const __nv_bfloat16* __restrict__ XL,
    const __nv_bfloat16* __restrict__ WH, const __nv_bfloat16* __restrict__ WL,
    float* __restrict__ QKV, __nv_bfloat16* __restrict__ QH, __nv_bfloat16* __restrict__ QL)
{
    const int bm = blockIdx.y, bn = blockIdx.x;
    extern __shared__ char sm[];
    const uint32_t smb = smem_u32(sm);
    const int t = threadIdx.x;
    const int wid = t >> 5, lane = t & 31;
    const int m0 = (wid & 1) * 64;
    const int n0 = (wid >> 1) * 32;

    // cp.async mapping
    const int grp  = t >> 6;
    const int gg   = t & 63;
    const int col  = gg & 7;
    const int row0 = gg >> 3;
    const __nv_bfloat16* base;
    if (grp == 0)      base = XH + (size_t)(bm * 128) * DIMM;
    else if (grp == 1) base = XL + (size_t)(bm * 128) * DIMM;
    else if (grp == 2) base = WH + (size_t)(bn * 128) * DIMM;
    else               base = WL + (size_t)(bn * 128) * DIMM;
    const __nv_bfloat16* gsrc = base + (size_t)row0 * DIMM + col * 8;
    const uint32_t sdst = smb + grp * TILEB + row0 * PADB + col * 16;

#define QKV_ISSUE(c)                                                       \
    do {                                                                   \
        const __nv_bfloat16* gp = gsrc + (size_t)(c) * 64;                 \
        const uint32_t sb = sdst + ((c) & 1) * BUFB;                       \
        _Pragma("unroll")                                                  \
        for (int kq = 0; kq < 16; kq++)                                    \
            CPASYNC16(sb + kq * 8 * PADB, gp + (size_t)(kq * 8) * DIMM);   \
        CP_COMMIT();                                                       \
    } while (0)

    QKV_ISSUE(0);

    float acc[4][4][4] = {};
    const int lrow = lane & 15;
    const uint32_t lkoff = (uint32_t)((lane >> 4) * 16);

    for (int c = 0; c < 16; c++) {
        if (c + 1 < 16) { QKV_ISSUE(c + 1); CP_WAIT1(); }
        else            { CP_WAIT0(); }
        __syncthreads();

        const uint32_t bse = smb + (c & 1) * BUFB;
        const uint32_t aH = bse, aL = bse + TILEB, bH = bse + 2 * TILEB, bL = bse + 3 * TILEB;

#pragma unroll
        for (int kk = 0; kk < 4; kk++) {
            const uint32_t ko = kk * 32 + lkoff;
            uint32_t ah[4][4], al[4][4];
            const uint32_t aoff = (uint32_t)((m0 + lrow) * PADB) + ko;
#pragma unroll
            for (int tm = 0; tm < 4; tm++) {
                LDMX4(ah[tm], aH + aoff + tm * 16 * PADB);
                LDMX4(al[tm], aL + aoff + tm * 16 * PADB);
            }
            uint32_t bh[2][4], bl[2][4];
            const uint32_t boff = (uint32_t)((n0 + lrow) * PADB) + ko;
#pragma unroll
            for (int tp = 0; tp < 2; tp++) {
                LDMX4(bh[tp], bH + boff + tp * 16 * PADB);
                LDMX4(bl[tp], bL + boff + tp * 16 * PADB);
            }
#pragma unroll
            for (int tm = 0; tm < 4; tm++) {
#pragma unroll
                for (int tn = 0; tn < 4; tn++) {
                    const int tp = tn >> 1, sel = tn & 1;
                    MMA16816(acc[tm][tn], ah[tm], bh[tp][sel], bh[tp][sel + 2]);
                    MMA16816(acc[tm][tn], ah[tm], bl[tp][sel], bl[tp][sel + 2]);
                    MMA16816(acc[tm][tn], al[tm], bh[tp][sel], bh[tp][sel + 2]);
                }
            }
        }
        __syncthreads();
    }

    const int g  = lane >> 2;
    const int tg = lane & 3;
#pragma unroll
    for (int tm = 0; tm < 4; tm++) {
#pragma unroll
        for (int tn = 0; tn < 4; tn++) {
            const int i0 = bm * 128 + m0 + tm * 16 + g;
            const int j0 = bn * 128 + n0 + tn * 8 + tg * 2;
            float v0 = acc[tm][tn][0], v1 = acc[tm][tn][1];
            float v2 = acc[tm][tn][2], v3 = acc[tm][tn][3];
            size_t o0 = (size_t)i0 * LDQ + j0;
            size_t o1 = o0 + (size_t)8 * LDQ;
            *(float2*)(QKV + o0) = make_float2(v0, v1);
            *(float2*)(QKV + o1) = make_float2(v2, v3);
            __nv_bfloat16 h; float r;
            float r0, r1, r2, r3;
            split1(v0, h, r0); split1(v1, h, r1); split1(v2, h, r2); split1(v3, h, r3);
            *(uint32_t*)(QH + o0) = pack_bf2(v0, v1);
            *(uint32_t*)(QH + o1) = pack_bf2(v2, v3);
            *(uint32_t*)(QL + o0) = pack_bf2(r0, r1);
            *(uint32_t*)(QL + o1) = pack_bf2(r2, r3);
        }
    }
}

// ============================================================
// Per-head NT GEMM K=64 on split-bf16 qkv via mma.
// MODE 1: term1 -> split bf16. MODE 2: lookahead(sigmoid) -> split bf16.
// MODE 3: Sc -> fp32.
// ============================================================
template <int MODE>
__global__ void __launch_bounds__(256) head_mma(
    const __nv_bfloat16* __restrict__ QH, const __nv_bfloat16* __restrict__ QL,
    int aoff, int boff,
    __nv_bfloat16* __restrict__ CH, __nv_bfloat16* __restrict__ CL,
    float* __restrict__ CF)
{
    const int h  = blockIdx.z;
    const int bi = blockIdx.y, bj = blockIdx.x;
    if (MODE != 2 && bj > bi) return;
    if (MODE == 2 && bj < bi) return;

    extern __shared__ char sm[];
    const uint32_t smb = smem_u32(sm);
    const int t = threadIdx.x;
    const int wid = t >> 5, lane = t & 31;
    const int m0 = (wid & 1) * 64;
    const int n0 = (wid >> 1) * 32;

    const int grp  = t >> 6;
    const int gg   = t & 63;
    const int col  = gg & 7;
    const int row0 = gg >> 3;
    const __nv_bfloat16* base;
    if (grp == 0)      base = QH + (size_t)(bi * 128) * LDQ + aoff + h * DH;
    else if (grp == 1) base = QL + (size_t)(bi * 128) * LDQ + aoff + h * DH;
    else if (grp == 2) base = QH + (size_t)(bj * 128) * LDQ + boff + h * DH;
    else               base = QL + (size_t)(bj * 128) * LDQ + boff + h * DH;
    const __nv_bfloat16* gsrc = base + (size_t)row0 * LDQ + col * 8;
    const uint32_t sdst = smb + grp * TILEB + row0 * PADB + col * 16;

#pragma unroll
    for (int kq = 0; kq < 16; kq++)
        CPASYNC16(sdst + kq * 8 * PADB, gsrc + (size_t)(kq * 8) * LDQ);
    CP_COMMIT();
    CP_WAIT0();
    __syncthreads();

    float acc[4][4][4] = {};
    const int lrow = lane & 15;
    const uint32_t lkoff = (uint32_t)((lane >> 4) * 16);
    const uint32_t aH = smb, aL = smb + TILEB, bH = smb + 2 * TILEB, bL = smb + 3 * TILEB;

#pragma unroll
    for (int kk = 0; kk < 4; kk++) {
        const uint32_t ko = kk * 32 + lkoff;
        uint32_t ah[4][4], al[4][4];
        const uint32_t aoff2 = (uint32_t)((m0 + lrow) * PADB) + ko;
#pragma unroll
        for (int tm = 0; tm < 4; tm++) {
            LDMX4(ah[tm], aH + aoff2 + tm * 16 * PADB);
            LDMX4(al[tm], aL + aoff2 + tm * 16 * PADB);
        }
        uint32_t bh[2][4], bl[2][4];
        const uint32_t boff2 = (uint32_t)((n0 + lrow) * PADB) + ko;
#pragma unroll
        for (int tp = 0; tp < 2; tp++) {
            LDMX4(bh[tp], bH + boff2 + tp * 16 * PADB);
            LDMX4(bl[tp], bL + boff2 + tp * 16 * PADB);
        }
#pragma unroll
        for (int tm = 0; tm < 4; tm++) {
#pragma unroll
            for (int tn = 0; tn < 4; tn++) {
                const int tp = tn >> 1, sel = tn & 1;
                MMA16816(acc[tm][tn], ah[tm], bh[tp][sel], bh[tp][sel + 2]);
                MMA16816(acc[tm][tn], ah[tm], bl[tp][sel], bl[tp][sel + 2]);
                MMA16816(acc[tm][tn], al[tm], bh[tp][sel], bh[tp][sel + 2]);
            }
        }
    }

    const size_t hb = (size_t)h * NS * NS;
    const int g  = lane >> 2;
    const int tg = lane & 3;
#pragma unroll
    for (int tm = 0; tm < 4; tm++) {
#pragma unroll
        for (int tn = 0; tn < 4; tn++) {
            const int i0 = bi * 128 + m0 + tm * 16 + g;
            const int j0 = bj * 128 + n0 + tn * 8 + tg * 2;
            float v[4];
            v[0] = acc[tm][tn][0] * SCALE; v[1] = acc[tm][tn][1] * SCALE;
            v[2] = acc[tm][tn][2] * SCALE; v[3] = acc[tm][tn][3] * SCALE;
            const int ii[4] = {i0, i0, i0 + 8, i0 + 8};
            const int jj[4] = {j0, j0 + 1, j0, j0 + 1};
#pragma unroll
            for (int q = 0; q < 4; q++) {
                if (MODE == 1) v[q] = (jj[q] <= ii[q]) ? v[q] : 0.0f;
                if (MODE == 2) v[q] = (jj[q] >  ii[q]) ? (1.0f / (1.0f + expf(-v[q]))) : 0.0f;
            }
            size_t o0 = hb + (size_t)i0 * NS + j0;
            size_t o1 = o0 + (size_t)8 * NS;
            if (MODE == 3) {
                *(float2*)(CF + o0) = make_float2(v[0], v[1]);
                *(float2*)(CF + o1) = make_float2(v[2], v[3]);
            } else {
                __nv_bfloat16 hh; float r[4];
                split1(v[0], hh, r[0]); split1(v[1], hh, r[1]);
                split1(v[2], hh, r[2]); split1(v[3], hh, r[3]);
                *(uint32_t*)(CH + o0) = pack_bf2(v[0], v[1]);
                *(uint32_t*)(CH + o1) = pack_bf2(v[2], v[3]);
                *(uint32_t*)(CL + o0) = pack_bf2(r[0], r[1]);
                *(uint32_t*)(CL + o1) = pack_bf2(r[2], r[3]);
            }
        }
    }
}

// ============================================================
// Su via split-bf16 mma, fused SC -= silu(Su). (unchanged from R4)
// ============================================================
__global__ void __launch_bounds__(256) su_fuse_mma(
    const __nv_bfloat16* __restrict__ T1H, const __nv_bfloat16* __restrict__ T1L,
    const __nv_bfloat16* __restrict__ LKH, const __nv_bfloat16* __restrict__ LKL,
    float* __restrict__ SC)
{
    const int h = blockIdx.z, bi = blockIdx.y, bk = blockIdx.x;
    if (bk > bi) return;

    extern __shared__ char sm[];
    const uint32_t smb = smem_u32(sm);
    const int t = threadIdx.x;
    const int wid = t >> 5, lane = t & 31;
    const int m0 = (wid & 1) * 64;
    const int n0 = (wid >> 1) * 32;

    const size_t hb = (size_t)h * NS * NS;
    const __nv_bfloat16* srcs[4] = {
        T1H + hb + (size_t)(bi * 128) * NS,
        T1L + hb + (size_t)(bi * 128) * NS,
        LKH + hb + (size_t)(bk * 128) * NS,
        LKL + hb + (size_t)(bk * 128) * NS
    };

    const int grp  = t >> 6;
    const int gg   = t & 63;
    const int col  = gg & 7;
    const int row0 = gg >> 3;
    const __nv_bfloat16* gsrc = srcs[grp] + (size_t)row0 * NS + col * 8;
    const uint32_t sdst = smb + grp * TILEB + row0 * PADB + col * 16;

    const int nCh = 2 * (bi - bk + 1);

#define SU_ISSUE(c)                                                        \
    do {                                                                   \
        const __nv_bfloat16* gp = gsrc + (size_t)bk * 128 + (size_t)(c) * 64; \
        const uint32_t sb = sdst + ((c) & 1) * BUFB;                       \
        _Pragma("unroll")                                                  \
        for (int kq = 0; kq < 16; kq++)                                    \
            CPASYNC16(sb + kq * 8 * PADB, gp + (size_t)(kq * 8) * NS);     \
        CP_COMMIT();                                                       \
    } while (0)

    SU_ISSUE(0);

    float acc[4][4][4] = {};
    const int lrow = lane & 15;
    const uint32_t lkoff = (uint32_t)((lane >> 4) * 16);

    for (int c = 0; c < nCh; c++) {
        if (c + 1 < nCh) { SU_ISSUE(c + 1); CP_WAIT1(); }
        else             { CP_WAIT0(); }
        __syncthreads();

        const uint32_t bse = smb + (c & 1) * BUFB;
        const uint32_t aH = bse, aL = bse + TILEB, bH = bse + 2 * TILEB, bL = bse + 3 * TILEB;

#pragma unroll
        for (int kk = 0; kk < 4; kk++) {
            const uint32_t ko = kk * 32 + lkoff;
            uint32_t ah[4][4], al[4][4];
            const uint32_t aoff = (uint32_t)((m0 + lrow) * PADB) + ko;
#pragma unroll
            for (int tm = 0; tm < 4; tm++) {
                LDMX4(ah[tm], aH + aoff + tm * 16 * PADB);
                LDMX4(al[tm], aL + aoff + tm * 16 * PADB);
            }
            uint32_t bh[2][4], bl[2][4];
            const uint32_t boff = (uint32_t)((n0 + lrow) * PADB) + ko;
#pragma unroll
            for (int tp = 0; tp < 2; tp++) {
                LDMX4(bh[tp], bH + boff + tp * 16 * PADB);
                LDMX4(bl[tp], bL + boff + tp * 16 * PADB);
            }
#pragma unroll
            for (int tm = 0; tm < 4; tm++) {
#pragma unroll
                for (int tn = 0; tn < 4; tn++) {
                    const int tp = tn >> 1, sel = tn & 1;
                    MMA16816(acc[tm][tn], ah[tm], bh[tp][sel], bh[tp][sel + 2]);
                    MMA16816(acc[tm][tn], ah[tm], bl[tp][sel], bl[tp][sel + 2]);
                    MMA16816(acc[tm][tn], al[tm], bh[tp][sel], bh[tp][sel + 2]);
                }
            }
        }
        __syncthreads();
    }

    const int g  = lane >> 2;
    const int tg = lane & 3;
#pragma unroll
    for (int tm = 0; tm < 4; tm++) {
#pragma unroll
        for (int tn = 0; tn < 4; tn++) {
            const int i0 = bi * 128 + m0 + tm * 16 + g;
            const int j0 = bk * 128 + n0 + tn * 8 + tg * 2;
            float* p0 = SC + hb + (size_t)i0 * NS + j0;
            float* p1 = p0 + (size_t)8 * NS;
            float2 c0 = *(float2*)p0;
            float2 c1 = *(float2*)p1;
            float s0 = acc[tm][tn][0], s1 = acc[tm][tn][1];
            float s2 = acc[tm][tn][2], s3 = acc[tm][tn][3];
            c0.x -= s0 / (1.0f + expf(-s0));
            c0.y -= s1 / (1.0f + expf(-s1));
            c1.x -= s2 / (1.0f + expf(-s2));
            c1.y -= s3 / (1.0f + expf(-s3));
            *(float2*)p0 = c0;
            *(float2*)p1 = c1;
        }
    }
}

// ============================================================
// Row softmax (causal), zero-pads row to next 128 boundary.
// ============================================================
__global__ void row_softmax(float* __restrict__ SC) {
    const int h = blockIdx.y, i = blockIdx.x;
    float* row = SC + (size_t)h * NS * NS + (size_t)i * NS;
    const int t = threadIdx.x;
    const int len = i + 1;

    __shared__ float red[256];

    float lmax = -1e30f;
    for (int j = t; j < len; j += 256) lmax = fmaxf(lmax, row[j]);
    red[t] = lmax; __syncthreads();
    for (int s = 128; s > 0; s >>= 1) { if (t < s) red[t] = fmaxf(red[t], red[t + s]); __syncthreads(); }
    const float bmax = red[0];
    __syncthreads();

    float lsum = 0.0f;
    for (int j = t; j < len; j += 256) {
        float e = expf(row[j] - bmax);
        row[j] = e;
        lsum += e;
    }
    red[t] = lsum; __syncthreads();
    for (int s = 128; s > 0; s >>= 1) { if (t < s) red[t] += red[t + s]; __syncthreads(); }
    const float inv = 1.0f / red[0];
    __syncthreads();

    for (int j = t; j < len; j += 256) row[j] *= inv;

    const int padEnd = ((i >> 7) + 1) << 7;
    for (int j = len + t; j < padEnd; j += 256) row[j] = 0.0f;
}

// ============================================================
// AV GEMM (FFMA): ctx = attn @ vc. M=128, N=64, BK=8, causal K.
// ============================================================
__global__ void av_gemm(const float* __restrict__ ATT, const float* __restrict__ qkv,
                        float* __restrict__ ctx) {
    const int h = blockIdx.y, bi = blockIdx.x;
    __shared__ float As[8][128];
    __shared__ float Bs[8][64];
    const int t  = threadIdx.x;
    const int tx = t & 15, ty = t >> 4;
    const int ar = t >> 1, ac = (t & 1) << 2;
    const int br = t >> 5, bc = (t & 31) << 1;

    const size_t hoff = (size_t)h * NS * NS;
    const float* Ap = ATT + hoff + (size_t)(bi * 128 + ar) * NS + ac;
    const float* Bp = qkv + (size_t)br * LDQ + 5 * 1024 + h * DH + bc;

    float acc[8][4] = {};
    const int K = (bi + 1) * 128;
    float4 aR = *(const float4*)Ap;
    float2 bR = *(const float2*)Bp;

    for (int k0 = 0; k0 < K; k0 += 8) {
        As[ac + 0][ar] = aR.x; As[ac + 1][ar] = aR.y;
        As[ac + 2][ar] = aR.z; As[ac + 3][ar] = aR.w;
        *(float2*)&Bs[br][bc] = bR;
        __syncthreads();
        if (k0 + 8 < K) {
            aR = *(const float4*)(Ap + k0 + 8);
            bR = *(const float2*)(Bp + (size_t)(k0 + 8) * LDQ);
        }
#pragma unroll
        for (int kk = 0; kk < 8; kk++) {
            float4 a0 = *(float4*)&As[kk][ty * 8];
            float4 a1 = *(float4*)&As[kk][ty * 8 + 4];
            float4 bv = *(float4*)&Bs[kk][tx * 4];
            float a[8] = {a0.x, a0.y, a0.z, a0.w, a1.x, a1.y, a1.z, a1.w};
            float b[4] = {bv.x, bv.y, bv.z, bv.w};
#pragma unroll
            for (int m = 0; m < 8; m++)
#pragma unroll
                for (int n = 0; n < 4; n++)
                    acc[m][n] = fmaf(a[m], b[n], acc[m][n]);
        }
        __syncthreads();
    }

    float* Cp = ctx + (size_t)(bi * 128 + ty * 8) * DIMM + h * DH + tx * 4;
#pragma unroll
    for (int m = 0; m < 8; m++)
        *(float4*)(Cp + (size_t)m * DIMM) = make_float4(acc[m][0], acc[m][1], acc[m][2], acc[m][3]);
}

// ============================================================
// Generic NN SGEMM (FFMA) for the output projection.
// ============================================================
#define MICRO_8x8(As, Bs)                                              \
    _Pragma("unroll")                                                  \
    for (int kk = 0; kk < 8; kk++) {                                   \
        float4 a0 = *(float4*)&As[kk][ty * 8];                         \
        float4 a1 = *(float4*)&As[kk][ty * 8 + 4];                     \
        float4 b0 = *(float4*)&Bs[kk][tx * 8];                         \
        float4 b1 = *(float4*)&Bs[kk][tx * 8 + 4];                     \
        float a[8] = {a0.x, a0.y, a0.z, a0.w, a1.x, a1.y, a1.z, a1.w}; \
        float b[8] = {b0.x, b0.y, b0.z, b0.w, b1.x, b1.y, b1.z, b1.w}; \
        _Pragma("unroll")                                              \
        for (int m = 0; m < 8; m++)                                    \
            _Pragma("unroll")                                          \
            for (int n = 0; n < 8; n++)                                \
                acc[m][n] = fmaf(a[m], b[n], acc[m][n]);               \
    }

__global__ void gemm_nn(const float* __restrict__ A, const float* __restrict__ B,
                        float* __restrict__ C, int K, int lda, int ldb, int ldc) {
    __shared__ float As[8][128];
    __shared__ float Bs[8][128];
    const int t  = threadIdx.x;
    const int tx = t & 15, ty = t >> 4;
    const int bi = blockIdx.y, bj = blockIdx.x;
    const int ar = t >> 1, ac = (t & 1) << 2;
    const int br = t >> 5, bc = (t & 31) << 2;

    const float* Ap = A + (size_t)(bi * 128 + ar) * lda + ac;
    const float* Bp = B + (size_t)br * ldb + bj * 128 + bc;

    float acc[8][8] = {};
    float4 aR = *(const float4*)Ap;
    float4 bR = *(const float4*)Bp;

    for (int k0 = 0; k0 < K; k0 += 8) {
        As[ac + 0][ar] = aR.x; As[ac + 1][ar] = aR.y;
        As[ac + 2][ar] = aR.z; As[ac + 3][ar] = aR.w;
        *(float4*)&Bs[br][bc] = bR;
        __syncthreads();
        if (k0 + 8 < K) {
            aR = *(const float4*)(Ap + k0 + 8);
            bR = *(const float4*)(Bp + (size_t)(k0 + 8) * ldb);
        }
        MICRO_8x8(As, Bs)
        __syncthreads();
    }

    float* Cp = C + (size_t)(bi * 128 + ty * 8) * ldc + bj * 128 + tx * 8;
#pragma unroll
    for (int m = 0; m < 8; m++) {
        *(float4*)(Cp + (size_t)m * ldc)     = make_float4(acc[m][0], acc[m][1], acc[m][2], acc[m][3]);
        *(float4*)(Cp + (size_t)m * ldc + 4) = make_float4(acc[m][4], acc[m][5], acc[m][6], acc[m][7]);
    }
}

// ============================================================
extern "C" void kernel_launch(void* const* d_in, const int* in_sizes, int n_in,
                              void* d_out, int out_size) {
    const float* x    = (const float*)d_in[0];
    const float* Wqkv = (const float*)d_in[1];
    const float* Wout = (const float*)d_in[2];
    float* out = (float*)d_out;

    float *qkv, *sc, *ctx;
    __nv_bfloat16 *qh, *ql, *xh, *xl, *wqh, *wql, *t1h, *t1l, *lkh, *lkl;
    cudaGetSymbolAddress((void**)&qkv, g_qkv);
    cudaGetSymbolAddress((void**)&qh,  g_qh);
    cudaGetSymbolAddress((void**)&ql,  g_ql);
    cudaGetSymbolAddress((void**)&xh,  g_xh);
    cudaGetSymbolAddress((void**)&xl,  g_xl);
    cudaGetSymbolAddress((void**)&wqh, g_wqh);
    cudaGetSymbolAddress((void**)&wql, g_wql);
    cudaGetSymbolAddress((void**)&t1h, g_t1h);
    cudaGetSymbolAddress((void**)&t1l, g_t1l);
    cudaGetSymbolAddress((void**)&lkh, g_lkh);
    cudaGetSymbolAddress((void**)&lkl, g_lkl);
    cudaGetSymbolAddress((void**)&sc,  g_sc);
    cudaGetSymbolAddress((void**)&ctx, g_ctx);

    cudaFuncSetAttribute(qkv_mma,     cudaFuncAttributeMaxDynamicSharedMemorySize, DBUF_SMEM);
    cudaFuncSetAttribute(su_fuse_mma, cudaFuncAttributeMaxDynamicSharedMemorySize, DBUF_SMEM);
    cudaFuncSetAttribute(head_mma<1>, cudaFuncAttributeMaxDynamicSharedMemorySize, SBUF_SMEM);
    cudaFuncSetAttribute(head_mma<2>, cudaFuncAttributeMaxDynamicSharedMemorySize, SBUF_SMEM);
    cudaFuncSetAttribute(head_mma<3>, cudaFuncAttributeMaxDynamicSharedMemorySize, SBUF_SMEM);

    const dim3 thr(256);

    // 0) split inputs
    conv_split  <<<(NS * DIMM + 255) / 256, thr>>>(x, xh, xl, NS * DIMM);
    conv_split_T<<<dim3(LDQ / 32, DIMM / 32), dim3(32, 8)>>>(Wqkv, wqh, wql, DIMM, LDQ);

    // 1) qkv projection on tensor cores
    qkv_mma<<<dim3(LDQ / 128, NS / 128), thr, DBUF_SMEM>>>(xh, xl, wqh, wql, qkv, qh, ql);

    // 2) per-head K=64 GEMMs on tensor cores
    const dim3 gHead(NS / 128, NS / 128, NH);
    head_mma<1><<<gHead, thr, SBUF_SMEM>>>(qh, ql, 3 * 1024, 2 * 1024, t1h, t1l, nullptr);
    head_mma<2><<<gHead, thr, SBUF_SMEM>>>(qh, ql, 0 * 1024, 1 * 1024, lkh, lkl, nullptr);
    head_mma<3><<<gHead, thr, SBUF_SMEM>>>(qh, ql, 3 * 1024, 4 * 1024, nullptr, nullptr, sc);

    // 3) Su on tensor cores, fused scores = Sc - silu(Su)
    su_fuse_mma<<<gHead, thr, DBUF_SMEM>>>(t1h, t1l, lkh, lkl, sc);

    // 4) causal softmax
    row_softmax<<<dim3(NS, NH), thr>>>(sc);

    // 5) ctx = attn @ vc (FFMA)
    av_gemm<<<dim3(NS / 128, NH), thr>>>(sc, qkv, ctx);

    // 6) out = ctx @ W_out (FFMA)
    gemm_nn<<<dim3(DIMM / 128, NS / 128), thr>>>(ctx, Wout, out, DIMM, DIMM, DIMM, DIMM);
}

// round 6
// speedup vs baseline: 1.6938x; 1.1034x over previous
#include <cuda_runtime.h>
#include <cuda_bf16.h>
#include <math.h>
#include <stdint.h>

#define NS   2048
#define NH   16
#define DH   64
#define DIMM 1024
#define LDQ  6144

__device__ __constant__ float SCALE = 0.125f;

// ---- scratch ----
__device__ float g_qkv[(size_t)NS * LDQ];                 // fp32 qkv
__device__ __nv_bfloat16 g_qh [(size_t)NS * LDQ];
__device__ __nv_bfloat16 g_ql [(size_t)NS * LDQ];
__device__ __nv_bfloat16 g_xh [(size_t)NS * DIMM];
__device__ __nv_bfloat16 g_xl [(size_t)NS * DIMM];
__device__ __nv_bfloat16 g_wqh[(size_t)LDQ * DIMM];
__device__ __nv_bfloat16 g_wql[(size_t)LDQ * DIMM];
__device__ __nv_bfloat16 g_t1h[(size_t)NH * NS * NS];     // term1 hi -> attn hi
__device__ __nv_bfloat16 g_t1l[(size_t)NH * NS * NS];     // term1 lo -> attn lo
__device__ __nv_bfloat16 g_lkh[(size_t)NH * NS * NS];
__device__ __nv_bfloat16 g_lkl[(size_t)NH * NS * NS];
__device__ float g_sc [(size_t)NH * NS * NS];
__device__ __nv_bfloat16 g_vth[(size_t)NH * DH * NS];     // vc^T hi [h][d][j]
__device__ __nv_bfloat16 g_vtl[(size_t)NH * DH * NS];
__device__ __nv_bfloat16 g_cth[(size_t)NS * DIMM];        // ctx hi
__device__ __nv_bfloat16 g_ctl[(size_t)NS * DIMM];        // ctx lo
__device__ __nv_bfloat16 g_woh[(size_t)DIMM * DIMM];      // Wout^T hi
__device__ __nv_bfloat16 g_wol[(size_t)DIMM * DIMM];

// ============================================================
// helpers
// ============================================================
__device__ __forceinline__ uint32_t smem_u32(const void* p) {
    uint32_t a;
    asm("{ .reg .u64 t; cvta.to.shared.u64 t, %1; cvt.u32.u64 %0, t; }" : "=r"(a) : "l"(p));
    return a;
}

#define CPASYNC16(s, g) \
    asm volatile("cp.async.cg.shared.global [%0], [%1], 16;" :: "r"(s), "l"(g) : "memory")
#define CP_COMMIT() asm volatile("cp.async.commit_group;" ::: "memory")
#define CP_WAIT0()  asm volatile("cp.async.wait_group 0;" ::: "memory")
#define CP_WAIT1()  asm volatile("cp.async.wait_group 1;" ::: "memory")

#define LDMX4(r, addr) \
    asm volatile("ldmatrix.sync.aligned.m8n8.x4.shared.b16 {%0,%1,%2,%3}, [%4];" \
        : "=r"((r)[0]), "=r"((r)[1]), "=r"((r)[2]), "=r"((r)[3]) : "r"(addr))

#define MMA16816(d, a, b0, b1) \
    asm volatile("mma.sync.aligned.m16n8k16.row.col.f32.bf16.bf16.f32 " \
        "{%0,%1,%2,%3}, {%4,%5,%6,%7}, {%8,%9}, {%0,%1,%2,%3};" \
        : "+f"((d)[0]), "+f"((d)[1]), "+f"((d)[2]), "+f"((d)[3]) \
        : "r"((a)[0]), "r"((a)[1]), "r"((a)[2]), "r"((a)[3]), "r"(b0), "r"(b1))

__device__ __forceinline__ uint32_t pack_bf2(float a, float b) {
    __nv_bfloat162 t = __floats2bfloat162_rn(a, b);
    return *(uint32_t*)&t;
}
__device__ __forceinline__ void split1(float v, __nv_bfloat16& h, float& r) {
    h = __float2bfloat16_rn(v);
    r = v - __bfloat162float(h);
}

#define PADB   144
#define TILEB  (128 * PADB)
#define BUFB   (4 * TILEB)
#define DBUF_SMEM (2 * BUFB)       // 147456
#define SBUF_SMEM BUFB             // 73728
#define AV_BUFB   (384 * PADB)     // Ah,Al(128 rows) + Bh,Bl(64 rows)
#define AV_SMEM   (2 * AV_BUFB)    // 110592

// ============================================================
// conversion kernels
// ============================================================
__global__ void conv_split(const float* __restrict__ src,
                           __nv_bfloat16* __restrict__ hi, __nv_bfloat16* __restrict__ lo,
                           int n) {
    int i = blockIdx.x * 256 + threadIdx.x;
    if (i >= n) return;
    float v = src[i];
    __nv_bfloat16 h; float r;
    split1(v, h, r);
    hi[i] = h;
    lo[i] = __float2bfloat16_rn(r);
}

// dst[C x R] = src[R x C]^T, split bf16
__global__ void conv_split_T(const float* __restrict__ src,
                             __nv_bfloat16* __restrict__ hi, __nv_bfloat16* __restrict__ lo,
                             int R, int C) {
    __shared__ float tile[32][33];
    const int bx = blockIdx.x * 32, by = blockIdx.y * 32;
    const int tx = threadIdx.x, ty = threadIdx.y;
#pragma unroll
    for (int i = 0; i < 32; i += 8)
        tile[ty + i][tx] = src[(size_t)(by + ty + i) * C + bx + tx];
    __syncthreads();
#pragma unroll
    for (int i = 0; i < 32; i += 8) {
        float v = tile[tx][ty + i];
        __nv_bfloat16 h; float r;
        split1(v, h, r);
        size_t o = (size_t)(bx + ty + i) * R + by + tx;
        hi[o] = h;
        lo[o] = __float2bfloat16_rn(r);
    }
}

// vt[h][d][j] = qkv[j][5*1024 + h*64 + d], split bf16
__global__ void conv_vT(const float* __restrict__ qkv,
                        __nv_bfloat16* __restrict__ hi, __nv_bfloat16* __restrict__ lo) {
    __shared__ float tile[32][33];
    const int h = blockIdx.z;
    const int bx = blockIdx.x * 32;   // j base
    const int by = blockIdx.y * 32;   // d base
    const int tx = threadIdx.x, ty = threadIdx.y;
#pragma unroll
    for (int i = 0; i < 32; i += 8)
        tile[ty + i][tx] = qkv[(size_t)(bx + ty + i) * LDQ + 5 * 1024 + h * DH + by + tx];
    __syncthreads();
#pragma unroll
    for (int i = 0; i < 32; i += 8) {
        float v = tile[tx][ty + i];
        __nv_bfloat16 hh; float r;
        split1(v, hh, r);
        size_t o = (size_t)(h * DH + by + ty + i) * NS + bx + tx;
        hi[o] = hh;
        lo[o] = __float2bfloat16_rn(r);
    }
}

// ============================================================
// qkv = x @ Wqkv via split-bf16 mma
// ============================================================
__global__ void __launch_bounds__(256) qkv_mma(
    const __nv_bfloat16* __restrict__ XH, const __nv_bfloat16* __restrict__ XL,
    const __nv_bfloat16* __restrict__ WH, const __nv_bfloat16* __restrict__ WL,
    float* __restrict__ QKV, __nv_bfloat16* __restrict__ QH, __nv_bfloat16* __restrict__ QL)
{
    const int bm = blockIdx.y, bn = blockIdx.x;
    extern __shared__ char sm[];
    const uint32_t smb = smem_u32(sm);
    const int t = threadIdx.x;
    const int wid = t >> 5, lane = t & 31;
    const int m0 = (wid & 1) * 64;
    const int n0 = (wid >> 1) * 32;

    const int grp  = t >> 6;
    const int gg   = t & 63;
    const int col  = gg & 7;
    const int row0 = gg >> 3;
    const __nv_bfloat16* base;
    if (grp == 0)      base = XH + (size_t)(bm * 128) * DIMM;
    else if (grp == 1) base = XL + (size_t)(bm * 128) * DIMM;
    else if (grp == 2) base = WH + (size_t)(bn * 128) * DIMM;
    else               base = WL + (size_t)(bn * 128) * DIMM;
    const __nv_bfloat16* gsrc = base + (size_t)row0 * DIMM + col * 8;
    const uint32_t sdst = smb + grp * TILEB + row0 * PADB + col * 16;

#define QKV_ISSUE(c)                                                       \
    do {                                                                   \
        const __nv_bfloat16* gp = gsrc + (size_t)(c) * 64;                 \
        const uint32_t sb = sdst + ((c) & 1) * BUFB;                       \
        _Pragma("unroll")                                                  \
        for (int kq = 0; kq < 16; kq++)                                    \
            CPASYNC16(sb + kq * 8 * PADB, gp + (size_t)(kq * 8) * DIMM);   \
        CP_COMMIT();                                                       \
    } while (0)

    QKV_ISSUE(0);

    float acc[4][4][4] = {};
    const int lrow = lane & 15;
    const uint32_t lkoff = (uint32_t)((lane >> 4) * 16);

    for (int c = 0; c < 16; c++) {
        if (c + 1 < 16) { QKV_ISSUE(c + 1); CP_WAIT1(); }
        else            { CP_WAIT0(); }
        __syncthreads();

        const uint32_t bse = smb + (c & 1) * BUFB;
        const uint32_t aH = bse, aL = bse + TILEB, bH = bse + 2 * TILEB, bL = bse + 3 * TILEB;

#pragma unroll
        for (int kk = 0; kk < 4; kk++) {
            const uint32_t ko = kk * 32 + lkoff;
            uint32_t ah[4][4], al[4][4];
            const uint32_t aoff = (uint32_t)((m0 + lrow) * PADB) + ko;
#pragma unroll
            for (int tm = 0; tm < 4; tm++) {
                LDMX4(ah[tm], aH + aoff + tm * 16 * PADB);
                LDMX4(al[tm], aL + aoff + tm * 16 * PADB);
            }
            uint32_t bh[2][4], bl[2][4];
            const uint32_t boff = (uint32_t)((n0 + lrow) * PADB) + ko;
#pragma unroll
            for (int tp = 0; tp < 2; tp++) {
                LDMX4(bh[tp], bH + boff + tp * 16 * PADB);
                LDMX4(bl[tp], bL + boff + tp * 16 * PADB);
            }
#pragma unroll
            for (int tm = 0; tm < 4; tm++) {
#pragma unroll
                for (int tn = 0; tn < 4; tn++) {
                    const int tp = tn >> 1, sel = tn & 1;
                    MMA16816(acc[tm][tn], ah[tm], bh[tp][sel], bh[tp][sel + 2]);
                    MMA16816(acc[tm][tn], ah[tm], bl[tp][sel], bl[tp][sel + 2]);
                    MMA16816(acc[tm][tn], al[tm], bh[tp][sel], bh[tp][sel + 2]);
                }
            }
        }
        __syncthreads();
    }

    const int g  = lane >> 2;
    const int tg = lane & 3;
#pragma unroll
    for (int tm = 0; tm < 4; tm++) {
#pragma unroll
        for (int tn = 0; tn < 4; tn++) {
            const int i0 = bm * 128 + m0 + tm * 16 + g;
            const int j0 = bn * 128 + n0 + tn * 8 + tg * 2;
            float v0 = acc[tm][tn][0], v1 = acc[tm][tn][1];
            float v2 = acc[tm][tn][2], v3 = acc[tm][tn][3];
            size_t o0 = (size_t)i0 * LDQ + j0;
            size_t o1 = o0 + (size_t)8 * LDQ;
            *(float2*)(QKV + o0) = make_float2(v0, v1);
            *(float2*)(QKV + o1) = make_float2(v2, v3);
            __nv_bfloat16 h; float r0, r1, r2, r3;
            split1(v0, h, r0); split1(v1, h, r1); split1(v2, h, r2); split1(v3, h, r3);
            *(uint32_t*)(QH + o0) = pack_bf2(v0, v1);
            *(uint32_t*)(QH + o1) = pack_bf2(v2, v3);
            *(uint32_t*)(QL + o0) = pack_bf2(r0, r1);
            *(uint32_t*)(QL + o1) = pack_bf2(r2, r3);
        }
    }
}

// ============================================================
// Per-head NT GEMM K=64 via mma. MODE1 term1, MODE2 lookahead, MODE3 Sc.
// ============================================================
template <int MODE>
__global__ void __launch_bounds__(256) head_mma(
    const __nv_bfloat16* __restrict__ QH, const __nv_bfloat16* __restrict__ QL,
    int aoff, int boff,
    __nv_bfloat16* __restrict__ CH, __nv_bfloat16* __restrict__ CL,
    float* __restrict__ CF)
{
    const int h  = blockIdx.z;
    const int bi = blockIdx.y, bj = blockIdx.x;
    if (MODE != 2 && bj > bi) return;
    if (MODE == 2 && bj < bi) return;

    extern __shared__ char sm[];
    const uint32_t smb = smem_u32(sm);
    const int t = threadIdx.x;
    const int wid = t >> 5, lane = t & 31;
    const int m0 = (wid & 1) * 64;
    const int n0 = (wid >> 1) * 32;

    const int grp  = t >> 6;
    const int gg   = t & 63;
    const int col  = gg & 7;
    const int row0 = gg >> 3;
    const __nv_bfloat16* base;
    if (grp == 0)      base = QH + (size_t)(bi * 128) * LDQ + aoff + h * DH;
    else if (grp == 1) base = QL + (size_t)(bi * 128) * LDQ + aoff + h * DH;
    else if (grp == 2) base = QH + (size_t)(bj * 128) * LDQ + boff + h * DH;
    else               base = QL + (size_t)(bj * 128) * LDQ + boff + h * DH;
    const __nv_bfloat16* gsrc = base + (size_t)row0 * LDQ + col * 8;
    const uint32_t sdst = smb + grp * TILEB + row0 * PADB + col * 16;

#pragma unroll
    for (int kq = 0; kq < 16; kq++)
        CPASYNC16(sdst + kq * 8 * PADB, gsrc + (size_t)(kq * 8) * LDQ);
    CP_COMMIT();
    CP_WAIT0();
    __syncthreads();

    float acc[4][4][4] = {};
    const int lrow = lane & 15;
    const uint32_t lkoff = (uint32_t)((lane >> 4) * 16);
    const uint32_t aH = smb, aL = smb + TILEB, bH = smb + 2 * TILEB, bL = smb + 3 * TILEB;

#pragma unroll
    for (int kk = 0; kk < 4; kk++) {
        const uint32_t ko = kk * 32 + lkoff;
        uint32_t ah[4][4], al[4][4];
        const uint32_t aoff2 = (uint32_t)((m0 + lrow) * PADB) + ko;
#pragma unroll
        for (int tm = 0; tm < 4; tm++) {
            LDMX4(ah[tm], aH + aoff2 + tm * 16 * PADB);
            LDMX4(al[tm], aL + aoff2 + tm * 16 * PADB);
        }
        uint32_t bh[2][4], bl[2][4];
        const uint32_t boff2 = (uint32_t)((n0 + lrow) * PADB) + ko;
#pragma unroll
        for (int tp = 0; tp < 2; tp++) {
            LDMX4(bh[tp], bH + boff2 + tp * 16 * PADB);
            LDMX4(bl[tp], bL + boff2 + tp * 16 * PADB);
        }
#pragma unroll
        for (int tm = 0; tm < 4; tm++) {
#pragma unroll
            for (int tn = 0; tn < 4; tn++) {
                const int tp = tn >> 1, sel = tn & 1;
                MMA16816(acc[tm][tn], ah[tm], bh[tp][sel], bh[tp][sel + 2]);
                MMA16816(acc[tm][tn], ah[tm], bl[tp][sel], bl[tp][sel + 2]);
                MMA16816(acc[tm][tn], al[tm], bh[tp][sel], bh[tp][sel + 2]);
            }
        }
    }

    const size_t hb = (size_t)h * NS * NS;
    const int g  = lane >> 2;
    const int tg = lane & 3;
#pragma unroll
    for (int tm = 0; tm < 4; tm++) {
#pragma unroll
        for (int tn = 0; tn < 4; tn++) {
            const int i0 = bi * 128 + m0 + tm * 16 + g;
            const int j0 = bj * 128 + n0 + tn * 8 + tg * 2;
            float v[4];
            v[0] = acc[tm][tn][0] * SCALE; v[1] = acc[tm][tn][1] * SCALE;
            v[2] = acc[tm][tn][2] * SCALE; v[3] = acc[tm][tn][3] * SCALE;
            const int ii[4] = {i0, i0, i0 + 8, i0 + 8};
            const int jj[4] = {j0, j0 + 1, j0, j0 + 1};
#pragma unroll
            for (int q = 0; q < 4; q++) {
                if (MODE == 1) v[q] = (jj[q] <= ii[q]) ? v[q] : 0.0f;
                if (MODE == 2) v[q] = (jj[q] >  ii[q]) ? (1.0f / (1.0f + expf(-v[q]))) : 0.0f;
            }
            size_t o0 = hb + (size_t)i0 * NS + j0;
            size_t o1 = o0 + (size_t)8 * NS;
            if (MODE == 3) {
                *(float2*)(CF + o0) = make_float2(v[0], v[1]);
                *(float2*)(CF + o1) = make_float2(v[2], v[3]);
            } else {
                __nv_bfloat16 hh; float r[4];
                split1(v[0], hh, r[0]); split1(v[1], hh, r[1]);
                split1(v[2], hh, r[2]); split1(v[3], hh, r[3]);
                *(uint32_t*)(CH + o0) = pack_bf2(v[0], v[1]);
                *(uint32_t*)(CH + o1) = pack_bf2(v[2], v[3]);
                *(uint32_t*)(CL + o0) = pack_bf2(r[0], r[1]);
                *(uint32_t*)(CL + o1) = pack_bf2(r[2], r[3]);
            }
        }
    }
}

// ============================================================
// Su via split-bf16 mma, fused SC -= silu(Su).
// ============================================================
__global__ void __launch_bounds__(256) su_fuse_mma(
    const __nv_bfloat16* __restrict__ T1H, const __nv_bfloat16* __restrict__ T1L,
    const __nv_bfloat16* __restrict__ LKH, const __nv_bfloat16* __restrict__ LKL,
    float* __restrict__ SC)
{
    const int h = blockIdx.z, bi = blockIdx.y, bk = blockIdx.x;
    if (bk > bi) return;

    extern __shared__ char sm[];
    const uint32_t smb = smem_u32(sm);
    const int t = threadIdx.x;
    const int wid = t >> 5, lane = t & 31;
    const int m0 = (wid & 1) * 64;
    const int n0 = (wid >> 1) * 32;

    const size_t hb = (size_t)h * NS * NS;
    const __nv_bfloat16* srcs[4] = {
        T1H + hb + (size_t)(bi * 128) * NS,
        T1L + hb + (size_t)(bi * 128) * NS,
        LKH + hb + (size_t)(bk * 128) * NS,
        LKL + hb + (size_t)(bk * 128) * NS
    };

    const int grp  = t >> 6;
    const int gg   = t & 63;
    const int col  = gg & 7;
    const int row0 = gg >> 3;
    const __nv_bfloat16* gsrc = srcs[grp] + (size_t)row0 * NS + col * 8;
    const uint32_t sdst = smb + grp * TILEB + row0 * PADB + col * 16;

    const int nCh = 2 * (bi - bk + 1);

#define SU_ISSUE(c)                                                        \
    do {                                                                   \
        const __nv_bfloat16* gp = gsrc + (size_t)bk * 128 + (size_t)(c) * 64; \
        const uint32_t sb = sdst + ((c) & 1) * BUFB;                       \
        _Pragma("unroll")                                                  \
        for (int kq = 0; kq < 16; kq++)                                    \
            CPASYNC16(sb + kq * 8 * PADB, gp + (size_t)(kq * 8) * NS);     \
        CP_COMMIT();                                                       \
    } while (0)

    SU_ISSUE(0);

    float acc[4][4][4] = {};
    const int lrow = lane & 15;
    const uint32_t lkoff = (uint32_t)((lane >> 4) * 16);

    for (int c = 0; c < nCh; c++) {
        if (c + 1 < nCh) { SU_ISSUE(c + 1); CP_WAIT1(); }
        else             { CP_WAIT0(); }
        __syncthreads();

        const uint32_t bse = smb + (c & 1) * BUFB;
        const uint32_t aH = bse, aL = bse + TILEB, bH = bse + 2 * TILEB, bL = bse + 3 * TILEB;

#pragma unroll
        for (int kk = 0; kk < 4; kk++) {
            const uint32_t ko = kk * 32 + lkoff;
            uint32_t ah[4][4], al[4][4];
            const uint32_t aoff = (uint32_t)((m0 + lrow) * PADB) + ko;
#pragma unroll
            for (int tm = 0; tm < 4; tm++) {
                LDMX4(ah[tm], aH + aoff + tm * 16 * PADB);
                LDMX4(al[tm], aL + aoff + tm * 16 * PADB);
            }
            uint32_t bh[2][4], bl[2][4];
            const uint32_t boff = (uint32_t)((n0 + lrow) * PADB) + ko;
#pragma unroll
            for (int tp = 0; tp < 2; tp++) {
                LDMX4(bh[tp], bH + boff + tp * 16 * PADB);
                LDMX4(bl[tp], bL + boff + tp * 16 * PADB);
            }
#pragma unroll
            for (int tm = 0; tm < 4; tm++) {
#pragma unroll
                for (int tn = 0; tn < 4; tn++) {
                    const int tp = tn >> 1, sel = tn & 1;
                    MMA16816(acc[tm][tn], ah[tm], bh[tp][sel], bh[tp][sel + 2]);
                    MMA16816(acc[tm][tn], ah[tm], bl[tp][sel], bl[tp][sel + 2]);
                    MMA16816(acc[tm][tn], al[tm], bh[tp][sel], bh[tp][sel + 2]);
                }
            }
        }
        __syncthreads();
    }

    const int g  = lane >> 2;
    const int tg = lane & 3;
#pragma unroll
    for (int tm = 0; tm < 4; tm++) {
#pragma unroll
        for (int tn = 0; tn < 4; tn++) {
            const int i0 = bi * 128 + m0 + tm * 16 + g;
            const int j0 = bk * 128 + n0 + tn * 8 + tg * 2;
            float* p0 = SC + hb + (size_t)i0 * NS + j0;
            float* p1 = p0 + (size_t)8 * NS;
            float2 c0 = *(float2*)p0;
            float2 c1 = *(float2*)p1;
            float s0 = acc[tm][tn][0], s1 = acc[tm][tn][1];
            float s2 = acc[tm][tn][2], s3 = acc[tm][tn][3];
            c0.x -= s0 / (1.0f + expf(-s0));
            c0.y -= s1 / (1.0f + expf(-s1));
            c1.x -= s2 / (1.0f + expf(-s2));
            c1.y -= s3 / (1.0f + expf(-s3));
            *(float2*)p0 = c0;
            *(float2*)p1 = c1;
        }
    }
}

// ============================================================
// Row softmax (causal). Reads fp32 scores, writes attn as split bf16
// into AH/AL, zero-padded to the next 128 boundary.
// ============================================================
__global__ void row_softmax_bf(const float* __restrict__ SC,
                               __nv_bfloat16* __restrict__ AH,
                               __nv_bfloat16* __restrict__ AL) {
    const int h = blockIdx.y, i = blockIdx.x;
    const float* row = SC + (size_t)h * NS * NS + (size_t)i * NS;
    __nv_bfloat16* rh = AH + (size_t)h * NS * NS + (size_t)i * NS;
    __nv_bfloat16* rl = AL + (size_t)h * NS * NS + (size_t)i * NS;
    const int t = threadIdx.x;
    const int len = i + 1;

    __shared__ float red[256];

    float lmax = -1e30f;
    for (int j = t; j < len; j += 256) lmax = fmaxf(lmax, row[j]);
    red[t] = lmax; __syncthreads();
    for (int s = 128; s > 0; s >>= 1) { if (t < s) red[t] = fmaxf(red[t], red[t + s]); __syncthreads(); }
    const float bmax = red[0];
    __syncthreads();

    float ev[8];
    int cnt = 0;
    float lsum = 0.0f;
    for (int j = t; j < len; j += 256) {
        float e = expf(row[j] - bmax);
        ev[cnt++] = e;
        lsum += e;
    }
    red[t] = lsum; __syncthreads();
    for (int s = 128; s > 0; s >>= 1) { if (t < s) red[t] += red[t + s]; __syncthreads(); }
    const float inv = 1.0f / red[0];

    cnt = 0;
    for (int j = t; j < len; j += 256) {
        float p = ev[cnt++] * inv;
        __nv_bfloat16 hh; float r;
        split1(p, hh, r);
        rh[j] = hh;
        rl[j] = __float2bfloat16_rn(r);
    }
    const int padEnd = ((i >> 7) + 1) << 7;
    const __nv_bfloat16 z = __float2bfloat16_rn(0.0f);
    for (int j = len + t; j < padEnd; j += 256) { rh[j] = z; rl[j] = z; }
}

// ============================================================
// AV via split-bf16 mma: ctx = attn @ vc. M=128, N=64(DH), causal K.
// A = attn hi/lo [i][j] k-contig; B = vt hi/lo [d][j] k-contig.
// 8 warps: m0=(wid&3)*32, n0=(wid>>2)*32; warp tile 32x32.
// Writes ctx as split bf16.
// ============================================================
__global__ void __launch_bounds__(256) av_mma(
    const __nv_bfloat16* __restrict__ ATH, const __nv_bfloat16* __restrict__ ATL,
    const __nv_bfloat16* __restrict__ VTH, const __nv_bfloat16* __restrict__ VTL,
    __nv_bfloat16* __restrict__ CTH, __nv_bfloat16* __restrict__ CTL)
{
    const int h = blockIdx.y, bi = blockIdx.x;
    extern __shared__ char sm[];
    const uint32_t smb = smem_u32(sm);
    const int t = threadIdx.x;
    const int wid = t >> 5, lane = t & 31;
    const int m0 = (wid & 3) * 32;
    const int n0 = (wid >> 2) * 32;

    const size_t hb = (size_t)h * NS * NS;
    const __nv_bfloat16* gAh = ATH + hb + (size_t)(bi * 128) * NS;
    const __nv_bfloat16* gAl = ATL + hb + (size_t)(bi * 128) * NS;
    const __nv_bfloat16* gBh = VTH + (size_t)(h * DH) * NS;
    const __nv_bfloat16* gBl = VTL + (size_t)(h * DH) * NS;

    // loader mapping
    const int arow = t >> 1;               // 0..127
    const int acolB = (t & 1) * 64;        // byte offset within 128B row
    const int brow = t >> 2;               // 0..63
    const int bcolB = (t & 3) * 32;        // byte offset

    const uint32_t sA = smb + arow * PADB + acolB;
    const uint32_t sB = smb + brow * PADB + bcolB;

#define AV_ISSUE(c)                                                             \
    do {                                                                        \
        const size_t j0 = (size_t)(c) * 64;                                     \
        const uint32_t bb = ((c) & 1) * AV_BUFB;                                \
        const __nv_bfloat16* pah = gAh + (size_t)arow * NS + j0 + acolB / 2;    \
        const __nv_bfloat16* pal = gAl + (size_t)arow * NS + j0 + acolB / 2;    \
        _Pragma("unroll")                                                       \
        for (int q = 0; q < 4; q++) {                                           \
            CPASYNC16(sA + bb + q * 16,               pah + q * 8);             \
            CPASYNC16(sA + bb + 128 * PADB + q * 16,  pal + q * 8);             \
        }                                                                       \
        const __nv_bfloat16* pbh = gBh + (size_t)brow * NS + j0 + bcolB / 2;    \
        const __nv_bfloat16* pbl = gBl + (size_t)brow * NS + j0 + bcolB / 2;    \
        _Pragma("unroll")                                                       \
        for (int q = 0; q < 2; q++) {                                           \
            CPASYNC16(sB + bb + 256 * PADB + q * 16,            pbh + q * 8);   \
            CPASYNC16(sB + bb + 256 * PADB + 64 * PADB + q * 16, pbl + q * 8);  \
        }                                                                       \
        CP_COMMIT();                                                            \
    } while (0)

    const int nCh = 2 * (bi + 1);
    AV_ISSUE(0);

    float acc[2][4][4] = {};
    const int lrow = lane & 15;
    const uint32_t lkoff = (uint32_t)((lane >> 4) * 16);

    for (int c = 0; c < nCh; c++) {
        if (c + 1 < nCh) { AV_ISSUE(c + 1); CP_WAIT1(); }
        else             { CP_WAIT0(); }
        __syncthreads();

        const uint32_t bse = smb + (c & 1) * AV_BUFB;
        const uint32_t aH = bse;
        const uint32_t aL = bse + 128 * PADB;
        const uint32_t bH = bse + 256 * PADB;
        const uint32_t bL = bse + 320 * PADB;

#pragma unroll
        for (int kk = 0; kk < 4; kk++) {
            const uint32_t ko = kk * 32 + lkoff;
            uint32_t ah[2][4], al[2][4];
            const uint32_t aoff = (uint32_t)((m0 + lrow) * PADB) + ko;
#pragma unroll
            for (int tm = 0; tm < 2; tm++) {
                LDMX4(ah[tm], aH + aoff + tm * 16 * PADB);
                LDMX4(al[tm], aL + aoff + tm * 16 * PADB);
            }
            uint32_t bh[2][4], bl[2][4];
            const uint32_t boff = (uint32_t)((n0 + lrow) * PADB) + ko;
#pragma unroll
            for (int tp = 0; tp < 2; tp++) {
                LDMX4(bh[tp], bH + boff + tp * 16 * PADB);
                LDMX4(bl[tp], bL + boff + tp * 16 * PADB);
            }
#pragma unroll
            for (int tm = 0; tm < 2; tm++) {
#pragma unroll
                for (int tn = 0; tn < 4; tn++) {
                    const int tp = tn >> 1, sel = tn & 1;
                    MMA16816(acc[tm][tn], ah[tm], bh[tp][sel], bh[tp][sel + 2]);
                    MMA16816(acc[tm][tn], ah[tm], bl[tp][sel], bl[tp][sel + 2]);
                    MMA16816(acc[tm][tn], al[tm], bh[tp][sel], bh[tp][sel + 2]);
                }
            }
        }
        __syncthreads();
    }

    const int g  = lane >> 2;
    const int tg = lane & 3;
#pragma unroll
    for (int tm = 0; tm < 2; tm++) {
#pragma unroll
        for (int tn = 0; tn < 4; tn++) {
            const int i0 = bi * 128 + m0 + tm * 16 + g;
            const int d0 = n0 + tn * 8 + tg * 2;
            size_t o0 = (size_t)i0 * DIMM + h * DH + d0;
            size_t o1 = o0 + (size_t)8 * DIMM;
            float v0 = acc[tm][tn][0], v1 = acc[tm][tn][1];
            float v2 = acc[tm][tn][2], v3 = acc[tm][tn][3];
            __nv_bfloat16 hh; float r0, r1, r2, r3;
            split1(v0, hh, r0); split1(v1, hh, r1); split1(v2, hh, r2); split1(v3, hh, r3);
            *(uint32_t*)(CTH + o0) = pack_bf2(v0, v1);
            *(uint32_t*)(CTH + o1) = pack_bf2(v2, v3);
            *(uint32_t*)(CTL + o0) = pack_bf2(r0, r1);
            *(uint32_t*)(CTL + o1) = pack_bf2(r2, r3);
        }
    }
}

// ============================================================
// out = ctx @ Wout via split-bf16 mma. M=2048, N=1024, K=1024.
// A = ctx hi/lo k-contig, B = Wout^T hi/lo k-contig. fp32 out.
// ============================================================
__global__ void __launch_bounds__(256) out_mma(
    const __nv_bfloat16* __restrict__ AH0, const __nv_bfloat16* __restrict__ AL0,
    const __nv_bfloat16* __restrict__ BH0, const __nv_bfloat16* __restrict__ BL0,
    float* __restrict__ C)
{
    const int bm = blockIdx.y, bn = blockIdx.x;
    extern __shared__ char sm[];
    const uint32_t smb = smem_u32(sm);
    const int t = threadIdx.x;
    const int wid = t >> 5, lane = t & 31;
    const int m0 = (wid & 1) * 64;
    const int n0 = (wid >> 1) * 32;

    const int grp  = t >> 6;
    const int gg   = t & 63;
    const int col  = gg & 7;
    const int row0 = gg >> 3;
    const __nv_bfloat16* base;
    if (grp == 0)      base = AH0 + (size_t)(bm * 128) * DIMM;
    else if (grp == 1) base = AL0 + (size_t)(bm * 128) * DIMM;
    else if (grp == 2) base = BH0 + (size_t)(bn * 128) * DIMM;
    else               base = BL0 + (size_t)(bn * 128) * DIMM;
    const __nv_bfloat16* gsrc = base + (size_t)row0 * DIMM + col * 8;
    const uint32_t sdst = smb + grp * TILEB + row0 * PADB + col * 16;

#define OUT_ISSUE(c)                                                       \
    do {                                                                   \
        const __nv_bfloat16* gp = gsrc + (size_t)(c) * 64;                 \
        const uint32_t sb = sdst + ((c) & 1) * BUFB;                       \
        _Pragma("unroll")                                                  \
        for (int kq = 0; kq < 16; kq++)                                    \
            CPASYNC16(sb + kq * 8 * PADB, gp + (size_t)(kq * 8) * DIMM);   \
        CP_COMMIT();                                                       \
    } while (0)

    OUT_ISSUE(0);

    float acc[4][4][4] = {};
    const int lrow = lane & 15;
    const uint32_t lkoff = (uint32_t)((lane >> 4) * 16);

    for (int c = 0; c < 16; c++) {
        if (c + 1 < 16) { OUT_ISSUE(c + 1); CP_WAIT1(); }
        else            { CP_WAIT0(); }
        __syncthreads();

        const uint32_t bse = smb + (c & 1) * BUFB;
        const uint32_t aH = bse, aL = bse + TILEB, bH = bse + 2 * TILEB, bL = bse + 3 * TILEB;

#pragma unroll
        for (int kk = 0; kk < 4; kk++) {
            const uint32_t ko = kk * 32 + lkoff;
            uint32_t ah[4][4], al[4][4];
            const uint32_t aoff = (uint32_t)((m0 + lrow) * PADB) + ko;
#pragma unroll
            for (int tm = 0; tm < 4; tm++) {
                LDMX4(ah[tm], aH + aoff + tm * 16 * PADB);
                LDMX4(al[tm], aL + aoff + tm * 16 * PADB);
            }
            uint32_t bh[2][4], bl[2][4];
            const uint32_t boff = (uint32_t)((n0 + lrow) * PADB) + ko;
#pragma unroll
            for (int tp = 0; tp < 2; tp++) {
                LDMX4(bh[tp], bH + boff + tp * 16 * PADB);
                LDMX4(bl[tp], bL + boff + tp * 16 * PADB);
            }
#pragma unroll
            for (int tm = 0; tm < 4; tm++) {
#pragma unroll
                for (int tn = 0; tn < 4; tn++) {
                    const int tp = tn >> 1, sel = tn & 1;
                    MMA16816(acc[tm][tn], ah[tm], bh[tp][sel], bh[tp][sel + 2]);
                    MMA16816(acc[tm][tn], ah[tm], bl[tp][sel], bl[tp][sel + 2]);
                    MMA16816(acc[tm][tn], al[tm], bh[tp][sel], bh[tp][sel + 2]);
                }
            }
        }
        __syncthreads();
    }

    const int g  = lane >> 2;
    const int tg = lane & 3;
#pragma unroll
    for (int tm = 0; tm < 4; tm++) {
#pragma unroll
        for (int tn = 0; tn < 4; tn++) {
            const int i0 = bm * 128 + m0 + tm * 16 + g;
            const int j0 = bn * 128 + n0 + tn * 8 + tg * 2;
            size_t o0 = (size_t)i0 * DIMM + j0;
            size_t o1 = o0 + (size_t)8 * DIMM;
            *(float2*)(C + o0) = make_float2(acc[tm][tn][0], acc[tm][tn][1]);
            *(float2*)(C + o1) = make_float2(acc[tm][tn][2], acc[tm][tn][3]);
        }
    }
}

// ============================================================
extern "C" void kernel_launch(void* const* d_in, const int* in_sizes, int n_in,
                              void* d_out, int out_size) {
    const float* x    = (const float*)d_in[0];
    const float* Wqkv = (const float*)d_in[1];
    const float* Wout = (const float*)d_in[2];
    float* out = (float*)d_out;

    float *qkv, *sc;
    __nv_bfloat16 *qh, *ql, *xh, *xl, *wqh, *wql, *t1h, *t1l, *lkh, *lkl;
    __nv_bfloat16 *vth, *vtl, *cth, *ctl, *woh, *wol;
    cudaGetSymbolAddress((void**)&qkv, g_qkv);
    cudaGetSymbolAddress((void**)&qh,  g_qh);
    cudaGetSymbolAddress((void**)&ql,  g_ql);
    cudaGetSymbolAddress((void**)&xh,  g_xh);
    cudaGetSymbolAddress((void**)&xl,  g_xl);
    cudaGetSymbolAddress((void**)&wqh, g_wqh);
    cudaGetSymbolAddress((void**)&wql, g_wql);
    cudaGetSymbolAddress((void**)&t1h, g_t1h);
    cudaGetSymbolAddress((void**)&t1l, g_t1l);
    cudaGetSymbolAddress((void**)&lkh, g_lkh);
    cudaGetSymbolAddress((void**)&lkl, g_lkl);
    cudaGetSymbolAddress((void**)&sc,  g_sc);
    cudaGetSymbolAddress((void**)&vth, g_vth);
    cudaGetSymbolAddress((void**)&vtl, g_vtl);
    cudaGetSymbolAddress((void**)&cth, g_cth);
    cudaGetSymbolAddress((void**)&ctl, g_ctl);
    cudaGetSymbolAddress((void**)&woh, g_woh);
    cudaGetSymbolAddress((void**)&wol, g_wol);

    cudaFuncSetAttribute(qkv_mma,     cudaFuncAttributeMaxDynamicSharedMemorySize, DBUF_SMEM);
    cudaFuncSetAttribute(su_fuse_mma, cudaFuncAttributeMaxDynamicSharedMemorySize, DBUF_SMEM);
    cudaFuncSetAttribute(out_mma,     cudaFuncAttributeMaxDynamicSharedMemorySize, DBUF_SMEM);
    cudaFuncSetAttribute(av_mma,      cudaFuncAttributeMaxDynamicSharedMemorySize, AV_SMEM);
    cudaFuncSetAttribute(head_mma<1>, cudaFuncAttributeMaxDynamicSharedMemorySize, SBUF_SMEM);
    cudaFuncSetAttribute(head_mma<2>, cudaFuncAttributeMaxDynamicSharedMemorySize, SBUF_SMEM);
    cudaFuncSetAttribute(head_mma<3>, cudaFuncAttributeMaxDynamicSharedMemorySize, SBUF_SMEM);

    const dim3 thr(256);

    // 0) split inputs
    conv_split  <<<(NS * DIMM + 255) / 256, thr>>>(x, xh, xl, NS * DIMM);
    conv_split_T<<<dim3(LDQ / 32, DIMM / 32), dim3(32, 8)>>>(Wqkv, wqh, wql, DIMM, LDQ);
    conv_split_T<<<dim3(DIMM / 32, DIMM / 32), dim3(32, 8)>>>(Wout, woh, wol, DIMM, DIMM);

    // 1) qkv projection (HMMA)
    qkv_mma<<<dim3(LDQ / 128, NS / 128), thr, DBUF_SMEM>>>(xh, xl, wqh, wql, qkv, qh, ql);

    // 1b) vc^T split for the AV GEMM
    conv_vT<<<dim3(NS / 32, DH / 32, NH), dim3(32, 8)>>>(qkv, vth, vtl);

    // 2) per-head K=64 GEMMs (HMMA)
    const dim3 gHead(NS / 128, NS / 128, NH);
    head_mma<1><<<gHead, thr, SBUF_SMEM>>>(qh, ql, 3 * 1024, 2 * 1024, t1h, t1l, nullptr);
    head_mma<2><<<gHead, thr, SBUF_SMEM>>>(qh, ql, 0 * 1024, 1 * 1024, lkh, lkl, nullptr);
    head_mma<3><<<gHead, thr, SBUF_SMEM>>>(qh, ql, 3 * 1024, 4 * 1024, nullptr, nullptr, sc);

    // 3) Su (HMMA), fused scores = Sc - silu(Su)
    su_fuse_mma<<<gHead, thr, DBUF_SMEM>>>(t1h, t1l, lkh, lkl, sc);

    // 4) causal softmax -> attn split bf16 (reuses t1h/t1l)
    row_softmax_bf<<<dim3(NS, NH), thr>>>(sc, t1h, t1l);

    // 5) ctx = attn @ vc (HMMA), ctx written as split bf16
    av_mma<<<dim3(NS / 128, NH), thr, AV_SMEM>>>(t1h, t1l, vth, vtl, cth, ctl);

    // 6) out = ctx @ W_out (HMMA)
    out_mma<<<dim3(DIMM / 128, NS / 128), thr, DBUF_SMEM>>>(cth, ctl, woh, wol, out);
}

// round 7
// speedup vs baseline: 2.0990x; 1.2393x over previous
#include <cuda_runtime.h>
#include <cuda_bf16.h>
#include <math.h>
#include <stdint.h>

#define NS   2048
#define NH   16
#define DH   64
#define DIMM 1024
#define LDQ  6144

__device__ __constant__ float SCALE = 0.125f;

// ---- scratch ----
__device__ float g_qkv[(size_t)NS * LDQ];
__device__ __nv_bfloat16 g_qh [(size_t)NS * LDQ];
__device__ __nv_bfloat16 g_ql [(size_t)NS * LDQ];
__device__ __nv_bfloat16 g_xh [(size_t)NS * DIMM];
__device__ __nv_bfloat16 g_xl [(size_t)NS * DIMM];
__device__ __nv_bfloat16 g_wqh[(size_t)LDQ * DIMM];
__device__ __nv_bfloat16 g_wql[(size_t)LDQ * DIMM];
__device__ __nv_bfloat16 g_t1h[(size_t)NH * NS * NS];
__device__ __nv_bfloat16 g_t1l[(size_t)NH * NS * NS];
__device__ __nv_bfloat16 g_lkh[(size_t)NH * NS * NS];
__device__ __nv_bfloat16 g_lkl[(size_t)NH * NS * NS];
__device__ float g_sc [(size_t)NH * NS * NS];
__device__ __nv_bfloat16 g_vth[(size_t)NH * DH * NS];
__device__ __nv_bfloat16 g_vtl[(size_t)NH * DH * NS];
__device__ __nv_bfloat16 g_cth[(size_t)NS * DIMM];
__device__ __nv_bfloat16 g_ctl[(size_t)NS * DIMM];
__device__ __nv_bfloat16 g_woh[(size_t)DIMM * DIMM];
__device__ __nv_bfloat16 g_wol[(size_t)DIMM * DIMM];

// ============================================================
// helpers
// ============================================================
__device__ __forceinline__ uint32_t smem_u32(const void* p) {
    uint32_t a;
    asm("{ .reg .u64 t; cvta.to.shared.u64 t, %1; cvt.u32.u64 %0, t; }" : "=r"(a) : "l"(p));
    return a;
}

#define CPASYNC16(s, g) \
    asm volatile("cp.async.cg.shared.global [%0], [%1], 16;" :: "r"(s), "l"(g) : "memory")
#define CP_COMMIT() asm volatile("cp.async.commit_group;" ::: "memory")
#define CP_WAIT0()  asm volatile("cp.async.wait_group 0;" ::: "memory")
#define CP_WAIT1()  asm volatile("cp.async.wait_group 1;" ::: "memory")

#define LDMX4(r, addr) \
    asm volatile("ldmatrix.sync.aligned.m8n8.x4.shared.b16 {%0,%1,%2,%3}, [%4];" \
        : "=r"((r)[0]), "=r"((r)[1]), "=r"((r)[2]), "=r"((r)[3]) : "r"(addr))

#define MMA16816(d, a, b0, b1) \
    asm volatile("mma.sync.aligned.m16n8k16.row.col.f32.bf16.bf16.f32 " \
        "{%0,%1,%2,%3}, {%4,%5,%6,%7}, {%8,%9}, {%0,%1,%2,%3};" \
        : "+f"((d)[0]), "+f"((d)[1]), "+f"((d)[2]), "+f"((d)[3]) \
        : "r"((a)[0]), "r"((a)[1]), "r"((a)[2]), "r"((a)[3]), "r"(b0), "r"(b1))

__device__ __forceinline__ uint32_t pack_bf2(float a, float b) {
    __nv_bfloat162 t = __floats2bfloat162_rn(a, b);
    return *(uint32_t*)&t;
}
__device__ __forceinline__ void split1(float v, __nv_bfloat16& h, float& r) {
    h = __float2bfloat16_rn(v);
    r = v - __bfloat162float(h);
}

// 32-wide K chunks: 64B data + 16B pad per row
#define PADB   80
#define TILEB  (128 * PADB)      // 10240
#define BUFB   (4 * TILEB)       // 40960
#define DBUF_SMEM (2 * BUFB)     // 81920 -> 2 CTAs/SM
#define AV_STAGE  (384 * PADB)   // 30720
#define AV_SMEM   (2 * AV_STAGE) // 61440

// ============================================================
// chunk compute: 128x128 tile, warp 64x32, K=32 per chunk
// ============================================================
__device__ __forceinline__ void mma_chunk_128(
    uint32_t aH, uint32_t aL, uint32_t bH, uint32_t bL,
    int m0, int n0, int lrow, uint32_t lkoff, float acc[4][4][4])
{
#pragma unroll
    for (int kk = 0; kk < 2; kk++) {
        const uint32_t ko = kk * 32 + lkoff;
        uint32_t ah[4][4], al[4][4];
        const uint32_t aoff = (uint32_t)((m0 + lrow) * PADB) + ko;
#pragma unroll
        for (int tm = 0; tm < 4; tm++) {
            LDMX4(ah[tm], aH + aoff + tm * 16 * PADB);
            LDMX4(al[tm], aL + aoff + tm * 16 * PADB);
        }
        uint32_t bh[2][4], bl[2][4];
        const uint32_t boff = (uint32_t)((n0 + lrow) * PADB) + ko;
#pragma unroll
        for (int tp = 0; tp < 2; tp++) {
            LDMX4(bh[tp], bH + boff + tp * 16 * PADB);
            LDMX4(bl[tp], bL + boff + tp * 16 * PADB);
        }
#pragma unroll
        for (int tm = 0; tm < 4; tm++) {
#pragma unroll
            for (int tn = 0; tn < 4; tn++) {
                const int tp = tn >> 1, sel = tn & 1;
                MMA16816(acc[tm][tn], ah[tm], bh[tp][sel], bh[tp][sel + 2]);
                MMA16816(acc[tm][tn], ah[tm], bl[tp][sel], bl[tp][sel + 2]);
                MMA16816(acc[tm][tn], al[tm], bh[tp][sel], bh[tp][sel + 2]);
            }
        }
    }
}

// cp.async issue of one 32-wide chunk for 4 tiles of 128 rows.
// gsrc: per-thread base (row0, col within tile); ld: element row stride.
#define ISSUE_128(c, gsrc, ld, sdst)                                      \
    do {                                                                  \
        const __nv_bfloat16* gp_ = (gsrc) + (size_t)(c) * 32;             \
        const uint32_t sb_ = (sdst) + ((c) & 1) * BUFB;                   \
        _Pragma("unroll")                                                 \
        for (int kq = 0; kq < 8; kq++)                                    \
            CPASYNC16(sb_ + kq * 16 * PADB, gp_ + (size_t)(kq * 16) * (ld)); \
        CP_COMMIT();                                                      \
    } while (0)

// ============================================================
// conversion kernels
// ============================================================
__global__ void conv_split(const float* __restrict__ src,
                           __nv_bfloat16* __restrict__ hi, __nv_bfloat16* __restrict__ lo,
                           int n) {
    int i = blockIdx.x * 256 + threadIdx.x;
    if (i >= n) return;
    float v = src[i];
    __nv_bfloat16 h; float r;
    split1(v, h, r);
    hi[i] = h;
    lo[i] = __float2bfloat16_rn(r);
}

__global__ void conv_split_T(const float* __restrict__ src,
                             __nv_bfloat16* __restrict__ hi, __nv_bfloat16* __restrict__ lo,
                             int R, int C) {
    __shared__ float tile[32][33];
    const int bx = blockIdx.x * 32, by = blockIdx.y * 32;
    const int tx = threadIdx.x, ty = threadIdx.y;
#pragma unroll
    for (int i = 0; i < 32; i += 8)
        tile[ty + i][tx] = src[(size_t)(by + ty + i) * C + bx + tx];
    __syncthreads();
#pragma unroll
    for (int i = 0; i < 32; i += 8) {
        float v = tile[tx][ty + i];
        __nv_bfloat16 h; float r;
        split1(v, h, r);
        size_t o = (size_t)(bx + ty + i) * R + by + tx;
        hi[o] = h;
        lo[o] = __float2bfloat16_rn(r);
    }
}

__global__ void conv_vT(const float* __restrict__ qkv,
                        __nv_bfloat16* __restrict__ hi, __nv_bfloat16* __restrict__ lo) {
    __shared__ float tile[32][33];
    const int h = blockIdx.z;
    const int bx = blockIdx.x * 32;
    const int by = blockIdx.y * 32;
    const int tx = threadIdx.x, ty = threadIdx.y;
#pragma unroll
    for (int i = 0; i < 32; i += 8)
        tile[ty + i][tx] = qkv[(size_t)(bx + ty + i) * LDQ + 5 * 1024 + h * DH + by + tx];
    __syncthreads();
#pragma unroll
    for (int i = 0; i < 32; i += 8) {
        float v = tile[tx][ty + i];
        __nv_bfloat16 hh; float r;
        split1(v, hh, r);
        size_t o = (size_t)(h * DH + by + ty + i) * NS + bx + tx;
        hi[o] = hh;
        lo[o] = __float2bfloat16_rn(r);
    }
}

// ============================================================
// qkv = x @ Wqkv (HMMA split), 32 chunks of K=32, 2 CTAs/SM
// ============================================================
__global__ void __launch_bounds__(256, 2) qkv_mma(
    const __nv_bfloat16* __restrict__ XH, const __nv_bfloat16* __restrict__ XL,
    const __nv_bfloat16* __restrict__ WH, const __nv_bfloat16* __restrict__ WL,
    float* __restrict__ QKV, __nv_bfloat16* __restrict__ QH, __nv_bfloat16* __restrict__ QL)
{
    const int bm = blockIdx.y, bn = blockIdx.x;
    extern __shared__ char sm[];
    const uint32_t smb = smem_u32(sm);
    const int t = threadIdx.x;
    const int wid = t >> 5, lane = t & 31;
    const int m0 = (wid & 1) * 64;
    const int n0 = (wid >> 1) * 32;

    const int grp  = t >> 6;
    const int gg   = t & 63;
    const int col  = gg & 3;
    const int row0 = gg >> 2;
    const __nv_bfloat16* base;
    if (grp == 0)      base = XH + (size_t)(bm * 128) * DIMM;
    else if (grp == 1) base = XL + (size_t)(bm * 128) * DIMM;
    else if (grp == 2) base = WH + (size_t)(bn * 128) * DIMM;
    else               base = WL + (size_t)(bn * 128) * DIMM;
    const __nv_bfloat16* gsrc = base + (size_t)row0 * DIMM + col * 8;
    const uint32_t sdst = smb + grp * TILEB + row0 * PADB + col * 16;

    ISSUE_128(0, gsrc, DIMM, sdst);

    float acc[4][4][4] = {};
    const int lrow = lane & 15;
    const uint32_t lkoff = (uint32_t)((lane >> 4) * 16);

    for (int c = 0; c < 32; c++) {
        if (c + 1 < 32) { ISSUE_128(c + 1, gsrc, DIMM, sdst); CP_WAIT1(); }
        else            { CP_WAIT0(); }
        __syncthreads();
        const uint32_t bse = smb + (c & 1) * BUFB;
        mma_chunk_128(bse, bse + TILEB, bse + 2 * TILEB, bse + 3 * TILEB,
                      m0, n0, lrow, lkoff, acc);
        __syncthreads();
    }

    const int g  = lane >> 2;
    const int tg = lane & 3;
#pragma unroll
    for (int tm = 0; tm < 4; tm++) {
#pragma unroll
        for (int tn = 0; tn < 4; tn++) {
            const int i0 = bm * 128 + m0 + tm * 16 + g;
            const int j0 = bn * 128 + n0 + tn * 8 + tg * 2;
            float v0 = acc[tm][tn][0], v1 = acc[tm][tn][1];
            float v2 = acc[tm][tn][2], v3 = acc[tm][tn][3];
            size_t o0 = (size_t)i0 * LDQ + j0;
            size_t o1 = o0 + (size_t)8 * LDQ;
            *(float2*)(QKV + o0) = make_float2(v0, v1);
            *(float2*)(QKV + o1) = make_float2(v2, v3);
            __nv_bfloat16 h; float r0, r1, r2, r3;
            split1(v0, h, r0); split1(v1, h, r1); split1(v2, h, r2); split1(v3, h, r3);
            *(uint32_t*)(QH + o0) = pack_bf2(v0, v1);
            *(uint32_t*)(QH + o1) = pack_bf2(v2, v3);
            *(uint32_t*)(QL + o0) = pack_bf2(r0, r1);
            *(uint32_t*)(QL + o1) = pack_bf2(r2, r3);
        }
    }
}

// ============================================================
// Per-head NT GEMM K=64 (2 chunks). MODE1 term1, MODE2 lookahead, MODE3 Sc.
// ============================================================
template <int MODE>
__global__ void __launch_bounds__(256, 2) head_mma(
    const __nv_bfloat16* __restrict__ QH, const __nv_bfloat16* __restrict__ QL,
    int aoff, int boff,
    __nv_bfloat16* __restrict__ CH, __nv_bfloat16* __restrict__ CL,
    float* __restrict__ CF)
{
    const int h  = blockIdx.z;
    const int bi = blockIdx.y, bj = blockIdx.x;
    if (MODE != 2 && bj > bi) return;
    if (MODE == 2 && bj < bi) return;

    extern __shared__ char sm[];
    const uint32_t smb = smem_u32(sm);
    const int t = threadIdx.x;
    const int wid = t >> 5, lane = t & 31;
    const int m0 = (wid & 1) * 64;
    const int n0 = (wid >> 1) * 32;

    const int grp  = t >> 6;
    const int gg   = t & 63;
    const int col  = gg & 3;
    const int row0 = gg >> 2;
    const __nv_bfloat16* base;
    if (grp == 0)      base = QH + (size_t)(bi * 128) * LDQ + aoff + h * DH;
    else if (grp == 1) base = QL + (size_t)(bi * 128) * LDQ + aoff + h * DH;
    else if (grp == 2) base = QH + (size_t)(bj * 128) * LDQ + boff + h * DH;
    else               base = QL + (size_t)(bj * 128) * LDQ + boff + h * DH;
    const __nv_bfloat16* gsrc = base + (size_t)row0 * LDQ + col * 8;
    const uint32_t sdst = smb + grp * TILEB + row0 * PADB + col * 16;

    ISSUE_128(0, gsrc, LDQ, sdst);
    ISSUE_128(1, gsrc, LDQ, sdst);

    float acc[4][4][4] = {};
    const int lrow = lane & 15;
    const uint32_t lkoff = (uint32_t)((lane >> 4) * 16);

    CP_WAIT1();
    __syncthreads();
    {
        const uint32_t bse = smb;
        mma_chunk_128(bse, bse + TILEB, bse + 2 * TILEB, bse + 3 * TILEB,
                      m0, n0, lrow, lkoff, acc);
    }
    CP_WAIT0();
    __syncthreads();
    {
        const uint32_t bse = smb + BUFB;
        mma_chunk_128(bse, bse + TILEB, bse + 2 * TILEB, bse + 3 * TILEB,
                      m0, n0, lrow, lkoff, acc);
    }

    const size_t hb = (size_t)h * NS * NS;
    const int g  = lane >> 2;
    const int tg = lane & 3;
#pragma unroll
    for (int tm = 0; tm < 4; tm++) {
#pragma unroll
        for (int tn = 0; tn < 4; tn++) {
            const int i0 = bi * 128 + m0 + tm * 16 + g;
            const int j0 = bj * 128 + n0 + tn * 8 + tg * 2;
            float v[4];
            v[0] = acc[tm][tn][0] * SCALE; v[1] = acc[tm][tn][1] * SCALE;
            v[2] = acc[tm][tn][2] * SCALE; v[3] = acc[tm][tn][3] * SCALE;
            const int ii[4] = {i0, i0, i0 + 8, i0 + 8};
            const int jj[4] = {j0, j0 + 1, j0, j0 + 1};
#pragma unroll
            for (int q = 0; q < 4; q++) {
                if (MODE == 1) v[q] = (jj[q] <= ii[q]) ? v[q] : 0.0f;
                if (MODE == 2) v[q] = (jj[q] >  ii[q]) ? (1.0f / (1.0f + expf(-v[q]))) : 0.0f;
            }
            size_t o0 = hb + (size_t)i0 * NS + j0;
            size_t o1 = o0 + (size_t)8 * NS;
            if (MODE == 3) {
                *(float2*)(CF + o0) = make_float2(v[0], v[1]);
                *(float2*)(CF + o1) = make_float2(v[2], v[3]);
            } else {
                __nv_bfloat16 hh; float r[4];
                split1(v[0], hh, r[0]); split1(v[1], hh, r[1]);
                split1(v[2], hh, r[2]); split1(v[3], hh, r[3]);
                *(uint32_t*)(CH + o0) = pack_bf2(v[0], v[1]);
                *(uint32_t*)(CH + o1) = pack_bf2(v[2], v[3]);
                *(uint32_t*)(CL + o0) = pack_bf2(r[0], r[1]);
                *(uint32_t*)(CL + o1) = pack_bf2(r[2], r[3]);
            }
        }
    }
}

// ============================================================
// Su (HMMA split), fused SC -= silu(Su). 32-wide chunks.
// ============================================================
__global__ void __launch_bounds__(256, 2) su_fuse_mma(
    const __nv_bfloat16* __restrict__ T1H, const __nv_bfloat16* __restrict__ T1L,
    const __nv_bfloat16* __restrict__ LKH, const __nv_bfloat16* __restrict__ LKL,
    float* __restrict__ SC)
{
    const int h = blockIdx.z, bi = blockIdx.y, bk = blockIdx.x;
    if (bk > bi) return;

    extern __shared__ char sm[];
    const uint32_t smb = smem_u32(sm);
    const int t = threadIdx.x;
    const int wid = t >> 5, lane = t & 31;
    const int m0 = (wid & 1) * 64;
    const int n0 = (wid >> 1) * 32;

    const size_t hb = (size_t)h * NS * NS;
    const __nv_bfloat16* srcs[4] = {
        T1H + hb + (size_t)(bi * 128) * NS,
        T1L + hb + (size_t)(bi * 128) * NS,
        LKH + hb + (size_t)(bk * 128) * NS,
        LKL + hb + (size_t)(bk * 128) * NS
    };

    const int grp  = t >> 6;
    const int gg   = t & 63;
    const int col  = gg & 3;
    const int row0 = gg >> 2;
    const __nv_bfloat16* gsrc = srcs[grp] + (size_t)row0 * NS + (size_t)bk * 128 + col * 8;
    const uint32_t sdst = smb + grp * TILEB + row0 * PADB + col * 16;

    const int nCh = 4 * (bi - bk + 1);
    ISSUE_128(0, gsrc, NS, sdst);

    float acc[4][4][4] = {};
    const int lrow = lane & 15;
    const uint32_t lkoff = (uint32_t)((lane >> 4) * 16);

    for (int c = 0; c < nCh; c++) {
        if (c + 1 < nCh) { ISSUE_128(c + 1, gsrc, NS, sdst); CP_WAIT1(); }
        else             { CP_WAIT0(); }
        __syncthreads();
        const uint32_t bse = smb + (c & 1) * BUFB;
        mma_chunk_128(bse, bse + TILEB, bse + 2 * TILEB, bse + 3 * TILEB,
                      m0, n0, lrow, lkoff, acc);
        __syncthreads();
    }

    const int g  = lane >> 2;
    const int tg = lane & 3;
#pragma unroll
    for (int tm = 0; tm < 4; tm++) {
#pragma unroll
        for (int tn = 0; tn < 4; tn++) {
            const int i0 = bi * 128 + m0 + tm * 16 + g;
            const int j0 = bk * 128 + n0 + tn * 8 + tg * 2;
            float* p0 = SC + hb + (size_t)i0 * NS + j0;
            float* p1 = p0 + (size_t)8 * NS;
            float2 c0 = *(float2*)p0;
            float2 c1 = *(float2*)p1;
            float s0 = acc[tm][tn][0], s1 = acc[tm][tn][1];
            float s2 = acc[tm][tn][2], s3 = acc[tm][tn][3];
            c0.x -= s0 / (1.0f + expf(-s0));
            c0.y -= s1 / (1.0f + expf(-s1));
            c1.x -= s2 / (1.0f + expf(-s2));
            c1.y -= s3 / (1.0f + expf(-s3));
            *(float2*)p0 = c0;
            *(float2*)p1 = c1;
        }
    }
}

// ============================================================
// Row softmax -> split bf16 attn, zero-padded to 128 boundary.
// ============================================================
__global__ void row_softmax_bf(const float* __restrict__ SC,
                               __nv_bfloat16* __restrict__ AH,
                               __nv_bfloat16* __restrict__ AL) {
    const int h = blockIdx.y, i = blockIdx.x;
    const float* row = SC + (size_t)h * NS * NS + (size_t)i * NS;
    __nv_bfloat16* rh = AH + (size_t)h * NS * NS + (size_t)i * NS;
    __nv_bfloat16* rl = AL + (size_t)h * NS * NS + (size_t)i * NS;
    const int t = threadIdx.x;
    const int len = i + 1;

    __shared__ float red[256];

    float lmax = -1e30f;
    for (int j = t; j < len; j += 256) lmax = fmaxf(lmax, row[j]);
    red[t] = lmax; __syncthreads();
    for (int s = 128; s > 0; s >>= 1) { if (t < s) red[t] = fmaxf(red[t], red[t + s]); __syncthreads(); }
    const float bmax = red[0];
    __syncthreads();

    float ev[8];
    int cnt = 0;
    float lsum = 0.0f;
    for (int j = t; j < len; j += 256) {
        float e = expf(row[j] - bmax);
        ev[cnt++] = e;
        lsum += e;
    }
    red[t] = lsum; __syncthreads();
    for (int s = 128; s > 0; s >>= 1) { if (t < s) red[t] += red[t + s]; __syncthreads(); }
    const float inv = 1.0f / red[0];

    cnt = 0;
    for (int j = t; j < len; j += 256) {
        float p = ev[cnt++] * inv;
        __nv_bfloat16 hh; float r;
        split1(p, hh, r);
        rh[j] = hh;
        rl[j] = __float2bfloat16_rn(r);
    }
    const int padEnd = ((i >> 7) + 1) << 7;
    const __nv_bfloat16 z = __float2bfloat16_rn(0.0f);
    for (int j = len + t; j < padEnd; j += 256) { rh[j] = z; rl[j] = z; }
}

// ============================================================
// AV (HMMA split): ctx = attn @ vc. M=128, N=64, 32-wide chunks.
// ============================================================
__global__ void __launch_bounds__(256, 2) av_mma(
    const __nv_bfloat16* __restrict__ ATH, const __nv_bfloat16* __restrict__ ATL,
    const __nv_bfloat16* __restrict__ VTH, const __nv_bfloat16* __restrict__ VTL,
    __nv_bfloat16* __restrict__ CTH, __nv_bfloat16* __restrict__ CTL)
{
    const int h = blockIdx.y, bi = blockIdx.x;
    extern __shared__ char sm[];
    const uint32_t smb = smem_u32(sm);
    const int t = threadIdx.x;
    const int wid = t >> 5, lane = t & 31;
    const int m0 = (wid & 3) * 32;
    const int n0 = (wid >> 2) * 32;

    const size_t hb = (size_t)h * NS * NS;
    const __nv_bfloat16* gAh = ATH + hb + (size_t)(bi * 128) * NS;
    const __nv_bfloat16* gAl = ATL + hb + (size_t)(bi * 128) * NS;
    const __nv_bfloat16* gBh = VTH + (size_t)(h * DH) * NS;
    const __nv_bfloat16* gBl = VTL + (size_t)(h * DH) * NS;

    const int arow = t >> 1;
    const int ac0  = (t & 1) * 2;       // 2 of 4 16B cols
    const int brow = t >> 2;
    const int bc0  = t & 3;

#define AV_ISSUE(c)                                                             \
    do {                                                                        \
        const size_t j0 = (size_t)(c) * 32;                                     \
        const uint32_t bb = smb + ((c) & 1) * AV_STAGE;                         \
        const __nv_bfloat16* pah = gAh + (size_t)arow * NS + j0 + ac0 * 8;      \
        const __nv_bfloat16* pal = gAl + (size_t)arow * NS + j0 + ac0 * 8;      \
        const uint32_t sA = bb + arow * PADB + ac0 * 16;                        \
        CPASYNC16(sA,                        pah);                              \
        CPASYNC16(sA + 16,                   pah + 8);                          \
        CPASYNC16(sA + 128 * PADB,           pal);                              \
        CPASYNC16(sA + 128 * PADB + 16,      pal + 8);                          \
        const __nv_bfloat16* pbh = gBh + (size_t)brow * NS + j0 + bc0 * 8;      \
        const __nv_bfloat16* pbl = gBl + (size_t)brow * NS + j0 + bc0 * 8;      \
        const uint32_t sB = bb + 256 * PADB + brow * PADB + bc0 * 16;           \
        CPASYNC16(sB,             pbh);                                         \
        CPASYNC16(sB + 64 * PADB, pbl);                                         \
        CP_COMMIT();                                                            \
    } while (0)

    const int nCh = 4 * (bi + 1);
    AV_ISSUE(0);

    float acc[2][4][4] = {};
    const int lrow = lane & 15;
    const uint32_t lkoff = (uint32_t)((lane >> 4) * 16);

    for (int c = 0; c < nCh; c++) {
        if (c + 1 < nCh) { AV_ISSUE(c + 1); CP_WAIT1(); }
        else             { CP_WAIT0(); }
        __syncthreads();

        const uint32_t bse = smb + (c & 1) * AV_STAGE;
        const uint32_t aH = bse;
        const uint32_t aL = bse + 128 * PADB;
        const uint32_t bH = bse + 256 * PADB;
        const uint32_t bL = bse + 320 * PADB;

#pragma unroll
        for (int kk = 0; kk < 2; kk++) {
            const uint32_t ko = kk * 32 + lkoff;
            uint32_t ah[2][4], al[2][4];
            const uint32_t aoff = (uint32_t)((m0 + lrow) * PADB) + ko;
#pragma unroll
            for (int tm = 0; tm < 2; tm++) {
                LDMX4(ah[tm], aH + aoff + tm * 16 * PADB);
                LDMX4(al[tm], aL + aoff + tm * 16 * PADB);
            }
            uint32_t bh[2][4], bl[2][4];
            const uint32_t boff = (uint32_t)((n0 + lrow) * PADB) + ko;
#pragma unroll
            for (int tp = 0; tp < 2; tp++) {
                LDMX4(bh[tp], bH + boff + tp * 16 * PADB);
                LDMX4(bl[tp], bL + boff + tp * 16 * PADB);
            }
#pragma unroll
            for (int tm = 0; tm < 2; tm++) {
#pragma unroll
                for (int tn = 0; tn < 4; tn++) {
                    const int tp = tn >> 1, sel = tn & 1;
                    MMA16816(acc[tm][tn], ah[tm], bh[tp][sel], bh[tp][sel + 2]);
                    MMA16816(acc[tm][tn], ah[tm], bl[tp][sel], bl[tp][sel + 2]);
                    MMA16816(acc[tm][tn], al[tm], bh[tp][sel], bh[tp][sel + 2]);
                }
            }
        }
        __syncthreads();
    }

    const int g  = lane >> 2;
    const int tg = lane & 3;
#pragma unroll
    for (int tm = 0; tm < 2; tm++) {
#pragma unroll
        for (int tn = 0; tn < 4; tn++) {
            const int i0 = bi * 128 + m0 + tm * 16 + g;
            const int d0 = n0 + tn * 8 + tg * 2;
            size_t o0 = (size_t)i0 * DIMM + h * DH + d0;
            size_t o1 = o0 + (size_t)8 * DIMM;
            float v0 = acc[tm][tn][0], v1 = acc[tm][tn][1];
            float v2 = acc[tm][tn][2], v3 = acc[tm][tn][3];
            __nv_bfloat16 hh; float r0, r1, r2, r3;
            split1(v0, hh, r0); split1(v1, hh, r1); split1(v2, hh, r2); split1(v3, hh, r3);
            *(uint32_t*)(CTH + o0) = pack_bf2(v0, v1);
            *(uint32_t*)(CTH + o1) = pack_bf2(v2, v3);
            *(uint32_t*)(CTL + o0) = pack_bf2(r0, r1);
            *(uint32_t*)(CTL + o1) = pack_bf2(r2, r3);
        }
    }
}

// ============================================================
// out = ctx @ Wout (HMMA split), 32 chunks of K=32.
// ============================================================
__global__ void __launch_bounds__(256, 2) out_mma(
    const __nv_bfloat16* __restrict__ AH0, const __nv_bfloat16* __restrict__ AL0,
    const __nv_bfloat16* __restrict__ BH0, const __nv_bfloat16* __restrict__ BL0,
    float* __restrict__ C)
{
    const int bm = blockIdx.y, bn = blockIdx.x;
    extern __shared__ char sm[];
    const uint32_t smb = smem_u32(sm);
    const int t = threadIdx.x;
    const int wid = t >> 5, lane = t & 31;
    const int m0 = (wid & 1) * 64;
    const int n0 = (wid >> 1) * 32;

    const int grp  = t >> 6;
    const int gg   = t & 63;
    const int col  = gg & 3;
    const int row0 = gg >> 2;
    const __nv_bfloat16* base;
    if (grp == 0)      base = AH0 + (size_t)(bm * 128) * DIMM;
    else if (grp == 1) base = AL0 + (size_t)(bm * 128) * DIMM;
    else if (grp == 2) base = BH0 + (size_t)(bn * 128) * DIMM;
    else               base = BL0 + (size_t)(bn * 128) * DIMM;
    const __nv_bfloat16* gsrc = base + (size_t)row0 * DIMM + col * 8;
    const uint32_t sdst = smb + grp * TILEB + row0 * PADB + col * 16;

    ISSUE_128(0, gsrc, DIMM, sdst);

    float acc[4][4][4] = {};
    const int lrow = lane & 15;
    const uint32_t lkoff = (uint32_t)((lane >> 4) * 16);

    for (int c = 0; c < 32; c++) {
        if (c + 1 < 32) { ISSUE_128(c + 1, gsrc, DIMM, sdst); CP_WAIT1(); }
        else            { CP_WAIT0(); }
        __syncthreads();
        const uint32_t bse = smb + (c & 1) * BUFB;
        mma_chunk_128(bse, bse + TILEB, bse + 2 * TILEB, bse + 3 * TILEB,
                      m0, n0, lrow, lkoff, acc);
        __syncthreads();
    }

    const int g  = lane >> 2;
    const int tg = lane & 3;
#pragma unroll
    for (int tm = 0; tm < 4; tm++) {
#pragma unroll
        for (int tn = 0; tn < 4; tn++) {
            const int i0 = bm * 128 + m0 + tm * 16 + g;
            const int j0 = bn * 128 + n0 + tn * 8 + tg * 2;
            size_t o0 = (size_t)i0 * DIMM + j0;
            size_t o1 = o0 + (size_t)8 * DIMM;
            *(float2*)(C + o0) = make_float2(acc[tm][tn][0], acc[tm][tn][1]);
            *(float2*)(C + o1) = make_float2(acc[tm][tn][2], acc[tm][tn][3]);
        }
    }
}

// ============================================================
extern "C" void kernel_launch(void* const* d_in, const int* in_sizes, int n_in,
                              void* d_out, int out_size) {
    const float* x    = (const float*)d_in[0];
    const float* Wqkv = (const float*)d_in[1];
    const float* Wout = (const float*)d_in[2];
    float* out = (float*)d_out;

    float *qkv, *sc;
    __nv_bfloat16 *qh, *ql, *xh, *xl, *wqh, *wql, *t1h, *t1l, *lkh, *lkl;
    __nv_bfloat16 *vth, *vtl, *cth, *ctl, *woh, *wol;
    cudaGetSymbolAddress((void**)&qkv, g_qkv);
    cudaGetSymbolAddress((void**)&qh,  g_qh);
    cudaGetSymbolAddress((void**)&ql,  g_ql);
    cudaGetSymbolAddress((void**)&xh,  g_xh);
    cudaGetSymbolAddress((void**)&xl,  g_xl);
    cudaGetSymbolAddress((void**)&wqh, g_wqh);
    cudaGetSymbolAddress((void**)&wql, g_wql);
    cudaGetSymbolAddress((void**)&t1h, g_t1h);
    cudaGetSymbolAddress((void**)&t1l, g_t1l);
    cudaGetSymbolAddress((void**)&lkh, g_lkh);
    cudaGetSymbolAddress((void**)&lkl, g_lkl);
    cudaGetSymbolAddress((void**)&sc,  g_sc);
    cudaGetSymbolAddress((void**)&vth, g_vth);
    cudaGetSymbolAddress((void**)&vtl, g_vtl);
    cudaGetSymbolAddress((void**)&cth, g_cth);
    cudaGetSymbolAddress((void**)&ctl, g_ctl);
    cudaGetSymbolAddress((void**)&woh, g_woh);
    cudaGetSymbolAddress((void**)&wol, g_wol);

    cudaFuncSetAttribute(qkv_mma,     cudaFuncAttributeMaxDynamicSharedMemorySize, DBUF_SMEM);
    cudaFuncSetAttribute(su_fuse_mma, cudaFuncAttributeMaxDynamicSharedMemorySize, DBUF_SMEM);
    cudaFuncSetAttribute(out_mma,     cudaFuncAttributeMaxDynamicSharedMemorySize, DBUF_SMEM);
    cudaFuncSetAttribute(av_mma,      cudaFuncAttributeMaxDynamicSharedMemorySize, AV_SMEM);
    cudaFuncSetAttribute(head_mma<1>, cudaFuncAttributeMaxDynamicSharedMemorySize, DBUF_SMEM);
    cudaFuncSetAttribute(head_mma<2>, cudaFuncAttributeMaxDynamicSharedMemorySize, DBUF_SMEM);
    cudaFuncSetAttribute(head_mma<3>, cudaFuncAttributeMaxDynamicSharedMemorySize, DBUF_SMEM);

    const dim3 thr(256);

    // 0) split inputs
    conv_split  <<<(NS * DIMM + 255) / 256, thr>>>(x, xh, xl, NS * DIMM);
    conv_split_T<<<dim3(LDQ / 32, DIMM / 32), dim3(32, 8)>>>(Wqkv, wqh, wql, DIMM, LDQ);
    conv_split_T<<<dim3(DIMM / 32, DIMM / 32), dim3(32, 8)>>>(Wout, woh, wol, DIMM, DIMM);

    // 1) qkv projection (HMMA)
    qkv_mma<<<dim3(LDQ / 128, NS / 128), thr, DBUF_SMEM>>>(xh, xl, wqh, wql, qkv, qh, ql);

    // 1b) vc^T split
    conv_vT<<<dim3(NS / 32, DH / 32, NH), dim3(32, 8)>>>(qkv, vth, vtl);

    // 2) per-head K=64 GEMMs (HMMA)
    const dim3 gHead(NS / 128, NS / 128, NH);
    head_mma<1><<<gHead, thr, DBUF_SMEM>>>(qh, ql, 3 * 1024, 2 * 1024, t1h, t1l, nullptr);
    head_mma<2><<<gHead, thr, DBUF_SMEM>>>(qh, ql, 0 * 1024, 1 * 1024, lkh, lkl, nullptr);
    head_mma<3><<<gHead, thr, DBUF_SMEM>>>(qh, ql, 3 * 1024, 4 * 1024, nullptr, nullptr, sc);

    // 3) Su (HMMA), fused scores = Sc - silu(Su)
    su_fuse_mma<<<gHead, thr, DBUF_SMEM>>>(t1h, t1l, lkh, lkl, sc);

    // 4) softmax -> attn split bf16 (reuses t1h/t1l)
    row_softmax_bf<<<dim3(NS, NH), thr>>>(sc, t1h, t1l);

    // 5) ctx = attn @ vc (HMMA)
    av_mma<<<dim3(NS / 128, NH), thr, AV_SMEM>>>(t1h, t1l, vth, vtl, cth, ctl);

    // 6) out = ctx @ W_out (HMMA)
    out_mma<<<dim3(DIMM / 128, NS / 128), thr, DBUF_SMEM>>>(cth, ctl, woh, wol, out);
}

// round 8
// speedup vs baseline: 2.2428x; 1.0685x over previous
#include <cuda_runtime.h>
#include <cuda_bf16.h>
#include <math.h>
#include <stdint.h>

#define NS   2048
#define NH   16
#define DH   64
#define DIMM 1024
#define LDQ  6144

__device__ __constant__ float SCALE = 0.125f;

// ---- scratch ----
__device__ __nv_bfloat16 g_qh [(size_t)NS * LDQ];
__device__ __nv_bfloat16 g_ql [(size_t)NS * LDQ];
__device__ __nv_bfloat16 g_xh [(size_t)NS * DIMM];
__device__ __nv_bfloat16 g_xl [(size_t)NS * DIMM];
__device__ __nv_bfloat16 g_wqh[(size_t)LDQ * DIMM];
__device__ __nv_bfloat16 g_wql[(size_t)LDQ * DIMM];
__device__ __nv_bfloat16 g_t1h[(size_t)NH * NS * NS];
__device__ __nv_bfloat16 g_t1l[(size_t)NH * NS * NS];
__device__ __nv_bfloat16 g_lkh[(size_t)NH * NS * NS];
__device__ __nv_bfloat16 g_lkl[(size_t)NH * NS * NS];
__device__ float g_sc [(size_t)NH * NS * NS];
__device__ __nv_bfloat16 g_vth[(size_t)NH * DH * NS];
__device__ __nv_bfloat16 g_vtl[(size_t)NH * DH * NS];
__device__ __nv_bfloat16 g_cth[(size_t)NS * DIMM];
__device__ __nv_bfloat16 g_ctl[(size_t)NS * DIMM];
__device__ __nv_bfloat16 g_woh[(size_t)DIMM * DIMM];
__device__ __nv_bfloat16 g_wol[(size_t)DIMM * DIMM];

// ============================================================
// helpers
// ============================================================
__device__ __forceinline__ uint32_t smem_u32(const void* p) {
    uint32_t a;
    asm("{ .reg .u64 t; cvta.to.shared.u64 t, %1; cvt.u32.u64 %0, t; }" : "=r"(a) : "l"(p));
    return a;
}

#define CPASYNC16(s, g) \
    asm volatile("cp.async.cg.shared.global [%0], [%1], 16;" :: "r"(s), "l"(g) : "memory")
#define CP_COMMIT() asm volatile("cp.async.commit_group;" ::: "memory")
#define CP_WAIT0()  asm volatile("cp.async.wait_group 0;" ::: "memory")
#define CP_WAIT1()  asm volatile("cp.async.wait_group 1;" ::: "memory")

#define LDMX4(r, addr) \
    asm volatile("ldmatrix.sync.aligned.m8n8.x4.shared.b16 {%0,%1,%2,%3}, [%4];" \
        : "=r"((r)[0]), "=r"((r)[1]), "=r"((r)[2]), "=r"((r)[3]) : "r"(addr))

#define MMA16816(d, a, b0, b1) \
    asm volatile("mma.sync.aligned.m16n8k16.row.col.f32.bf16.bf16.f32 " \
        "{%0,%1,%2,%3}, {%4,%5,%6,%7}, {%8,%9}, {%0,%1,%2,%3};" \
        : "+f"((d)[0]), "+f"((d)[1]), "+f"((d)[2]), "+f"((d)[3]) \
        : "r"((a)[0]), "r"((a)[1]), "r"((a)[2]), "r"((a)[3]), "r"(b0), "r"(b1))

__device__ __forceinline__ uint32_t pack_bf2(float a, float b) {
    __nv_bfloat162 t = __floats2bfloat162_rn(a, b);
    return *(uint32_t*)&t;
}
__device__ __forceinline__ void split1(float v, __nv_bfloat16& h, float& r) {
    h = __float2bfloat16_rn(v);
    r = v - __bfloat162float(h);
}
__device__ __forceinline__ float fast_sigmoid(float x) {
    return __fdividef(1.0f, 1.0f + __expf(-x));
}
__device__ __forceinline__ float fast_silu(float x) {
    return __fdividef(x, 1.0f + __expf(-x));
}

// 32-wide K chunks: 64B data + 16B pad per row
#define PADB   80
#define TILEB  (128 * PADB)      // 10240
#define BUFB   (4 * TILEB)       // 40960
#define DBUF_SMEM (2 * BUFB)     // 81920 -> 2 CTAs/SM
#define AV_STAGE  (384 * PADB)   // 30720
#define AV_SMEM   (2 * AV_STAGE) // 61440

// ============================================================
// chunk compute: 128x128 tile, warp 64x32, K=32 per chunk
// ============================================================
__device__ __forceinline__ void mma_chunk_128(
    uint32_t aH, uint32_t aL, uint32_t bH, uint32_t bL,
    int m0, int n0, int lrow, uint32_t lkoff, float acc[4][4][4])
{
#pragma unroll
    for (int kk = 0; kk < 2; kk++) {
        const uint32_t ko = kk * 32 + lkoff;
        uint32_t ah[4][4], al[4][4];
        const uint32_t aoff = (uint32_t)((m0 + lrow) * PADB) + ko;
#pragma unroll
        for (int tm = 0; tm < 4; tm++) {
            LDMX4(ah[tm], aH + aoff + tm * 16 * PADB);
            LDMX4(al[tm], aL + aoff + tm * 16 * PADB);
        }
        uint32_t bh[2][4], bl[2][4];
        const uint32_t boff = (uint32_t)((n0 + lrow) * PADB) + ko;
#pragma unroll
        for (int tp = 0; tp < 2; tp++) {
            LDMX4(bh[tp], bH + boff + tp * 16 * PADB);
            LDMX4(bl[tp], bL + boff + tp * 16 * PADB);
        }
#pragma unroll
        for (int tm = 0; tm < 4; tm++) {
#pragma unroll
            for (int tn = 0; tn < 4; tn++) {
                const int tp = tn >> 1, sel = tn & 1;
                MMA16816(acc[tm][tn], ah[tm], bh[tp][sel], bh[tp][sel + 2]);
                MMA16816(acc[tm][tn], ah[tm], bl[tp][sel], bl[tp][sel + 2]);
                MMA16816(acc[tm][tn], al[tm], bh[tp][sel], bh[tp][sel + 2]);
            }
        }
    }
}

#define ISSUE_128(c, gsrc, ld, sdst)                                      \
    do {                                                                  \
        const __nv_bfloat16* gp_ = (gsrc) + (size_t)(c) * 32;             \
        const uint32_t sb_ = (sdst) + ((c) & 1) * BUFB;                   \
        _Pragma("unroll")                                                 \
        for (int kq = 0; kq < 8; kq++)                                    \
            CPASYNC16(sb_ + kq * 16 * PADB, gp_ + (size_t)(kq * 16) * (ld)); \
        CP_COMMIT();                                                      \
    } while (0)

// ============================================================
// conversion kernels
// ============================================================
__global__ void conv_split(const float* __restrict__ src,
                           __nv_bfloat16* __restrict__ hi, __nv_bfloat16* __restrict__ lo,
                           int n) {
    int i = blockIdx.x * 256 + threadIdx.x;
    if (i >= n) return;
    float v = src[i];
    __nv_bfloat16 h; float r;
    split1(v, h, r);
    hi[i] = h;
    lo[i] = __float2bfloat16_rn(r);
}

__global__ void conv_split_T(const float* __restrict__ src,
                             __nv_bfloat16* __restrict__ hi, __nv_bfloat16* __restrict__ lo,
                             int R, int C) {
    __shared__ float tile[32][33];
    const int bx = blockIdx.x * 32, by = blockIdx.y * 32;
    const int tx = threadIdx.x, ty = threadIdx.y;
#pragma unroll
    for (int i = 0; i < 32; i += 8)
        tile[ty + i][tx] = src[(size_t)(by + ty + i) * C + bx + tx];
    __syncthreads();
#pragma unroll
    for (int i = 0; i < 32; i += 8) {
        float v = tile[tx][ty + i];
        __nv_bfloat16 h; float r;
        split1(v, h, r);
        size_t o = (size_t)(bx + ty + i) * R + by + tx;
        hi[o] = h;
        lo[o] = __float2bfloat16_rn(r);
    }
}

// vt[h][d][j] from split qkv (reconstruct v = hi + lo)
__global__ void conv_vT(const __nv_bfloat16* __restrict__ QH,
                        const __nv_bfloat16* __restrict__ QL,
                        __nv_bfloat16* __restrict__ hi, __nv_bfloat16* __restrict__ lo) {
    __shared__ float tile[32][33];
    const int h = blockIdx.z;
    const int bx = blockIdx.x * 32;
    const int by = blockIdx.y * 32;
    const int tx = threadIdx.x, ty = threadIdx.y;
#pragma unroll
    for (int i = 0; i < 32; i += 8) {
        size_t o = (size_t)(bx + ty + i) * LDQ + 5 * 1024 + h * DH + by + tx;
        tile[ty + i][tx] = __bfloat162float(QH[o]) + __bfloat162float(QL[o]);
    }
    __syncthreads();
#pragma unroll
    for (int i = 0; i < 32; i += 8) {
        float v = tile[tx][ty + i];
        __nv_bfloat16 hh; float r;
        split1(v, hh, r);
        size_t o = (size_t)(h * DH + by + ty + i) * NS + bx + tx;
        hi[o] = hh;
        lo[o] = __float2bfloat16_rn(r);
    }
}

// ============================================================
// qkv = x @ Wqkv (HMMA split), writes split bf16 only
// ============================================================
__global__ void __launch_bounds__(256, 2) qkv_mma(
    const __nv_bfloat16* __restrict__ XH, const __nv_bfloat16* __restrict__ XL,
    const __nv_bfloat16* __restrict__ WH, const __nv_bfloat16* __restrict__ WL,
    __nv_bfloat16* __restrict__ QH, __nv_bfloat16* __restrict__ QL)
{
    const int bm = blockIdx.y, bn = blockIdx.x;
    extern __shared__ char sm[];
    const uint32_t smb = smem_u32(sm);
    const int t = threadIdx.x;
    const int wid = t >> 5, lane = t & 31;
    const int m0 = (wid & 1) * 64;
    const int n0 = (wid >> 1) * 32;

    const int grp  = t >> 6;
    const int gg   = t & 63;
    const int col  = gg & 3;
    const int row0 = gg >> 2;
    const __nv_bfloat16* base;
    if (grp == 0)      base = XH + (size_t)(bm * 128) * DIMM;
    else if (grp == 1) base = XL + (size_t)(bm * 128) * DIMM;
    else if (grp == 2) base = WH + (size_t)(bn * 128) * DIMM;
    else               base = WL + (size_t)(bn * 128) * DIMM;
    const __nv_bfloat16* gsrc = base + (size_t)row0 * DIMM + col * 8;
    const uint32_t sdst = smb + grp * TILEB + row0 * PADB + col * 16;

    ISSUE_128(0, gsrc, DIMM, sdst);

    float acc[4][4][4] = {};
    const int lrow = lane & 15;
    const uint32_t lkoff = (uint32_t)((lane >> 4) * 16);

    for (int c = 0; c < 32; c++) {
        if (c + 1 < 32) { ISSUE_128(c + 1, gsrc, DIMM, sdst); CP_WAIT1(); }
        else            { CP_WAIT0(); }
        __syncthreads();
        const uint32_t bse = smb + (c & 1) * BUFB;
        mma_chunk_128(bse, bse + TILEB, bse + 2 * TILEB, bse + 3 * TILEB,
                      m0, n0, lrow, lkoff, acc);
        __syncthreads();
    }

    const int g  = lane >> 2;
    const int tg = lane & 3;
#pragma unroll
    for (int tm = 0; tm < 4; tm++) {
#pragma unroll
        for (int tn = 0; tn < 4; tn++) {
            const int i0 = bm * 128 + m0 + tm * 16 + g;
            const int j0 = bn * 128 + n0 + tn * 8 + tg * 2;
            float v0 = acc[tm][tn][0], v1 = acc[tm][tn][1];
            float v2 = acc[tm][tn][2], v3 = acc[tm][tn][3];
            size_t o0 = (size_t)i0 * LDQ + j0;
            size_t o1 = o0 + (size_t)8 * LDQ;
            __nv_bfloat16 h; float r0, r1, r2, r3;
            split1(v0, h, r0); split1(v1, h, r1); split1(v2, h, r2); split1(v3, h, r3);
            *(uint32_t*)(QH + o0) = pack_bf2(v0, v1);
            *(uint32_t*)(QH + o1) = pack_bf2(v2, v3);
            *(uint32_t*)(QL + o0) = pack_bf2(r0, r1);
            *(uint32_t*)(QL + o1) = pack_bf2(r2, r3);
        }
    }
}

// ============================================================
// Per-head NT GEMM K=64. MODE1 term1, MODE2 lookahead, MODE3 Sc.
// ============================================================
template <int MODE>
__global__ void __launch_bounds__(256, 2) head_mma(
    const __nv_bfloat16* __restrict__ QH, const __nv_bfloat16* __restrict__ QL,
    int aoff, int boff,
    __nv_bfloat16* __restrict__ CH, __nv_bfloat16* __restrict__ CL,
    float* __restrict__ CF)
{
    const int h  = blockIdx.z;
    const int bi = blockIdx.y, bj = blockIdx.x;
    if (MODE != 2 && bj > bi) return;
    if (MODE == 2 && bj < bi) return;

    extern __shared__ char sm[];
    const uint32_t smb = smem_u32(sm);
    const int t = threadIdx.x;
    const int wid = t >> 5, lane = t & 31;
    const int m0 = (wid & 1) * 64;
    const int n0 = (wid >> 1) * 32;

    const int grp  = t >> 6;
    const int gg   = t & 63;
    const int col  = gg & 3;
    const int row0 = gg >> 2;
    const __nv_bfloat16* base;
    if (grp == 0)      base = QH + (size_t)(bi * 128) * LDQ + aoff + h * DH;
    else if (grp == 1) base = QL + (size_t)(bi * 128) * LDQ + aoff + h * DH;
    else if (grp == 2) base = QH + (size_t)(bj * 128) * LDQ + boff + h * DH;
    else               base = QL + (size_t)(bj * 128) * LDQ + boff + h * DH;
    const __nv_bfloat16* gsrc = base + (size_t)row0 * LDQ + col * 8;
    const uint32_t sdst = smb + grp * TILEB + row0 * PADB + col * 16;

    ISSUE_128(0, gsrc, LDQ, sdst);
    ISSUE_128(1, gsrc, LDQ, sdst);

    float acc[4][4][4] = {};
    const int lrow = lane & 15;
    const uint32_t lkoff = (uint32_t)((lane >> 4) * 16);

    CP_WAIT1();
    __syncthreads();
    {
        const uint32_t bse = smb;
        mma_chunk_128(bse, bse + TILEB, bse + 2 * TILEB, bse + 3 * TILEB,
                      m0, n0, lrow, lkoff, acc);
    }
    CP_WAIT0();
    __syncthreads();
    {
        const uint32_t bse = smb + BUFB;
        mma_chunk_128(bse, bse + TILEB, bse + 2 * TILEB, bse + 3 * TILEB,
                      m0, n0, lrow, lkoff, acc);
    }

    const size_t hb = (size_t)h * NS * NS;
    const int g  = lane >> 2;
    const int tg = lane & 3;
#pragma unroll
    for (int tm = 0; tm < 4; tm++) {
#pragma unroll
        for (int tn = 0; tn < 4; tn++) {
            const int i0 = bi * 128 + m0 + tm * 16 + g;
            const int j0 = bj * 128 + n0 + tn * 8 + tg * 2;
            float v[4];
            v[0] = acc[tm][tn][0] * SCALE; v[1] = acc[tm][tn][1] * SCALE;
            v[2] = acc[tm][tn][2] * SCALE; v[3] = acc[tm][tn][3] * SCALE;
            const int ii[4] = {i0, i0, i0 + 8, i0 + 8};
            const int jj[4] = {j0, j0 + 1, j0, j0 + 1};
#pragma unroll
            for (int q = 0; q < 4; q++) {
                if (MODE == 1) v[q] = (jj[q] <= ii[q]) ? v[q] : 0.0f;
                if (MODE == 2) v[q] = (jj[q] >  ii[q]) ? fast_sigmoid(v[q]) : 0.0f;
            }
            size_t o0 = hb + (size_t)i0 * NS + j0;
            size_t o1 = o0 + (size_t)8 * NS;
            if (MODE == 3) {
                *(float2*)(CF + o0) = make_float2(v[0], v[1]);
                *(float2*)(CF + o1) = make_float2(v[2], v[3]);
            } else {
                __nv_bfloat16 hh; float r[4];
                split1(v[0], hh, r[0]); split1(v[1], hh, r[1]);
                split1(v[2], hh, r[2]); split1(v[3], hh, r[3]);
                *(uint32_t*)(CH + o0) = pack_bf2(v[0], v[1]);
                *(uint32_t*)(CH + o1) = pack_bf2(v[2], v[3]);
                *(uint32_t*)(CL + o0) = pack_bf2(r[0], r[1]);
                *(uint32_t*)(CL + o1) = pack_bf2(r[2], r[3]);
            }
        }
    }
}

// ============================================================
// Su (HMMA split), fused SC -= silu(Su).
// ============================================================
__global__ void __launch_bounds__(256, 2) su_fuse_mma(
    const __nv_bfloat16* __restrict__ T1H, const __nv_bfloat16* __restrict__ T1L,
    const __nv_bfloat16* __restrict__ LKH, const __nv_bfloat16* __restrict__ LKL,
    float* __restrict__ SC)
{
    const int h = blockIdx.z, bi = blockIdx.y, bk = blockIdx.x;
    if (bk > bi) return;

    extern __shared__ char sm[];
    const uint32_t smb = smem_u32(sm);
    const int t = threadIdx.x;
    const int wid = t >> 5, lane = t & 31;
    const int m0 = (wid & 1) * 64;
    const int n0 = (wid >> 1) * 32;

    const size_t hb = (size_t)h * NS * NS;
    const __nv_bfloat16* srcs[4] = {
        T1H + hb + (size_t)(bi * 128) * NS,
        T1L + hb + (size_t)(bi * 128) * NS,
        LKH + hb + (size_t)(bk * 128) * NS,
        LKL + hb + (size_t)(bk * 128) * NS
    };

    const int grp  = t >> 6;
    const int gg   = t & 63;
    const int col  = gg & 3;
    const int row0 = gg >> 2;
    const __nv_bfloat16* gsrc = srcs[grp] + (size_t)row0 * NS + (size_t)bk * 128 + col * 8;
    const uint32_t sdst = smb + grp * TILEB + row0 * PADB + col * 16;

    const int nCh = 4 * (bi - bk + 1);
    ISSUE_128(0, gsrc, NS, sdst);

    float acc[4][4][4] = {};
    const int lrow = lane & 15;
    const uint32_t lkoff = (uint32_t)((lane >> 4) * 16);

    for (int c = 0; c < nCh; c++) {
        if (c + 1 < nCh) { ISSUE_128(c + 1, gsrc, NS, sdst); CP_WAIT1(); }
        else             { CP_WAIT0(); }
        __syncthreads();
        const uint32_t bse = smb + (c & 1) * BUFB;
        mma_chunk_128(bse, bse + TILEB, bse + 2 * TILEB, bse + 3 * TILEB,
                      m0, n0, lrow, lkoff, acc);
        __syncthreads();
    }

    const int g  = lane >> 2;
    const int tg = lane & 3;
#pragma unroll
    for (int tm = 0; tm < 4; tm++) {
#pragma unroll
        for (int tn = 0; tn < 4; tn++) {
            const int i0 = bi * 128 + m0 + tm * 16 + g;
            const int j0 = bk * 128 + n0 + tn * 8 + tg * 2;
            float* p0 = SC + hb + (size_t)i0 * NS + j0;
            float* p1 = p0 + (size_t)8 * NS;
            float2 c0 = *(float2*)p0;
            float2 c1 = *(float2*)p1;
            c0.x -= fast_silu(acc[tm][tn][0]);
            c0.y -= fast_silu(acc[tm][tn][1]);
            c1.x -= fast_silu(acc[tm][tn][2]);
            c1.y -= fast_silu(acc[tm][tn][3]);
            *(float2*)p0 = c0;
            *(float2*)p1 = c1;
        }
    }
}

// ============================================================
// Row softmax -> split bf16 attn, zero-padded to 128 boundary.
// ============================================================
__global__ void row_softmax_bf(const float* __restrict__ SC,
                               __nv_bfloat16* __restrict__ AH,
                               __nv_bfloat16* __restrict__ AL) {
    const int h = blockIdx.y, i = blockIdx.x;
    const float* row = SC + (size_t)h * NS * NS + (size_t)i * NS;
    __nv_bfloat16* rh = AH + (size_t)h * NS * NS + (size_t)i * NS;
    __nv_bfloat16* rl = AL + (size_t)h * NS * NS + (size_t)i * NS;
    const int t = threadIdx.x;
    const int len = i + 1;

    __shared__ float red[256];

    float lmax = -1e30f;
    for (int j = t; j < len; j += 256) lmax = fmaxf(lmax, row[j]);
    red[t] = lmax; __syncthreads();
    for (int s = 128; s > 0; s >>= 1) { if (t < s) red[t] = fmaxf(red[t], red[t + s]); __syncthreads(); }
    const float bmax = red[0];
    __syncthreads();

    float ev[8];
    int cnt = 0;
    float lsum = 0.0f;
    for (int j = t; j < len; j += 256) {
        float e = __expf(row[j] - bmax);
        ev[cnt++] = e;
        lsum += e;
    }
    red[t] = lsum; __syncthreads();
    for (int s = 128; s > 0; s >>= 1) { if (t < s) red[t] += red[t + s]; __syncthreads(); }
    const float inv = __fdividef(1.0f, red[0]);

    cnt = 0;
    for (int j = t; j < len; j += 256) {
        float p = ev[cnt++] * inv;
        __nv_bfloat16 hh; float r;
        split1(p, hh, r);
        rh[j] = hh;
        rl[j] = __float2bfloat16_rn(r);
    }
    const int padEnd = ((i >> 7) + 1) << 7;
    const __nv_bfloat16 z = __float2bfloat16_rn(0.0f);
    for (int j = len + t; j < padEnd; j += 256) { rh[j] = z; rl[j] = z; }
}

// ============================================================
// AV (HMMA split): ctx = attn @ vc. M=128, N=64.
// ============================================================
__global__ void __launch_bounds__(256, 2) av_mma(
    const __nv_bfloat16* __restrict__ ATH, const __nv_bfloat16* __restrict__ ATL,
    const __nv_bfloat16* __restrict__ VTH, const __nv_bfloat16* __restrict__ VTL,
    __nv_bfloat16* __restrict__ CTH, __nv_bfloat16* __restrict__ CTL)
{
    const int h = blockIdx.y, bi = blockIdx.x;
    extern __shared__ char sm[];
    const uint32_t smb = smem_u32(sm);
    const int t = threadIdx.x;
    const int wid = t >> 5, lane = t & 31;
    const int m0 = (wid & 3) * 32;
    const int n0 = (wid >> 2) * 32;

    const size_t hb = (size_t)h * NS * NS;
    const __nv_bfloat16* gAh = ATH + hb + (size_t)(bi * 128) * NS;
    const __nv_bfloat16* gAl = ATL + hb + (size_t)(bi * 128) * NS;
    const __nv_bfloat16* gBh = VTH + (size_t)(h * DH) * NS;
    const __nv_bfloat16* gBl = VTL + (size_t)(h * DH) * NS;

    const int arow = t >> 1;
    const int ac0  = (t & 1) * 2;
    const int brow = t >> 2;
    const int bc0  = t & 3;

#define AV_ISSUE(c)                                                             \
    do {                                                                        \
        const size_t j0 = (size_t)(c) * 32;                                     \
        const uint32_t bb = smb + ((c) & 1) * AV_STAGE;                         \
        const __nv_bfloat16* pah = gAh + (size_t)arow * NS + j0 + ac0 * 8;      \
        const __nv_bfloat16* pal = gAl + (size_t)arow * NS + j0 + ac0 * 8;      \
        const uint32_t sA = bb + arow * PADB + ac0 * 16;                        \
        CPASYNC16(sA,                        pah);                              \
        CPASYNC16(sA + 16,                   pah + 8);                          \
        CPASYNC16(sA + 128 * PADB,           pal);                              \
        CPASYNC16(sA + 128 * PADB + 16,      pal + 8);                          \
        const __nv_bfloat16* pbh = gBh + (size_t)brow * NS + j0 + bc0 * 8;      \
        const __nv_bfloat16* pbl = gBl + (size_t)brow * NS + j0 + bc0 * 8;      \
        const uint32_t sB = bb + 256 * PADB + brow * PADB + bc0 * 16;           \
        CPASYNC16(sB,             pbh);                                         \
        CPASYNC16(sB + 64 * PADB, pbl);                                         \
        CP_COMMIT();                                                            \
    } while (0)

    const int nCh = 4 * (bi + 1);
    AV_ISSUE(0);

    float acc[2][4][4] = {};
    const int lrow = lane & 15;
    const uint32_t lkoff = (uint32_t)((lane >> 4) * 16);

    for (int c = 0; c < nCh; c++) {
        if (c + 1 < nCh) { AV_ISSUE(c + 1); CP_WAIT1(); }
        else             { CP_WAIT0(); }
        __syncthreads();

        const uint32_t bse = smb + (c & 1) * AV_STAGE;
        const uint32_t aH = bse;
        const uint32_t aL = bse + 128 * PADB;
        const uint32_t bH = bse + 256 * PADB;
        const uint32_t bL = bse + 320 * PADB;

#pragma unroll
        for (int kk = 0; kk < 2; kk++) {
            const uint32_t ko = kk * 32 + lkoff;
            uint32_t ah[2][4], al[2][4];
            const uint32_t aoff = (uint32_t)((m0 + lrow) * PADB) + ko;
#pragma unroll
            for (int tm = 0; tm < 2; tm++) {
                LDMX4(ah[tm], aH + aoff + tm * 16 * PADB);
                LDMX4(al[tm], aL + aoff + tm * 16 * PADB);
            }
            uint32_t bh[2][4], bl[2][4];
            const uint32_t boff = (uint32_t)((n0 + lrow) * PADB) + ko;
#pragma unroll
            for (int tp = 0; tp < 2; tp++) {
                LDMX4(bh[tp], bH + boff + tp * 16 * PADB);
                LDMX4(bl[tp], bL + boff + tp * 16 * PADB);
            }
#pragma unroll
            for (int tm = 0; tm < 2; tm++) {
#pragma unroll
                for (int tn = 0; tn < 4; tn++) {
                    const int tp = tn >> 1, sel = tn & 1;
                    MMA16816(acc[tm][tn], ah[tm], bh[tp][sel], bh[tp][sel + 2]);
                    MMA16816(acc[tm][tn], ah[tm], bl[tp][sel], bl[tp][sel + 2]);
                    MMA16816(acc[tm][tn], al[tm], bh[tp][sel], bh[tp][sel + 2]);
                }
            }
        }
        __syncthreads();
    }

    const int g  = lane >> 2;
    const int tg = lane & 3;
#pragma unroll
    for (int tm = 0; tm < 2; tm++) {
#pragma unroll
        for (int tn = 0; tn < 4; tn++) {
            const int i0 = bi * 128 + m0 + tm * 16 + g;
            const int d0 = n0 + tn * 8 + tg * 2;
            size_t o0 = (size_t)i0 * DIMM + h * DH + d0;
            size_t o1 = o0 + (size_t)8 * DIMM;
            float v0 = acc[tm][tn][0], v1 = acc[tm][tn][1];
            float v2 = acc[tm][tn][2], v3 = acc[tm][tn][3];
            __nv_bfloat16 hh; float r0, r1, r2, r3;
            split1(v0, hh, r0); split1(v1, hh, r1); split1(v2, hh, r2); split1(v3, hh, r3);
            *(uint32_t*)(CTH + o0) = pack_bf2(v0, v1);
            *(uint32_t*)(CTH + o1) = pack_bf2(v2, v3);
            *(uint32_t*)(CTL + o0) = pack_bf2(r0, r1);
            *(uint32_t*)(CTL + o1) = pack_bf2(r2, r3);
        }
    }
}

// ============================================================
// out = ctx @ Wout (HMMA split). Tiles 128x64 -> grid 256 CTAs.
// ============================================================
__global__ void __launch_bounds__(256, 2) out_mma(
    const __nv_bfloat16* __restrict__ AH0, const __nv_bfloat16* __restrict__ AL0,
    const __nv_bfloat16* __restrict__ BH0, const __nv_bfloat16* __restrict__ BL0,
    float* __restrict__ C)
{
    const int bm = blockIdx.y, bn = blockIdx.x;
    extern __shared__ char sm[];
    const uint32_t smb = smem_u32(sm);
    const int t = threadIdx.x;
    const int wid = t >> 5, lane = t & 31;
    const int m0 = (wid & 3) * 32;
    const int n0 = (wid >> 2) * 32;

    const __nv_bfloat16* gAh = AH0 + (size_t)(bm * 128) * DIMM;
    const __nv_bfloat16* gAl = AL0 + (size_t)(bm * 128) * DIMM;
    const __nv_bfloat16* gBh = BH0 + (size_t)(bn * 64) * DIMM;
    const __nv_bfloat16* gBl = BL0 + (size_t)(bn * 64) * DIMM;

    const int arow = t >> 1;
    const int ac0  = (t & 1) * 2;
    const int brow = t >> 2;
    const int bc0  = t & 3;

#define OUT_ISSUE(c)                                                            \
    do {                                                                        \
        const size_t j0 = (size_t)(c) * 32;                                     \
        const uint32_t bb = smb + ((c) & 1) * AV_STAGE;                         \
        const __nv_bfloat16* pah = gAh + (size_t)arow * DIMM + j0 + ac0 * 8;    \
        const __nv_bfloat16* pal = gAl + (size_t)arow * DIMM + j0 + ac0 * 8;    \
        const uint32_t sA = bb + arow * PADB + ac0 * 16;                        \
        CPASYNC16(sA,                        pah);                              \
        CPASYNC16(sA + 16,                   pah + 8);                          \
        CPASYNC16(sA + 128 * PADB,           pal);                              \
        CPASYNC16(sA + 128 * PADB + 16,      pal + 8);                          \
        const __nv_bfloat16* pbh = gBh + (size_t)brow * DIMM + j0 + bc0 * 8;    \
        const __nv_bfloat16* pbl = gBl + (size_t)brow * DIMM + j0 + bc0 * 8;    \
        const uint32_t sB = bb + 256 * PADB + brow * PADB + bc0 * 16;           \
        CPASYNC16(sB,             pbh);                                         \
        CPASYNC16(sB + 64 * PADB, pbl);                                         \
        CP_COMMIT();                                                            \
    } while (0)

    OUT_ISSUE(0);

    float acc[2][4][4] = {};
    const int lrow = lane & 15;
    const uint32_t lkoff = (uint32_t)((lane >> 4) * 16);

    for (int c = 0; c < 32; c++) {
        if (c + 1 < 32) { OUT_ISSUE(c + 1); CP_WAIT1(); }
        else            { CP_WAIT0(); }
        __syncthreads();

        const uint32_t bse = smb + (c & 1) * AV_STAGE;
        const uint32_t aH = bse;
        const uint32_t aL = bse + 128 * PADB;
        const uint32_t bH = bse + 256 * PADB;
        const uint32_t bL = bse + 320 * PADB;

#pragma unroll
        for (int kk = 0; kk < 2; kk++) {
            const uint32_t ko = kk * 32 + lkoff;
            uint32_t ah[2][4], al[2][4];
            const uint32_t aoff = (uint32_t)((m0 + lrow) * PADB) + ko;
#pragma unroll
            for (int tm = 0; tm < 2; tm++) {
                LDMX4(ah[tm], aH + aoff + tm * 16 * PADB);
                LDMX4(al[tm], aL + aoff + tm * 16 * PADB);
            }
            uint32_t bh[2][4], bl[2][4];
            const uint32_t boff = (uint32_t)((n0 + lrow) * PADB) + ko;
#pragma unroll
            for (int tp = 0; tp < 2; tp++) {
                LDMX4(bh[tp], bH + boff + tp * 16 * PADB);
                LDMX4(bl[tp], bL + boff + tp * 16 * PADB);
            }
#pragma unroll
            for (int tm = 0; tm < 2; tm++) {
#pragma unroll
                for (int tn = 0; tn < 4; tn++) {
                    const int tp = tn >> 1, sel = tn & 1;
                    MMA16816(acc[tm][tn], ah[tm], bh[tp][sel], bh[tp][sel + 2]);
                    MMA16816(acc[tm][tn], ah[tm], bl[tp][sel], bl[tp][sel + 2]);
                    MMA16816(acc[tm][tn], al[tm], bh[tp][sel], bh[tp][sel + 2]);
                }
            }
        }
        __syncthreads();
    }

    const int g  = lane >> 2;
    const int tg = lane & 3;
#pragma unroll
    for (int tm = 0; tm < 2; tm++) {
#pragma unroll
        for (int tn = 0; tn < 4; tn++) {
            const int i0 = bm * 128 + m0 + tm * 16 + g;
            const int j0 = bn * 64 + n0 + tn * 8 + tg * 2;
            size_t o0 = (size_t)i0 * DIMM + j0;
            size_t o1 = o0 + (size_t)8 * DIMM;
            *(float2*)(C + o0) = make_float2(acc[tm][tn][0], acc[tm][tn][1]);
            *(float2*)(C + o1) = make_float2(acc[tm][tn][2], acc[tm][tn][3]);
        }
    }
}

// ============================================================
extern "C" void kernel_launch(void* const* d_in, const int* in_sizes, int n_in,
                              void* d_out, int out_size) {
    const float* x    = (const float*)d_in[0];
    const float* Wqkv = (const float*)d_in[1];
    const float* Wout = (const float*)d_in[2];
    float* out = (float*)d_out;

    float *sc;
    __nv_bfloat16 *qh, *ql, *xh, *xl, *wqh, *wql, *t1h, *t1l, *lkh, *lkl;
    __nv_bfloat16 *vth, *vtl, *cth, *ctl, *woh, *wol;
    cudaGetSymbolAddress((void**)&qh,  g_qh);
    cudaGetSymbolAddress((void**)&ql,  g_ql);
    cudaGetSymbolAddress((void**)&xh,  g_xh);
    cudaGetSymbolAddress((void**)&xl,  g_xl);
    cudaGetSymbolAddress((void**)&wqh, g_wqh);
    cudaGetSymbolAddress((void**)&wql, g_wql);
    cudaGetSymbolAddress((void**)&t1h, g_t1h);
    cudaGetSymbolAddress((void**)&t1l, g_t1l);
    cudaGetSymbolAddress((void**)&lkh, g_lkh);
    cudaGetSymbolAddress((void**)&lkl, g_lkl);
    cudaGetSymbolAddress((void**)&sc,  g_sc);
    cudaGetSymbolAddress((void**)&vth, g_vth);
    cudaGetSymbolAddress((void**)&vtl, g_vtl);
    cudaGetSymbolAddress((void**)&cth, g_cth);
    cudaGetSymbolAddress((void**)&ctl, g_ctl);
    cudaGetSymbolAddress((void**)&woh, g_woh);
    cudaGetSymbolAddress((void**)&wol, g_wol);

    cudaFuncSetAttribute(qkv_mma,     cudaFuncAttributeMaxDynamicSharedMemorySize, DBUF_SMEM);
    cudaFuncSetAttribute(su_fuse_mma, cudaFuncAttributeMaxDynamicSharedMemorySize, DBUF_SMEM);
    cudaFuncSetAttribute(out_mma,     cudaFuncAttributeMaxDynamicSharedMemorySize, AV_SMEM);
    cudaFuncSetAttribute(av_mma,      cudaFuncAttributeMaxDynamicSharedMemorySize, AV_SMEM);
    cudaFuncSetAttribute(head_mma<1>, cudaFuncAttributeMaxDynamicSharedMemorySize, DBUF_SMEM);
    cudaFuncSetAttribute(head_mma<2>, cudaFuncAttributeMaxDynamicSharedMemorySize, DBUF_SMEM);
    cudaFuncSetAttribute(head_mma<3>, cudaFuncAttributeMaxDynamicSharedMemorySize, DBUF_SMEM);

    const dim3 thr(256);

    // 0) split inputs
    conv_split  <<<(NS * DIMM + 255) / 256, thr>>>(x, xh, xl, NS * DIMM);
    conv_split_T<<<dim3(LDQ / 32, DIMM / 32), dim3(32, 8)>>>(Wqkv, wqh, wql, DIMM, LDQ);
    conv_split_T<<<dim3(DIMM / 32, DIMM / 32), dim3(32, 8)>>>(Wout, woh, wol, DIMM, DIMM);

    // 1) qkv projection (HMMA, split-only output)
    qkv_mma<<<dim3(LDQ / 128, NS / 128), thr, DBUF_SMEM>>>(xh, xl, wqh, wql, qh, ql);

    // 1b) vc^T split (reconstructed from split qkv)
    conv_vT<<<dim3(NS / 32, DH / 32, NH), dim3(32, 8)>>>(qh, ql, vth, vtl);

    // 2) per-head K=64 GEMMs (HMMA)
    const dim3 gHead(NS / 128, NS / 128, NH);
    head_mma<1><<<gHead, thr, DBUF_SMEM>>>(qh, ql, 3 * 1024, 2 * 1024, t1h, t1l, nullptr);
    head_mma<2><<<gHead, thr, DBUF_SMEM>>>(qh, ql, 0 * 1024, 1 * 1024, lkh, lkl, nullptr);
    head_mma<3><<<gHead, thr, DBUF_SMEM>>>(qh, ql, 3 * 1024, 4 * 1024, nullptr, nullptr, sc);

    // 3) Su (HMMA), fused scores = Sc - silu(Su)
    su_fuse_mma<<<gHead, thr, DBUF_SMEM>>>(t1h, t1l, lkh, lkl, sc);

    // 4) softmax -> attn split bf16 (reuses t1h/t1l)
    row_softmax_bf<<<dim3(NS, NH), thr>>>(sc, t1h, t1l);

    // 5) ctx = attn @ vc (HMMA)
    av_mma<<<dim3(NS / 128, NH), thr, AV_SMEM>>>(t1h, t1l, vth, vtl, cth, ctl);

    // 6) out = ctx @ W_out (HMMA, 128x64 tiles)
    out_mma<<<dim3(DIMM / 64, NS / 128), thr, AV_SMEM>>>(cth, ctl, woh, wol, out);
}

// round 9
// speedup vs baseline: 2.2995x; 1.0253x over previous
#include <cuda_runtime.h>
#include <cuda_bf16.h>
#include <math.h>
#include <stdint.h>

#define NS   2048
#define NH   16
#define DH   64
#define DIMM 1024
#define LDQ  6144

__device__ __constant__ float SCALE = 0.125f;

// ---- scratch ----
__device__ __nv_bfloat16 g_qh [(size_t)NS * LDQ];
__device__ __nv_bfloat16 g_ql [(size_t)NS * LDQ];
__device__ __nv_bfloat16 g_xh [(size_t)NS * DIMM];
__device__ __nv_bfloat16 g_xl [(size_t)NS * DIMM];
__device__ __nv_bfloat16 g_wqh[(size_t)LDQ * DIMM];
__device__ __nv_bfloat16 g_wql[(size_t)LDQ * DIMM];
__device__ __nv_bfloat16 g_t1h[(size_t)NH * NS * NS];
__device__ __nv_bfloat16 g_t1l[(size_t)NH * NS * NS];
__device__ __nv_bfloat16 g_lkh[(size_t)NH * NS * NS];
__device__ __nv_bfloat16 g_lkl[(size_t)NH * NS * NS];
__device__ float g_sc [(size_t)NH * NS * NS];
__device__ __nv_bfloat16 g_vth[(size_t)NH * DH * NS];
__device__ __nv_bfloat16 g_vtl[(size_t)NH * DH * NS];
__device__ __nv_bfloat16 g_cth[(size_t)NS * DIMM];
__device__ __nv_bfloat16 g_ctl[(size_t)NS * DIMM];
__device__ __nv_bfloat16 g_woh[(size_t)DIMM * DIMM];
__device__ __nv_bfloat16 g_wol[(size_t)DIMM * DIMM];

// ============================================================
// helpers
// ============================================================
__device__ __forceinline__ uint32_t smem_u32(const void* p) {
    uint32_t a;
    asm("{ .reg .u64 t; cvta.to.shared.u64 t, %1; cvt.u32.u64 %0, t; }" : "=r"(a) : "l"(p));
    return a;
}

#define CPASYNC16(s, g) \
    asm volatile("cp.async.cg.shared.global [%0], [%1], 16;" :: "r"(s), "l"(g) : "memory")
#define CP_COMMIT() asm volatile("cp.async.commit_group;" ::: "memory")
#define CP_WAIT0()  asm volatile("cp.async.wait_group 0;" ::: "memory")
#define CP_WAIT1()  asm volatile("cp.async.wait_group 1;" ::: "memory")

#define LDMX4(r, addr) \
    asm volatile("ldmatrix.sync.aligned.m8n8.x4.shared.b16 {%0,%1,%2,%3}, [%4];" \
        : "=r"((r)[0]), "=r"((r)[1]), "=r"((r)[2]), "=r"((r)[3]) : "r"(addr))

#define MMA16816(d, a, b0, b1) \
    asm volatile("mma.sync.aligned.m16n8k16.row.col.f32.bf16.bf16.f32 " \
        "{%0,%1,%2,%3}, {%4,%5,%6,%7}, {%8,%9}, {%0,%1,%2,%3};" \
        : "+f"((d)[0]), "+f"((d)[1]), "+f"((d)[2]), "+f"((d)[3]) \
        : "r"((a)[0]), "r"((a)[1]), "r"((a)[2]), "r"((a)[3]), "r"(b0), "r"(b1))

__device__ __forceinline__ uint32_t pack_bf2(float a, float b) {
    __nv_bfloat162 t = __floats2bfloat162_rn(a, b);
    return *(uint32_t*)&t;
}
__device__ __forceinline__ void split1(float v, __nv_bfloat16& h, float& r) {
    h = __float2bfloat16_rn(v);
    r = v - __bfloat162float(h);
}
__device__ __forceinline__ float fast_sigmoid(float x) {
    return __fdividef(1.0f, 1.0f + __expf(-x));
}
__device__ __forceinline__ float fast_silu(float x) {
    return __fdividef(x, 1.0f + __expf(-x));
}

// 32-wide K chunks: 64B data + 16B pad per row
#define PADB   80
#define TILEB  (128 * PADB)      // 10240
#define BUFB   (4 * TILEB)       // 40960
#define DBUF_SMEM (2 * BUFB)     // 81920 -> 2 CTAs/SM
#define AV_STAGE  (384 * PADB)   // 30720
#define AV_SMEM3  (3 * AV_STAGE) // 92160 -> 2 CTAs/SM

// ============================================================
// chunk compute: 128x128 tile, warp 64x32, K=32 per chunk
// ============================================================
__device__ __forceinline__ void mma_chunk_128(
    uint32_t aH, uint32_t aL, uint32_t bH, uint32_t bL,
    int m0, int n0, int lrow, uint32_t lkoff, float acc[4][4][4])
{
#pragma unroll
    for (int kk = 0; kk < 2; kk++) {
        const uint32_t ko = kk * 32 + lkoff;
        uint32_t ah[4][4], al[4][4];
        const uint32_t aoff = (uint32_t)((m0 + lrow) * PADB) + ko;
#pragma unroll
        for (int tm = 0; tm < 4; tm++) {
            LDMX4(ah[tm], aH + aoff + tm * 16 * PADB);
            LDMX4(al[tm], aL + aoff + tm * 16 * PADB);
        }
        uint32_t bh[2][4], bl[2][4];
        const uint32_t boff = (uint32_t)((n0 + lrow) * PADB) + ko;
#pragma unroll
        for (int tp = 0; tp < 2; tp++) {
            LDMX4(bh[tp], bH + boff + tp * 16 * PADB);
            LDMX4(bl[tp], bL + boff + tp * 16 * PADB);
        }
#pragma unroll
        for (int tm = 0; tm < 4; tm++) {
#pragma unroll
            for (int tn = 0; tn < 4; tn++) {
                const int tp = tn >> 1, sel = tn & 1;
                MMA16816(acc[tm][tn], ah[tm], bh[tp][sel], bh[tp][sel + 2]);
                MMA16816(acc[tm][tn], ah[tm], bl[tp][sel], bl[tp][sel + 2]);
                MMA16816(acc[tm][tn], al[tm], bh[tp][sel], bh[tp][sel + 2]);
            }
        }
    }
}

#define ISSUE_128(c, gsrc, ld, sdst)                                      \
    do {                                                                  \
        const __nv_bfloat16* gp_ = (gsrc) + (size_t)(c) * 32;             \
        const uint32_t sb_ = (sdst) + ((c) & 1) * BUFB;                   \
        _Pragma("unroll")                                                 \
        for (int kq = 0; kq < 8; kq++)                                    \
            CPASYNC16(sb_ + kq * 16 * PADB, gp_ + (size_t)(kq * 16) * (ld)); \
        CP_COMMIT();                                                      \
    } while (0)

// ============================================================
// conversion kernels
// ============================================================
__global__ void conv_split(const float* __restrict__ src,
                           __nv_bfloat16* __restrict__ hi, __nv_bfloat16* __restrict__ lo,
                           int n) {
    int i = blockIdx.x * 256 + threadIdx.x;
    if (i >= n) return;
    float v = src[i];
    __nv_bfloat16 h; float r;
    split1(v, h, r);
    hi[i] = h;
    lo[i] = __float2bfloat16_rn(r);
}

__global__ void conv_split_T(const float* __restrict__ src,
                             __nv_bfloat16* __restrict__ hi, __nv_bfloat16* __restrict__ lo,
                             int R, int C) {
    __shared__ float tile[32][33];
    const int bx = blockIdx.x * 32, by = blockIdx.y * 32;
    const int tx = threadIdx.x, ty = threadIdx.y;
#pragma unroll
    for (int i = 0; i < 32; i += 8)
        tile[ty + i][tx] = src[(size_t)(by + ty + i) * C + bx + tx];
    __syncthreads();
#pragma unroll
    for (int i = 0; i < 32; i += 8) {
        float v = tile[tx][ty + i];
        __nv_bfloat16 h; float r;
        split1(v, h, r);
        size_t o = (size_t)(bx + ty + i) * R + by + tx;
        hi[o] = h;
        lo[o] = __float2bfloat16_rn(r);
    }
}

// vt[h][d][j] from split qkv (reconstruct v = hi + lo)
__global__ void conv_vT(const __nv_bfloat16* __restrict__ QH,
                        const __nv_bfloat16* __restrict__ QL,
                        __nv_bfloat16* __restrict__ hi, __nv_bfloat16* __restrict__ lo) {
    __shared__ float tile[32][33];
    const int h = blockIdx.z;
    const int bx = blockIdx.x * 32;
    const int by = blockIdx.y * 32;
    const int tx = threadIdx.x, ty = threadIdx.y;
#pragma unroll
    for (int i = 0; i < 32; i += 8) {
        size_t o = (size_t)(bx + ty + i) * LDQ + 5 * 1024 + h * DH + by + tx;
        tile[ty + i][tx] = __bfloat162float(QH[o]) + __bfloat162float(QL[o]);
    }
    __syncthreads();
#pragma unroll
    for (int i = 0; i < 32; i += 8) {
        float v = tile[tx][ty + i];
        __nv_bfloat16 hh; float r;
        split1(v, hh, r);
        size_t o = (size_t)(h * DH + by + ty + i) * NS + bx + tx;
        hi[o] = hh;
        lo[o] = __float2bfloat16_rn(r);
    }
}

// ============================================================
// qkv = x @ Wqkv (HMMA split) — single-sync double buffer
// ============================================================
__global__ void __launch_bounds__(256, 2) qkv_mma(
    const __nv_bfloat16* __restrict__ XH, const __nv_bfloat16* __restrict__ XL,
    const __nv_bfloat16* __restrict__ WH, const __nv_bfloat16* __restrict__ WL,
    __nv_bfloat16* __restrict__ QH, __nv_bfloat16* __restrict__ QL)
{
    const int bm = blockIdx.y, bn = blockIdx.x;
    extern __shared__ char sm[];
    const uint32_t smb = smem_u32(sm);
    const int t = threadIdx.x;
    const int wid = t >> 5, lane = t & 31;
    const int m0 = (wid & 1) * 64;
    const int n0 = (wid >> 1) * 32;

    const int grp  = t >> 6;
    const int gg   = t & 63;
    const int col  = gg & 3;
    const int row0 = gg >> 2;
    const __nv_bfloat16* base;
    if (grp == 0)      base = XH + (size_t)(bm * 128) * DIMM;
    else if (grp == 1) base = XL + (size_t)(bm * 128) * DIMM;
    else if (grp == 2) base = WH + (size_t)(bn * 128) * DIMM;
    else               base = WL + (size_t)(bn * 128) * DIMM;
    const __nv_bfloat16* gsrc = base + (size_t)row0 * DIMM + col * 8;
    const uint32_t sdst = smb + grp * TILEB + row0 * PADB + col * 16;

    ISSUE_128(0, gsrc, DIMM, sdst);

    float acc[4][4][4] = {};
    const int lrow = lane & 15;
    const uint32_t lkoff = (uint32_t)((lane >> 4) * 16);

    for (int c = 0; c < 32; c++) {
        CP_WAIT0();
        __syncthreads();
        if (c + 1 < 32) ISSUE_128(c + 1, gsrc, DIMM, sdst);
        const uint32_t bse = smb + (c & 1) * BUFB;
        mma_chunk_128(bse, bse + TILEB, bse + 2 * TILEB, bse + 3 * TILEB,
                      m0, n0, lrow, lkoff, acc);
    }

    const int g  = lane >> 2;
    const int tg = lane & 3;
#pragma unroll
    for (int tm = 0; tm < 4; tm++) {
#pragma unroll
        for (int tn = 0; tn < 4; tn++) {
            const int i0 = bm * 128 + m0 + tm * 16 + g;
            const int j0 = bn * 128 + n0 + tn * 8 + tg * 2;
            float v0 = acc[tm][tn][0], v1 = acc[tm][tn][1];
            float v2 = acc[tm][tn][2], v3 = acc[tm][tn][3];
            size_t o0 = (size_t)i0 * LDQ + j0;
            size_t o1 = o0 + (size_t)8 * LDQ;
            __nv_bfloat16 h; float r0, r1, r2, r3;
            split1(v0, h, r0); split1(v1, h, r1); split1(v2, h, r2); split1(v3, h, r3);
            *(uint32_t*)(QH + o0) = pack_bf2(v0, v1);
            *(uint32_t*)(QH + o1) = pack_bf2(v2, v3);
            *(uint32_t*)(QL + o0) = pack_bf2(r0, r1);
            *(uint32_t*)(QL + o1) = pack_bf2(r2, r3);
        }
    }
}

// ============================================================
// Per-head NT GEMM K=64. MODE1 term1, MODE2 lookahead, MODE3 Sc.
// ============================================================
template <int MODE>
__global__ void __launch_bounds__(256, 2) head_mma(
    const __nv_bfloat16* __restrict__ QH, const __nv_bfloat16* __restrict__ QL,
    int aoff, int boff,
    __nv_bfloat16* __restrict__ CH, __nv_bfloat16* __restrict__ CL,
    float* __restrict__ CF)
{
    const int h  = blockIdx.z;
    const int bi = blockIdx.y, bj = blockIdx.x;
    if (MODE != 2 && bj > bi) return;
    if (MODE == 2 && bj < bi) return;

    extern __shared__ char sm[];
    const uint32_t smb = smem_u32(sm);
    const int t = threadIdx.x;
    const int wid = t >> 5, lane = t & 31;
    const int m0 = (wid & 1) * 64;
    const int n0 = (wid >> 1) * 32;

    const int grp  = t >> 6;
    const int gg   = t & 63;
    const int col  = gg & 3;
    const int row0 = gg >> 2;
    const __nv_bfloat16* base;
    if (grp == 0)      base = QH + (size_t)(bi * 128) * LDQ + aoff + h * DH;
    else if (grp == 1) base = QL + (size_t)(bi * 128) * LDQ + aoff + h * DH;
    else if (grp == 2) base = QH + (size_t)(bj * 128) * LDQ + boff + h * DH;
    else               base = QL + (size_t)(bj * 128) * LDQ + boff + h * DH;
    const __nv_bfloat16* gsrc = base + (size_t)row0 * LDQ + col * 8;
    const uint32_t sdst = smb + grp * TILEB + row0 * PADB + col * 16;

    ISSUE_128(0, gsrc, LDQ, sdst);
    ISSUE_128(1, gsrc, LDQ, sdst);

    float acc[4][4][4] = {};
    const int lrow = lane & 15;
    const uint32_t lkoff = (uint32_t)((lane >> 4) * 16);

    CP_WAIT1();
    __syncthreads();
    {
        const uint32_t bse = smb;
        mma_chunk_128(bse, bse + TILEB, bse + 2 * TILEB, bse + 3 * TILEB,
                      m0, n0, lrow, lkoff, acc);
    }
    CP_WAIT0();
    __syncthreads();
    {
        const uint32_t bse = smb + BUFB;
        mma_chunk_128(bse, bse + TILEB, bse + 2 * TILEB, bse + 3 * TILEB,
                      m0, n0, lrow, lkoff, acc);
    }

    const size_t hb = (size_t)h * NS * NS;
    const int g  = lane >> 2;
    const int tg = lane & 3;
#pragma unroll
    for (int tm = 0; tm < 4; tm++) {
#pragma unroll
        for (int tn = 0; tn < 4; tn++) {
            const int i0 = bi * 128 + m0 + tm * 16 + g;
            const int j0 = bj * 128 + n0 + tn * 8 + tg * 2;
            float v[4];
            v[0] = acc[tm][tn][0] * SCALE; v[1] = acc[tm][tn][1] * SCALE;
            v[2] = acc[tm][tn][2] * SCALE; v[3] = acc[tm][tn][3] * SCALE;
            const int ii[4] = {i0, i0, i0 + 8, i0 + 8};
            const int jj[4] = {j0, j0 + 1, j0, j0 + 1};
#pragma unroll
            for (int q = 0; q < 4; q++) {
                if (MODE == 1) v[q] = (jj[q] <= ii[q]) ? v[q] : 0.0f;
                if (MODE == 2) v[q] = (jj[q] >  ii[q]) ? fast_sigmoid(v[q]) : 0.0f;
            }
            size_t o0 = hb + (size_t)i0 * NS + j0;
            size_t o1 = o0 + (size_t)8 * NS;
            if (MODE == 3) {
                *(float2*)(CF + o0) = make_float2(v[0], v[1]);
                *(float2*)(CF + o1) = make_float2(v[2], v[3]);
            } else {
                __nv_bfloat16 hh; float r[4];
                split1(v[0], hh, r[0]); split1(v[1], hh, r[1]);
                split1(v[2], hh, r[2]); split1(v[3], hh, r[3]);
                *(uint32_t*)(CH + o0) = pack_bf2(v[0], v[1]);
                *(uint32_t*)(CH + o1) = pack_bf2(v[2], v[3]);
                *(uint32_t*)(CL + o0) = pack_bf2(r[0], r[1]);
                *(uint32_t*)(CL + o1) = pack_bf2(r[2], r[3]);
            }
        }
    }
}

// ============================================================
// Su (HMMA split), fused SC -= silu(Su). Single-sync double buffer.
// ============================================================
__global__ void __launch_bounds__(256, 2) su_fuse_mma(
    const __nv_bfloat16* __restrict__ T1H, const __nv_bfloat16* __restrict__ T1L,
    const __nv_bfloat16* __restrict__ LKH, const __nv_bfloat16* __restrict__ LKL,
    float* __restrict__ SC)
{
    const int h = blockIdx.z, bi = blockIdx.y, bk = blockIdx.x;
    if (bk > bi) return;

    extern __shared__ char sm[];
    const uint32_t smb = smem_u32(sm);
    const int t = threadIdx.x;
    const int wid = t >> 5, lane = t & 31;
    const int m0 = (wid & 1) * 64;
    const int n0 = (wid >> 1) * 32;

    const size_t hb = (size_t)h * NS * NS;
    const __nv_bfloat16* srcs[4] = {
        T1H + hb + (size_t)(bi * 128) * NS,
        T1L + hb + (size_t)(bi * 128) * NS,
        LKH + hb + (size_t)(bk * 128) * NS,
        LKL + hb + (size_t)(bk * 128) * NS
    };

    const int grp  = t >> 6;
    const int gg   = t & 63;
    const int col  = gg & 3;
    const int row0 = gg >> 2;
    const __nv_bfloat16* gsrc = srcs[grp] + (size_t)row0 * NS + (size_t)bk * 128 + col * 8;
    const uint32_t sdst = smb + grp * TILEB + row0 * PADB + col * 16;

    const int nCh = 4 * (bi - bk + 1);
    ISSUE_128(0, gsrc, NS, sdst);

    float acc[4][4][4] = {};
    const int lrow = lane & 15;
    const uint32_t lkoff = (uint32_t)((lane >> 4) * 16);

    for (int c = 0; c < nCh; c++) {
        CP_WAIT0();
        __syncthreads();
        if (c + 1 < nCh) ISSUE_128(c + 1, gsrc, NS, sdst);
        const uint32_t bse = smb + (c & 1) * BUFB;
        mma_chunk_128(bse, bse + TILEB, bse + 2 * TILEB, bse + 3 * TILEB,
                      m0, n0, lrow, lkoff, acc);
    }

    const int g  = lane >> 2;
    const int tg = lane & 3;
#pragma unroll
    for (int tm = 0; tm < 4; tm++) {
#pragma unroll
        for (int tn = 0; tn < 4; tn++) {
            const int i0 = bi * 128 + m0 + tm * 16 + g;
            const int j0 = bk * 128 + n0 + tn * 8 + tg * 2;
            float* p0 = SC + hb + (size_t)i0 * NS + j0;
            float* p1 = p0 + (size_t)8 * NS;
            float2 c0 = *(float2*)p0;
            float2 c1 = *(float2*)p1;
            c0.x -= fast_silu(acc[tm][tn][0]);
            c0.y -= fast_silu(acc[tm][tn][1]);
            c1.x -= fast_silu(acc[tm][tn][2]);
            c1.y -= fast_silu(acc[tm][tn][3]);
            *(float2*)p0 = c0;
            *(float2*)p1 = c1;
        }
    }
}

// ============================================================
// Row softmax -> split bf16 attn, zero-padded to 128 boundary.
// ============================================================
__global__ void row_softmax_bf(const float* __restrict__ SC,
                               __nv_bfloat16* __restrict__ AH,
                               __nv_bfloat16* __restrict__ AL) {
    const int h = blockIdx.y, i = blockIdx.x;
    const float* row = SC + (size_t)h * NS * NS + (size_t)i * NS;
    __nv_bfloat16* rh = AH + (size_t)h * NS * NS + (size_t)i * NS;
    __nv_bfloat16* rl = AL + (size_t)h * NS * NS + (size_t)i * NS;
    const int t = threadIdx.x;
    const int len = i + 1;

    __shared__ float red[256];

    float lmax = -1e30f;
    for (int j = t; j < len; j += 256) lmax = fmaxf(lmax, row[j]);
    red[t] = lmax; __syncthreads();
    for (int s = 128; s > 0; s >>= 1) { if (t < s) red[t] = fmaxf(red[t], red[t + s]); __syncthreads(); }
    const float bmax = red[0];
    __syncthreads();

    float ev[8];
    int cnt = 0;
    float lsum = 0.0f;
    for (int j = t; j < len; j += 256) {
        float e = __expf(row[j] - bmax);
        ev[cnt++] = e;
        lsum += e;
    }
    red[t] = lsum; __syncthreads();
    for (int s = 128; s > 0; s >>= 1) { if (t < s) red[t] += red[t + s]; __syncthreads(); }
    const float inv = __fdividef(1.0f, red[0]);

    cnt = 0;
    for (int j = t; j < len; j += 256) {
        float p = ev[cnt++] * inv;
        __nv_bfloat16 hh; float r;
        split1(p, hh, r);
        rh[j] = hh;
        rl[j] = __float2bfloat16_rn(r);
    }
    const int padEnd = ((i >> 7) + 1) << 7;
    const __nv_bfloat16 z = __float2bfloat16_rn(0.0f);
    for (int j = len + t; j < padEnd; j += 256) { rh[j] = z; rl[j] = z; }
}

// ============================================================
// AV (HMMA split): ctx = attn @ vc. 3-stage ring, single sync.
// ============================================================
__global__ void __launch_bounds__(256, 2) av_mma(
    const __nv_bfloat16* __restrict__ ATH, const __nv_bfloat16* __restrict__ ATL,
    const __nv_bfloat16* __restrict__ VTH, const __nv_bfloat16* __restrict__ VTL,
    __nv_bfloat16* __restrict__ CTH, __nv_bfloat16* __restrict__ CTL)
{
    const int h = blockIdx.y, bi = blockIdx.x;
    extern __shared__ char sm[];
    const uint32_t smb = smem_u32(sm);
    const int t = threadIdx.x;
    const int wid = t >> 5, lane = t & 31;
    const int m0 = (wid & 3) * 32;
    const int n0 = (wid >> 2) * 32;

    const size_t hb = (size_t)h * NS * NS;
    const __nv_bfloat16* gAh = ATH + hb + (size_t)(bi * 128) * NS;
    const __nv_bfloat16* gAl = ATL + hb + (size_t)(bi * 128) * NS;
    const __nv_bfloat16* gBh = VTH + (size_t)(h * DH) * NS;
    const __nv_bfloat16* gBl = VTL + (size_t)(h * DH) * NS;

    const int arow = t >> 1;
    const int ac0  = (t & 1) * 2;
    const int brow = t >> 2;
    const int bc0  = t & 3;

#define AV_ISSUE(c, stg)                                                        \
    do {                                                                        \
        const size_t j0 = (size_t)(c) * 32;                                     \
        const uint32_t bb = smb + (stg) * AV_STAGE;                             \
        const __nv_bfloat16* pah = gAh + (size_t)arow * NS + j0 + ac0 * 8;      \
        const __nv_bfloat16* pal = gAl + (size_t)arow * NS + j0 + ac0 * 8;      \
        const uint32_t sA = bb + arow * PADB + ac0 * 16;                        \
        CPASYNC16(sA,                        pah);                              \
        CPASYNC16(sA + 16,                   pah + 8);                          \
        CPASYNC16(sA + 128 * PADB,           pal);                              \
        CPASYNC16(sA + 128 * PADB + 16,      pal + 8);                          \
        const __nv_bfloat16* pbh = gBh + (size_t)brow * NS + j0 + bc0 * 8;      \
        const __nv_bfloat16* pbl = gBl + (size_t)brow * NS + j0 + bc0 * 8;      \
        const uint32_t sB = bb + 256 * PADB + brow * PADB + bc0 * 16;           \
        CPASYNC16(sB,             pbh);                                         \
        CPASYNC16(sB + 64 * PADB, pbl);                                         \
        CP_COMMIT();                                                            \
    } while (0)

    const int nCh = 4 * (bi + 1);
    AV_ISSUE(0, 0);
    if (1 < nCh) AV_ISSUE(1, 1);

    float acc[2][4][4] = {};
    const int lrow = lane & 15;
    const uint32_t lkoff = (uint32_t)((lane >> 4) * 16);

    for (int c = 0; c < nCh; c++) {
        if (c + 1 < nCh) CP_WAIT1(); else CP_WAIT0();
        __syncthreads();
        if (c + 2 < nCh) AV_ISSUE(c + 2, (c + 2) % 3);

        const uint32_t bse = smb + (c % 3) * AV_STAGE;
        const uint32_t aH = bse;
        const uint32_t aL = bse + 128 * PADB;
        const uint32_t bH = bse + 256 * PADB;
        const uint32_t bL = bse + 320 * PADB;

#pragma unroll
        for (int kk = 0; kk < 2; kk++) {
            const uint32_t ko = kk * 32 + lkoff;
            uint32_t ah[2][4], al[2][4];
            const uint32_t aoff = (uint32_t)((m0 + lrow) * PADB) + ko;
#pragma unroll
            for (int tm = 0; tm < 2; tm++) {
                LDMX4(ah[tm], aH + aoff + tm * 16 * PADB);
                LDMX4(al[tm], aL + aoff + tm * 16 * PADB);
            }
            uint32_t bh[2][4], bl[2][4];
            const uint32_t boff = (uint32_t)((n0 + lrow) * PADB) + ko;
#pragma unroll
            for (int tp = 0; tp < 2; tp++) {
                LDMX4(bh[tp], bH + boff + tp * 16 * PADB);
                LDMX4(bl[tp], bL + boff + tp * 16 * PADB);
            }
#pragma unroll
            for (int tm = 0; tm < 2; tm++) {
#pragma unroll
                for (int tn = 0; tn < 4; tn++) {
                    const int tp = tn >> 1, sel = tn & 1;
                    MMA16816(acc[tm][tn], ah[tm], bh[tp][sel], bh[tp][sel + 2]);
                    MMA16816(acc[tm][tn], ah[tm], bl[tp][sel], bl[tp][sel + 2]);
                    MMA16816(acc[tm][tn], al[tm], bh[tp][sel], bh[tp][sel + 2]);
                }
            }
        }
    }

    const int g  = lane >> 2;
    const int tg = lane & 3;
#pragma unroll
    for (int tm = 0; tm < 2; tm++) {
#pragma unroll
        for (int tn = 0; tn < 4; tn++) {
            const int i0 = bi * 128 + m0 + tm * 16 + g;
            const int d0 = n0 + tn * 8 + tg * 2;
            size_t o0 = (size_t)i0 * DIMM + h * DH + d0;
            size_t o1 = o0 + (size_t)8 * DIMM;
            float v0 = acc[tm][tn][0], v1 = acc[tm][tn][1];
            float v2 = acc[tm][tn][2], v3 = acc[tm][tn][3];
            __nv_bfloat16 hh; float r0, r1, r2, r3;
            split1(v0, hh, r0); split1(v1, hh, r1); split1(v2, hh, r2); split1(v3, hh, r3);
            *(uint32_t*)(CTH + o0) = pack_bf2(v0, v1);
            *(uint32_t*)(CTH + o1) = pack_bf2(v2, v3);
            *(uint32_t*)(CTL + o0) = pack_bf2(r0, r1);
            *(uint32_t*)(CTL + o1) = pack_bf2(r2, r3);
        }
    }
}

// ============================================================
// out = ctx @ Wout (HMMA split). 128x64 tiles, 3-stage ring.
// ============================================================
__global__ void __launch_bounds__(256, 2) out_mma(
    const __nv_bfloat16* __restrict__ AH0, const __nv_bfloat16* __restrict__ AL0,
    const __nv_bfloat16* __restrict__ BH0, const __nv_bfloat16* __restrict__ BL0,
    float* __restrict__ C)
{
    const int bm = blockIdx.y, bn = blockIdx.x;
    extern __shared__ char sm[];
    const uint32_t smb = smem_u32(sm);
    const int t = threadIdx.x;
    const int wid = t >> 5, lane = t & 31;
    const int m0 = (wid & 3) * 32;
    const int n0 = (wid >> 2) * 32;

    const __nv_bfloat16* gAh = AH0 + (size_t)(bm * 128) * DIMM;
    const __nv_bfloat16* gAl = AL0 + (size_t)(bm * 128) * DIMM;
    const __nv_bfloat16* gBh = BH0 + (size_t)(bn * 64) * DIMM;
    const __nv_bfloat16* gBl = BL0 + (size_t)(bn * 64) * DIMM;

    const int arow = t >> 1;
    const int ac0  = (t & 1) * 2;
    const int brow = t >> 2;
    const int bc0  = t & 3;

#define OUT_ISSUE(c, stg)                                                       \
    do {                                                                        \
        const size_t j0 = (size_t)(c) * 32;                                     \
        const uint32_t bb = smb + (stg) * AV_STAGE;                             \
        const __nv_bfloat16* pah = gAh + (size_t)arow * DIMM + j0 + ac0 * 8;    \
        const __nv_bfloat16* pal = gAl + (size_t)arow * DIMM + j0 + ac0 * 8;    \
        const uint32_t sA = bb + arow * PADB + ac0 * 16;                        \
        CPASYNC16(sA,                        pah);                              \
        CPASYNC16(sA + 16,                   pah + 8);                          \
        CPASYNC16(sA + 128 * PADB,           pal);                              \
        CPASYNC16(sA + 128 * PADB + 16,      pal + 8);                          \
        const __nv_bfloat16* pbh = gBh + (size_t)brow * DIMM + j0 + bc0 * 8;    \
        const __nv_bfloat16* pbl = gBl + (size_t)brow * DIMM + j0 + bc0 * 8;    \
        const uint32_t sB = bb + 256 * PADB + brow * PADB + bc0 * 16;           \
        CPASYNC16(sB,             pbh);                                         \
        CPASYNC16(sB + 64 * PADB, pbl);                                         \
        CP_COMMIT();                                                            \
    } while (0)

    OUT_ISSUE(0, 0);
    OUT_ISSUE(1, 1);

    float acc[2][4][4] = {};
    const int lrow = lane & 15;
    const uint32_t lkoff = (uint32_t)((lane >> 4) * 16);

    for (int c = 0; c < 32; c++) {
        if (c + 1 < 32) CP_WAIT1(); else CP_WAIT0();
        __syncthreads();
        if (c + 2 < 32) OUT_ISSUE(c + 2, (c + 2) % 3);

        const uint32_t bse = smb + (c % 3) * AV_STAGE;
        const uint32_t aH = bse;
        const uint32_t aL = bse + 128 * PADB;
        const uint32_t bH = bse + 256 * PADB;
        const uint32_t bL = bse + 320 * PADB;

#pragma unroll
        for (int kk = 0; kk < 2; kk++) {
            const uint32_t ko = kk * 32 + lkoff;
            uint32_t ah[2][4], al[2][4];
            const uint32_t aoff = (uint32_t)((m0 + lrow) * PADB) + ko;
#pragma unroll
            for (int tm = 0; tm < 2; tm++) {
                LDMX4(ah[tm], aH + aoff + tm * 16 * PADB);
                LDMX4(al[tm], aL + aoff + tm * 16 * PADB);
            }
            uint32_t bh[2][4], bl[2][4];
            const uint32_t boff = (uint32_t)((n0 + lrow) * PADB) + ko;
#pragma unroll
            for (int tp = 0; tp < 2; tp++) {
                LDMX4(bh[tp], bH + boff + tp * 16 * PADB);
                LDMX4(bl[tp], bL + boff + tp * 16 * PADB);
            }
#pragma unroll
            for (int tm = 0; tm < 2; tm++) {
#pragma unroll
                for (int tn = 0; tn < 4; tn++) {
                    const int tp = tn >> 1, sel = tn & 1;
                    MMA16816(acc[tm][tn], ah[tm], bh[tp][sel], bh[tp][sel + 2]);
                    MMA16816(acc[tm][tn], ah[tm], bl[tp][sel], bl[tp][sel + 2]);
                    MMA16816(acc[tm][tn], al[tm], bh[tp][sel], bh[tp][sel + 2]);
                }
            }
        }
    }

    const int g  = lane >> 2;
    const int tg = lane & 3;
#pragma unroll
    for (int tm = 0; tm < 2; tm++) {
#pragma unroll
        for (int tn = 0; tn < 4; tn++) {
            const int i0 = bm * 128 + m0 + tm * 16 + g;
            const int j0 = bn * 64 + n0 + tn * 8 + tg * 2;
            size_t o0 = (size_t)i0 * DIMM + j0;
            size_t o1 = o0 + (size_t)8 * DIMM;
            *(float2*)(C + o0) = make_float2(acc[tm][tn][0], acc[tm][tn][1]);
            *(float2*)(C + o1) = make_float2(acc[tm][tn][2], acc[tm][tn][3]);
        }
    }
}

// ============================================================
extern "C" void kernel_launch(void* const* d_in, const int* in_sizes, int n_in,
                              void* d_out, int out_size) {
    const float* x    = (const float*)d_in[0];
    const float* Wqkv = (const float*)d_in[1];
    const float* Wout = (const float*)d_in[2];
    float* out = (float*)d_out;

    float *sc;
    __nv_bfloat16 *qh, *ql, *xh, *xl, *wqh, *wql, *t1h, *t1l, *lkh, *lkl;
    __nv_bfloat16 *vth, *vtl, *cth, *ctl, *woh, *wol;
    cudaGetSymbolAddress((void**)&qh,  g_qh);
    cudaGetSymbolAddress((void**)&ql,  g_ql);
    cudaGetSymbolAddress((void**)&xh,  g_xh);
    cudaGetSymbolAddress((void**)&xl,  g_xl);
    cudaGetSymbolAddress((void**)&wqh, g_wqh);
    cudaGetSymbolAddress((void**)&wql, g_wql);
    cudaGetSymbolAddress((void**)&t1h, g_t1h);
    cudaGetSymbolAddress((void**)&t1l, g_t1l);
    cudaGetSymbolAddress((void**)&lkh, g_lkh);
    cudaGetSymbolAddress((void**)&lkl, g_lkl);
    cudaGetSymbolAddress((void**)&sc,  g_sc);
    cudaGetSymbolAddress((void**)&vth, g_vth);
    cudaGetSymbolAddress((void**)&vtl, g_vtl);
    cudaGetSymbolAddress((void**)&cth, g_cth);
    cudaGetSymbolAddress((void**)&ctl, g_ctl);
    cudaGetSymbolAddress((void**)&woh, g_woh);
    cudaGetSymbolAddress((void**)&wol, g_wol);

    cudaFuncSetAttribute(qkv_mma,     cudaFuncAttributeMaxDynamicSharedMemorySize, DBUF_SMEM);
    cudaFuncSetAttribute(su_fuse_mma, cudaFuncAttributeMaxDynamicSharedMemorySize, DBUF_SMEM);
    cudaFuncSetAttribute(out_mma,     cudaFuncAttributeMaxDynamicSharedMemorySize, AV_SMEM3);
    cudaFuncSetAttribute(av_mma,      cudaFuncAttributeMaxDynamicSharedMemorySize, AV_SMEM3);
    cudaFuncSetAttribute(head_mma<1>, cudaFuncAttributeMaxDynamicSharedMemorySize, DBUF_SMEM);
    cudaFuncSetAttribute(head_mma<2>, cudaFuncAttributeMaxDynamicSharedMemorySize, DBUF_SMEM);
    cudaFuncSetAttribute(head_mma<3>, cudaFuncAttributeMaxDynamicSharedMemorySize, DBUF_SMEM);

    const dim3 thr(256);

    // 0) split inputs
    conv_split  <<<(NS * DIMM + 255) / 256, thr>>>(x, xh, xl, NS * DIMM);
    conv_split_T<<<dim3(LDQ / 32, DIMM / 32), dim3(32, 8)>>>(Wqkv, wqh, wql, DIMM, LDQ);
    conv_split_T<<<dim3(DIMM / 32, DIMM / 32), dim3(32, 8)>>>(Wout, woh, wol, DIMM, DIMM);

    // 1) qkv projection (HMMA, split output)
    qkv_mma<<<dim3(LDQ / 128, NS / 128), thr, DBUF_SMEM>>>(xh, xl, wqh, wql, qh, ql);

    // 1b) vc^T split
    conv_vT<<<dim3(NS / 32, DH / 32, NH), dim3(32, 8)>>>(qh, ql, vth, vtl);

    // 2) per-head K=64 GEMMs (HMMA)
    const dim3 gHead(NS / 128, NS / 128, NH);
    head_mma<1><<<gHead, thr, DBUF_SMEM>>>(qh, ql, 3 * 1024, 2 * 1024, t1h, t1l, nullptr);
    head_mma<2><<<gHead, thr, DBUF_SMEM>>>(qh, ql, 0 * 1024, 1 * 1024, lkh, lkl, nullptr);
    head_mma<3><<<gHead, thr, DBUF_SMEM>>>(qh, ql, 3 * 1024, 4 * 1024, nullptr, nullptr, sc);

    // 3) Su (HMMA), fused scores = Sc - silu(Su)
    su_fuse_mma<<<gHead, thr, DBUF_SMEM>>>(t1h, t1l, lkh, lkl, sc);

    // 4) softmax -> attn split bf16 (reuses t1h/t1l)
    row_softmax_bf<<<dim3(NS, NH), thr>>>(sc, t1h, t1l);

    // 5) ctx = attn @ vc (HMMA, 3-stage)
    av_mma<<<dim3(NS / 128, NH), thr, AV_SMEM3>>>(t1h, t1l, vth, vtl, cth, ctl);

    // 6) out = ctx @ W_out (HMMA, 3-stage, 128x64 tiles)
    out_mma<<<dim3(DIMM / 64, NS / 128), thr, AV_SMEM3>>>(cth, ctl, woh, wol, out);
}